// round 3
// baseline (speedup 1.0000x reference)
#include <cuda_runtime.h>
#include <cuda_bf16.h>
#include <math.h>
#include <stdint.h>

#define EMBED   768
#define HEADS   8
#define HDIM    96
#define DEPTH   12
#define MLPH    3072
#define NP      1568
#define BATCH   2
#define NTOK    (BATCH*NP)      // 3136
#define KPATCH  1536            // 3*2*16*16

typedef __nv_bfloat16 bf16;

// ---------------- scratch (device globals: allocation-free) ----------------
__device__ __align__(256) bf16  g_imh [NTOK*KPATCH];
__device__ __align__(256) bf16  g_iml [NTOK*KPATCH];
__device__ __align__(256) float g_h   [NTOK*EMBED];
__device__ __align__(256) bf16  g_yh  [NTOK*EMBED];
__device__ __align__(256) bf16  g_yl  [NTOK*EMBED];
__device__ __align__(256) bf16  g_qkvh[NTOK*3*EMBED];
__device__ __align__(256) bf16  g_qkvl[NTOK*3*EMBED];
__device__ __align__(256) float g_attn[39337984];     // scores fp32 (2*8*1568^2)
__device__ __align__(256) bf16  g_Ph  [39337984];
__device__ __align__(256) bf16  g_Pl  [39337984];
__device__ __align__(256) bf16  g_aoh [NTOK*EMBED];
__device__ __align__(256) bf16  g_aol [NTOK*EMBED];
__device__ __align__(256) bf16  g_mlph[NTOK*MLPH];
__device__ __align__(256) bf16  g_mlpl[NTOK*MLPH];
__device__ float g_pool[BATCH*EMBED];
__device__ float g_pln [BATCH*EMBED];
__device__ double g_freq[EMBED/2];
// weight splits
__device__ __align__(256) bf16 g_cwh[EMBED*KPATCH];
__device__ __align__(256) bf16 g_cwl[EMBED*KPATCH];
__device__ __align__(256) bf16 g_qwh[DEPTH*3*EMBED*EMBED];
__device__ __align__(256) bf16 g_qwl[DEPTH*3*EMBED*EMBED];
__device__ __align__(256) bf16 g_owh[DEPTH*EMBED*EMBED];
__device__ __align__(256) bf16 g_owl[DEPTH*EMBED*EMBED];
__device__ __align__(256) bf16 g_w1h[DEPTH*MLPH*EMBED];
__device__ __align__(256) bf16 g_w1l[DEPTH*MLPH*EMBED];
__device__ __align__(256) bf16 g_w2h[DEPTH*EMBED*MLPH];
__device__ __align__(256) bf16 g_w2l[DEPTH*EMBED*MLPH];

__device__ __forceinline__ void split_bf16(float v, bf16& h, bf16& l)
{
    h = __float2bfloat16(v);
    l = __float2bfloat16(v - __bfloat162float(h));
}

// ---------------- generic fp32 -> bf16 hi/lo split ----------------
__global__ void split_kernel(const float* __restrict__ s, bf16* __restrict__ h,
                             bf16* __restrict__ l, long long n)
{
    long long i = ((long long)blockIdx.x*256 + threadIdx.x)*4;
    if (i >= n) return;
    float4 v = *(const float4*)&s[i];
    bf16 h0,h1,h2,h3,l0,l1,l2,l3;
    split_bf16(v.x,h0,l0); split_bf16(v.y,h1,l1);
    split_bf16(v.z,h2,l2); split_bf16(v.w,h3,l3);
    __nv_bfloat162 p;
    p.x=h0;p.y=h1; *(__nv_bfloat162*)&h[i  ]=p;
    p.x=h2;p.y=h3; *(__nv_bfloat162*)&h[i+2]=p;
    p.x=l0;p.y=l1; *(__nv_bfloat162*)&l[i  ]=p;
    p.x=l2;p.y=l3; *(__nv_bfloat162*)&l[i+2]=p;
}

// ================= tensor-core GEMM v3: pre-split bf16, cp.async 2-stage ====
#define BM 128
#define BN 64
#define BK 32
#define SA 40     // smem k-stride (bf16) with pad -> conflict-free ldmatrix
#define SMEM_ELEMS (2*2*BM*SA + 2*2*BN*SA)   // 30720 bf16 = 61440 B
#define OFFA(st,hl) (((st)*2+(hl))*BM*SA)
#define OFFB(st,hl) (2*2*BM*SA + ((st)*2+(hl))*BN*SA)

#define LDSM4(R, addr) \
    asm volatile("ldmatrix.sync.aligned.m8n8.x4.shared.b16 {%0,%1,%2,%3},[%4];" \
        : "=r"((R)[0]), "=r"((R)[1]), "=r"((R)[2]), "=r"((R)[3]) : "r"(addr))

#define MMA16816(C, A, B0, B1) \
    asm volatile("mma.sync.aligned.m16n8k16.row.col.f32.bf16.bf16.f32 " \
        "{%0,%1,%2,%3},{%4,%5,%6,%7},{%8,%9},{%0,%1,%2,%3};" \
        : "+f"((C)[0]), "+f"((C)[1]), "+f"((C)[2]), "+f"((C)[3]) \
        : "r"((A)[0]), "r"((A)[1]), "r"((A)[2]), "r"((A)[3]), "r"(B0), "r"(B1))

__device__ __forceinline__ void cpa16(uint32_t dst, const void* src, bool p)
{
    int sz = p ? 16 : 0;
    asm volatile("cp.async.cg.shared.global [%0],[%1],16,%2;\n"
                 :: "r"(dst), "l"(src), "r"(sz));
}

// EPI: 0 none | 1 +bias | 2 +bias,gelu | 4 +bias,+residual
// BT=true: B[N][K] row-major. BT=false: B[K][N] row-major (scalar transpose path).
// SPLITOUT: write bf16 hi/lo (Ch,Cl) instead of fp32 Cf.
template<int EPI, bool BT, bool SPLITOUT>
__global__ void __launch_bounds__(256, 2)
mma3_gemm(const bf16* __restrict__ Ah, const bf16* __restrict__ Al,
          const bf16* __restrict__ Bh, const bf16* __restrict__ Bl,
          const float* __restrict__ bias, const float* __restrict__ R,
          float* __restrict__ Cf, bf16* __restrict__ Ch, bf16* __restrict__ Cl,
          int M, int N, int K, int lda, int ldb, int ldc, int ldr,
          long long sAb, long long sAh_, long long sBb, long long sBh_,
          long long sCb, long long sCh_, long long sRb, long long sRh_, int H)
{
    const int z  = blockIdx.z;
    const int bb = z / H, hh = z % H;
    Ah += bb*sAb + hh*sAh_;  Al += bb*sAb + hh*sAh_;
    Bh += bb*sBb + hh*sBh_;  Bl += bb*sBb + hh*sBh_;
    const long long coff = bb*sCb + hh*sCh_;
    if (SPLITOUT) { Ch += coff; Cl += coff; } else { Cf += coff; }
    if (EPI >= 3) R += bb*sRb + hh*sRh_;

    extern __shared__ __align__(16) bf16 smem[];
    const uint32_t su = (uint32_t)__cvta_generic_to_shared(smem);

    const int tid  = threadIdx.x;
    const int lane = tid & 31;
    const int w    = tid >> 5;
    const int wm   = w >> 1;
    const int wn   = w & 1;
    const int m0   = blockIdx.y * BM;
    const int n0   = blockIdx.x * BN;

    float c[2][4][4];
    #pragma unroll
    for (int i = 0; i < 2; i++)
        #pragma unroll
        for (int j = 0; j < 4; j++)
            #pragma unroll
            for (int q = 0; q < 4; q++) c[i][j][q] = 0.f;

    const int lrow = lane & 15;
    const int lcol = (lane >> 4) * 8;
    const uint32_t aoff = (uint32_t)(((wm*32 + lrow)*SA + lcol) * 2);
    const uint32_t boff = (uint32_t)(((wn*32 + lrow)*SA + lcol) * 2);

    const int T = K / BK;

    auto issue = [&](int t, int st) {
        const int k0 = t * BK;
        // ---- A: 1024 16B-chunks (hi+lo), 4 per thread
        #pragma unroll
        for (int i = 0; i < 4; i++) {
            int hl  = i >> 1;
            int ch  = tid + (i & 1) * 256;     // 0..511
            int row = ch >> 2;
            int kc  = (ch & 3) * 8;
            bool p  = (m0 + row) < M;
            int rr  = p ? (m0 + row) : 0;
            const bf16* src = (hl ? Al : Ah) + (long long)rr*lda + k0 + kc;
            cpa16(su + (uint32_t)((OFFA(st,hl) + row*SA + kc)*2), src, p);
        }
        if (BT) {
            // ---- B: 512 chunks (hi+lo), 2 per thread
            #pragma unroll
            for (int i = 0; i < 2; i++) {
                int hl  = i;
                int ch  = tid;                  // 0..255
                int row = ch >> 2;
                int kc  = (ch & 3) * 8;
                bool p  = (n0 + row) < N;
                int rr  = p ? (n0 + row) : 0;
                const bf16* src = (hl ? Bl : Bh) + (long long)rr*ldb + k0 + kc;
                cpa16(su + (uint32_t)((OFFB(st,hl) + row*SA + kc)*2), src, p);
            }
        } else {
            // ---- B in [K,N]: scalar transpose into [n][k] smem
            #pragma unroll
            for (int i = 0; i < 4; i++) {
                int ch  = tid + i*256;          // 0..1023
                int hl  = ch >> 9;
                int rem = ch & 511;
                int kr  = rem >> 4;             // 0..31
                int nc  = (rem & 15) * 4;       // 0..60
                bool p  = (n0 + nc) < N;
                bf16 v[4];
                if (p) {
                    const bf16* src = (hl ? Bl : Bh) + (long long)(k0+kr)*ldb + n0 + nc;
                    *(uint2*)v = *(const uint2*)src;
                } else {
                    v[0]=v[1]=v[2]=v[3] = __float2bfloat16(0.f);
                }
                bf16* sb = smem + OFFB(st,hl);
                #pragma unroll
                for (int j = 0; j < 4; j++) sb[(nc+j)*SA + kr] = v[j];
            }
        }
    };

    issue(0, 0);
    asm volatile("cp.async.commit_group;");

    for (int t = 0; t < T; t++) {
        const int st = t & 1;
        if (t + 1 < T) {
            issue(t + 1, st ^ 1);
            asm volatile("cp.async.commit_group;");
            asm volatile("cp.async.wait_group 1;");
        } else {
            asm volatile("cp.async.wait_group 0;");
        }
        __syncthreads();

        const uint32_t aHs = su + (uint32_t)(OFFA(st,0)*2) + aoff;
        const uint32_t aLs = su + (uint32_t)(OFFA(st,1)*2) + aoff;
        const uint32_t bHs = su + (uint32_t)(OFFB(st,0)*2) + boff;
        const uint32_t bLs = su + (uint32_t)(OFFB(st,1)*2) + boff;

        #pragma unroll
        for (int kk2 = 0; kk2 < 2; kk2++) {
            const uint32_t kb = (uint32_t)(kk2 * 16 * 2);
            uint32_t Af[2][4], Alf[2][4], Bf[2][4], Blf[2][4];
            #pragma unroll
            for (int mi = 0; mi < 2; mi++) {
                LDSM4(Af[mi],  aHs + (uint32_t)(mi*16*SA*2) + kb);
                LDSM4(Alf[mi], aLs + (uint32_t)(mi*16*SA*2) + kb);
            }
            #pragma unroll
            for (int pr = 0; pr < 2; pr++) {
                LDSM4(Bf[pr],  bHs + (uint32_t)(pr*16*SA*2) + kb);
                LDSM4(Blf[pr], bLs + (uint32_t)(pr*16*SA*2) + kb);
            }
            #pragma unroll
            for (int mi = 0; mi < 2; mi++) {
                #pragma unroll
                for (int pr = 0; pr < 2; pr++) {
                    MMA16816(c[mi][pr*2  ], Af[mi],  Bf[pr][0],  Bf[pr][2]);
                    MMA16816(c[mi][pr*2  ], Af[mi],  Blf[pr][0], Blf[pr][2]);
                    MMA16816(c[mi][pr*2  ], Alf[mi], Bf[pr][0],  Bf[pr][2]);
                    MMA16816(c[mi][pr*2+1], Af[mi],  Bf[pr][1],  Bf[pr][3]);
                    MMA16816(c[mi][pr*2+1], Af[mi],  Blf[pr][1], Blf[pr][3]);
                    MMA16816(c[mi][pr*2+1], Alf[mi], Bf[pr][1],  Bf[pr][3]);
                }
            }
        }
        __syncthreads();
    }

    // ---------------- epilogue ----------------
    const int g  = lane >> 2;
    const int tq = lane & 3;
    #pragma unroll
    for (int mi = 0; mi < 2; mi++) {
        #pragma unroll
        for (int nf = 0; nf < 4; nf++) {
            int col = n0 + wn*32 + nf*8 + tq*2;
            #pragma unroll
            for (int half = 0; half < 2; half++) {
                int row = m0 + wm*32 + mi*16 + g + half*8;
                if (row >= M || col >= N) continue;
                float v0 = c[mi][nf][half*2 + 0];
                float v1 = c[mi][nf][half*2 + 1];
                if (EPI == 1 || EPI == 2 || EPI == 4) { v0 += bias[col]; v1 += bias[col+1]; }
                if (EPI == 2) {
                    v0 = 0.5f * v0 * (1.0f + erff(v0 * 0.70710678118654752f));
                    v1 = 0.5f * v1 * (1.0f + erff(v1 * 0.70710678118654752f));
                }
                if (EPI >= 3) {
                    float2 r2 = *(const float2*)&R[(long long)row*ldr + col];
                    v0 += r2.x; v1 += r2.y;
                }
                if (SPLITOUT) {
                    bf16 h0,h1,l0,l1;
                    split_bf16(v0,h0,l0); split_bf16(v1,h1,l1);
                    __nv_bfloat162 ph; ph.x=h0; ph.y=h1;
                    __nv_bfloat162 pl; pl.x=l0; pl.y=l1;
                    *(__nv_bfloat162*)&Ch[(long long)row*ldc + col] = ph;
                    *(__nv_bfloat162*)&Cl[(long long)row*ldc + col] = pl;
                } else {
                    float2 o; o.x = v0; o.y = v1;
                    *(float2*)&Cf[(long long)row*ldc + col] = o;
                }
            }
        }
    }
}

// ---------------- layernorm: one block (256 thr) per row ----------------
__global__ void ln_kernel(const float* __restrict__ X, const float* __restrict__ sc,
                          const float* __restrict__ bi, float* __restrict__ Yf,
                          bf16* __restrict__ Yh, bf16* __restrict__ Yl, int Cn)
{
    const float* x = X + (long long)blockIdx.x * Cn;
    __shared__ float sh1[32], sh2[32];
    int tid = threadIdx.x;
    float s = 0.f, s2 = 0.f;
    for (int i = tid; i < Cn; i += 256) { float v = x[i]; s += v; s2 += v*v; }
    #pragma unroll
    for (int o = 16; o > 0; o >>= 1) {
        s  += __shfl_xor_sync(0xffffffffu, s,  o);
        s2 += __shfl_xor_sync(0xffffffffu, s2, o);
    }
    if ((tid & 31) == 0) { sh1[tid>>5] = s; sh2[tid>>5] = s2; }
    __syncthreads();
    if (tid < 32) {
        float a = (tid < 8) ? sh1[tid] : 0.f;
        float b = (tid < 8) ? sh2[tid] : 0.f;
        #pragma unroll
        for (int o = 4; o > 0; o >>= 1) {
            a += __shfl_xor_sync(0xffffffffu, a, o);
            b += __shfl_xor_sync(0xffffffffu, b, o);
        }
        if (tid == 0) { sh1[0] = a; sh2[0] = b; }
    }
    __syncthreads();
    float mean = sh1[0] / Cn;
    float var  = sh2[0] / Cn - mean*mean;
    float inv  = rsqrtf(var + 1e-5f);
    for (int i = tid; i < Cn; i += 256) {
        float v = (x[i] - mean) * inv * sc[i] + bi[i];
        if (Yf) Yf[(long long)blockIdx.x*Cn + i] = v;
        if (Yh) {
            bf16 h, l; split_bf16(v, h, l);
            Yh[(long long)blockIdx.x*Cn + i] = h;
            Yl[(long long)blockIdx.x*Cn + i] = l;
        }
    }
}

// ---------------- softmax (reads fp32 scores, writes split bf16 P) ---------
__global__ void softmax_kernel(const float* __restrict__ S,
                               bf16* __restrict__ Ph, bf16* __restrict__ Pl)
{
    const float* p = S + (long long)blockIdx.x * NP;
    bf16* ph = Ph + (long long)blockIdx.x * NP;
    bf16* pl = Pl + (long long)blockIdx.x * NP;
    __shared__ float sh[32];
    int tid = threadIdx.x;
    const int IT = (NP + 255) / 256;   // 7
    float vals[(NP + 255) / 256];
    float mx = -1e30f;
    #pragma unroll
    for (int it = 0; it < IT; it++) {
        int i = tid + it*256;
        float v = (i < NP) ? p[i] : -1e30f;
        vals[it] = v;
        mx = fmaxf(mx, v);
    }
    #pragma unroll
    for (int o = 16; o > 0; o >>= 1) mx = fmaxf(mx, __shfl_xor_sync(0xffffffffu, mx, o));
    if ((tid & 31) == 0) sh[tid>>5] = mx;
    __syncthreads();
    if (tid < 32) {
        float v = (tid < 8) ? sh[tid] : -1e30f;
        #pragma unroll
        for (int o = 4; o > 0; o >>= 1) v = fmaxf(v, __shfl_xor_sync(0xffffffffu, v, o));
        if (tid == 0) sh[0] = v;
    }
    __syncthreads();
    mx = sh[0];
    __syncthreads();
    float sum = 0.f;
    #pragma unroll
    for (int it = 0; it < IT; it++) {
        int i = tid + it*256;
        float e = (i < NP) ? expf(vals[it] - mx) : 0.f;
        vals[it] = e;
        sum += e;
    }
    #pragma unroll
    for (int o = 16; o > 0; o >>= 1) sum += __shfl_xor_sync(0xffffffffu, sum, o);
    if ((tid & 31) == 0) sh[tid>>5] = sum;
    __syncthreads();
    if (tid < 32) {
        float v = (tid < 8) ? sh[tid] : 0.f;
        #pragma unroll
        for (int o = 4; o > 0; o >>= 1) v += __shfl_xor_sync(0xffffffffu, v, o);
        if (tid == 0) sh[0] = v;
    }
    __syncthreads();
    float inv = 1.0f / sh[0];
    #pragma unroll
    for (int it = 0; it < IT; it++) {
        int i = tid + it*256;
        if (i < NP) {
            float v = vals[it] * inv;
            bf16 h, l; split_bf16(v, h, l);
            ph[i] = h; pl[i] = l;
        }
    }
}

// ---------------- im2col (writes split bf16 directly) ----------------
__global__ void im2col_kernel(const float* __restrict__ x)
{
    long long idx = (long long)blockIdx.x * 256 + threadIdx.x;
    if (idx >= (long long)NTOK * KPATCH) return;
    int j = (int)(idx % KPATCH);
    int m = (int)(idx / KPATCH);
    int b = m / NP, n = m % NP;
    int t = n / 196, r = n % 196, yy = r / 14, xx = r % 14;
    int i  = j / 512, r2 = j % 512;
    int dt = r2 / 256, r3 = r2 % 256;
    int dy = r3 / 16,  dx = r3 % 16;
    long long off = ((((long long)(b*3 + i)*16 + (2*t + dt))*224) + (16*yy + dy))*224 + (16*xx + dx);
    float v = x[off];
    bf16 h, l; split_bf16(v, h, l);
    g_imh[idx] = h; g_iml[idx] = l;
}

// ---------------- positional encoding ----------------
__global__ void freq_kernel()
{
    int c2 = threadIdx.x;
    if (c2 < EMBED/2) g_freq[c2] = pow(10000.0, -2.0 * c2 / (double)EMBED);
}
__global__ void posadd_kernel()
{
    int idx = blockIdx.x * 256 + threadIdx.x;
    if (idx >= NP*EMBED) return;
    int n = idx / EMBED, c = idx % EMBED;
    double a = (double)n * g_freq[c >> 1];
    const double TWO_PI = 6.283185307179586476925286766559;
    int k = (int)(a * (1.0 / TWO_PI) + 0.5);
    float rf = (float)(a - (double)k * TWO_PI);
    float v = (c & 1) ? cosf(rf) : sinf(rf);
    g_h[idx]            += v;
    g_h[idx + NP*EMBED] += v;
}

// ---------------- mean pool over tokens ----------------
__global__ void pool_kernel()
{
    int idx = blockIdx.x * 256 + threadIdx.x;
    if (idx >= BATCH*EMBED) return;
    int b = idx / EMBED, c = idx % EMBED;
    const float* base = g_h + (long long)b*NP*EMBED + c;
    float s = 0.f;
    for (int n = 0; n < NP; n++) s += base[(long long)n*EMBED];
    g_pool[idx] = s * (1.0f / NP);
}

// ---------------- classifier head ----------------
__global__ void head_kernel(const float* __restrict__ W, const float* __restrict__ hb,
                            float* __restrict__ out)
{
    int g = blockIdx.x * 256 + threadIdx.x;
    int warp = g >> 5, lane = g & 31;
    if (warp >= BATCH*1000) return;
    int b = warp / 1000, j = warp % 1000;
    float s = 0.f;
    for (int c = lane; c < EMBED; c += 32)
        s += g_pln[b*EMBED + c] * W[j*EMBED + c];
    #pragma unroll
    for (int o = 16; o > 0; o >>= 1) s += __shfl_xor_sync(0xffffffffu, s, o);
    if (lane == 0) out[warp] = s + hb[j];
}

// ---------------- host orchestration ----------------
#define SMEMB (SMEM_ELEMS*2)

extern "C" void kernel_launch(void* const* d_in, const int* in_sizes, int n_in,
                              void* d_out, int out_size)
{
    const float* x      = (const float*)d_in[0];
    const float* conv_w = (const float*)d_in[1];
    const float* conv_b = (const float*)d_in[2];
    const float* n1s    = (const float*)d_in[3];
    const float* n1b    = (const float*)d_in[4];
    const float* qkv_w  = (const float*)d_in[5];
    const float* out_w  = (const float*)d_in[6];
    const float* out_b  = (const float*)d_in[7];
    const float* n2s    = (const float*)d_in[8];
    const float* n2b    = (const float*)d_in[9];
    const float* fc1_w  = (const float*)d_in[10];
    const float* fc1_b  = (const float*)d_in[11];
    const float* fc2_w  = (const float*)d_in[12];
    const float* fc2_b  = (const float*)d_in[13];
    const float* fns    = (const float*)d_in[14];
    const float* fnb    = (const float*)d_in[15];
    const float* head_w = (const float*)d_in[16];
    const float* head_b = (const float*)d_in[17];
    float* out = (float*)d_out;

    float *h, *attn, *pool, *pln;
    bf16 *imh,*iml,*yh,*yl,*qkvh,*qkvl,*Ph,*Pl,*aoh,*aol,*mlph,*mlpl;
    bf16 *cwh,*cwl,*qwh,*qwl,*owh,*owl,*w1h,*w1l,*w2h,*w2l;
    cudaGetSymbolAddress((void**)&h,    g_h);
    cudaGetSymbolAddress((void**)&attn, g_attn);
    cudaGetSymbolAddress((void**)&pool, g_pool);
    cudaGetSymbolAddress((void**)&pln,  g_pln);
    cudaGetSymbolAddress((void**)&imh,  g_imh);   cudaGetSymbolAddress((void**)&iml, g_iml);
    cudaGetSymbolAddress((void**)&yh,   g_yh);    cudaGetSymbolAddress((void**)&yl,  g_yl);
    cudaGetSymbolAddress((void**)&qkvh, g_qkvh);  cudaGetSymbolAddress((void**)&qkvl,g_qkvl);
    cudaGetSymbolAddress((void**)&Ph,   g_Ph);    cudaGetSymbolAddress((void**)&Pl,  g_Pl);
    cudaGetSymbolAddress((void**)&aoh,  g_aoh);   cudaGetSymbolAddress((void**)&aol, g_aol);
    cudaGetSymbolAddress((void**)&mlph, g_mlph);  cudaGetSymbolAddress((void**)&mlpl,g_mlpl);
    cudaGetSymbolAddress((void**)&cwh,  g_cwh);   cudaGetSymbolAddress((void**)&cwl, g_cwl);
    cudaGetSymbolAddress((void**)&qwh,  g_qwh);   cudaGetSymbolAddress((void**)&qwl, g_qwl);
    cudaGetSymbolAddress((void**)&owh,  g_owh);   cudaGetSymbolAddress((void**)&owl, g_owl);
    cudaGetSymbolAddress((void**)&w1h,  g_w1h);   cudaGetSymbolAddress((void**)&w1l, g_w1l);
    cudaGetSymbolAddress((void**)&w2h,  g_w2h);   cudaGetSymbolAddress((void**)&w2l, g_w2l);

    // raise dynamic smem cap for all gemm instantiations
    cudaFuncSetAttribute(mma3_gemm<1,true ,false>, cudaFuncAttributeMaxDynamicSharedMemorySize, SMEMB);
    cudaFuncSetAttribute(mma3_gemm<0,true ,true >, cudaFuncAttributeMaxDynamicSharedMemorySize, SMEMB);
    cudaFuncSetAttribute(mma3_gemm<0,true ,false>, cudaFuncAttributeMaxDynamicSharedMemorySize, SMEMB);
    cudaFuncSetAttribute(mma3_gemm<0,false,true >, cudaFuncAttributeMaxDynamicSharedMemorySize, SMEMB);
    cudaFuncSetAttribute(mma3_gemm<4,true ,false>, cudaFuncAttributeMaxDynamicSharedMemorySize, SMEMB);
    cudaFuncSetAttribute(mma3_gemm<2,true ,true >, cudaFuncAttributeMaxDynamicSharedMemorySize, SMEMB);

    const long long Z0 = 0;

    // ---- weight splits (once per launch) ----
    {
        long long n;
        n = (long long)EMBED*KPATCH;
        split_kernel<<<(int)((n/4+255)/256),256>>>(conv_w, cwh, cwl, n);
        n = (long long)DEPTH*3*EMBED*EMBED;
        split_kernel<<<(int)((n/4+255)/256),256>>>(qkv_w, qwh, qwl, n);
        n = (long long)DEPTH*EMBED*EMBED;
        split_kernel<<<(int)((n/4+255)/256),256>>>(out_w, owh, owl, n);
        n = (long long)DEPTH*MLPH*EMBED;
        split_kernel<<<(int)((n/4+255)/256),256>>>(fc1_w, w1h, w1l, n);
        n = (long long)DEPTH*EMBED*MLPH;
        split_kernel<<<(int)((n/4+255)/256),256>>>(fc2_w, w2h, w2l, n);
    }

    // ---- patch embed ----
    im2col_kernel<<<(int)(((long long)NTOK*KPATCH + 255)/256), 256>>>(x);
    {
        dim3 g((EMBED+BN-1)/BN, (NTOK+BM-1)/BM, 1);
        mma3_gemm<1,true,false><<<g,256,SMEMB>>>(
            imh, iml, cwh, cwl, conv_b, nullptr, h, nullptr, nullptr,
            NTOK, EMBED, KPATCH, KPATCH, KPATCH, EMBED, 0,
            Z0,Z0,Z0,Z0,Z0,Z0,Z0,Z0, 1);
    }
    freq_kernel<<<1, EMBED/2>>>();
    posadd_kernel<<<(NP*EMBED + 255)/256, 256>>>();

    // ---- transformer blocks ----
    for (int l = 0; l < DEPTH; l++) {
        bf16* lqwh = qwh + (long long)l*3*EMBED*EMBED;
        bf16* lqwl = qwl + (long long)l*3*EMBED*EMBED;
        bf16* lowh = owh + (long long)l*EMBED*EMBED;
        bf16* lowl = owl + (long long)l*EMBED*EMBED;
        bf16* lw1h = w1h + (long long)l*MLPH*EMBED;
        bf16* lw1l = w1l + (long long)l*MLPH*EMBED;
        bf16* lw2h = w2h + (long long)l*EMBED*MLPH;
        bf16* lw2l = w2l + (long long)l*EMBED*MLPH;
        const float* ob = out_b + (long long)l*EMBED;
        const float* b1 = fc1_b + (long long)l*MLPH;
        const float* b2 = fc2_b + (long long)l*EMBED;

        // y = LN1(h)  -> split
        ln_kernel<<<NTOK,256>>>(h, n1s + l*EMBED, n1b + l*EMBED, nullptr, yh, yl, EMBED);

        // qkv = y @ qw^T  -> split
        {
            dim3 g((3*EMBED+BN-1)/BN, (NTOK+BM-1)/BM, 1);
            mma3_gemm<0,true,true><<<g,256,SMEMB>>>(
                yh, yl, lqwh, lqwl, nullptr, nullptr, nullptr, qkvh, qkvl,
                NTOK, 3*EMBED, EMBED, EMBED, EMBED, 3*EMBED, 0,
                Z0,Z0,Z0,Z0,Z0,Z0,Z0,Z0, 1);
        }

        // S = Q @ K^T  fp32, batched over (b,h)
        {
            dim3 g((NP+BN-1)/BN, (NP+BM-1)/BM, BATCH*HEADS);
            mma3_gemm<0,true,false><<<g,256,SMEMB>>>(
                qkvh, qkvl, qkvh + EMBED, qkvl + EMBED, nullptr, nullptr,
                attn, nullptr, nullptr,
                NP, NP, HDIM, 3*EMBED, 3*EMBED, NP, 0,
                (long long)NP*3*EMBED, (long long)HDIM,
                (long long)NP*3*EMBED, (long long)HDIM,
                (long long)HEADS*NP*NP, (long long)NP*NP,
                Z0, Z0, HEADS);
        }

        softmax_kernel<<<BATCH*HEADS*NP, 256>>>(attn, Ph, Pl);

        // ao = P @ V  -> split, B in [K,N]
        {
            dim3 g((HDIM+BN-1)/BN, (NP+BM-1)/BM, BATCH*HEADS);
            mma3_gemm<0,false,true><<<g,256,SMEMB>>>(
                Ph, Pl, qkvh + 2*EMBED, qkvl + 2*EMBED, nullptr, nullptr,
                nullptr, aoh, aol,
                NP, HDIM, NP, NP, 3*EMBED, EMBED, 0,
                (long long)HEADS*NP*NP, (long long)NP*NP,
                (long long)NP*3*EMBED, (long long)HDIM,
                (long long)NP*EMBED, (long long)HDIM,
                Z0, Z0, HEADS);
        }

        // h = h + ao @ ow^T + ob
        {
            dim3 g((EMBED+BN-1)/BN, (NTOK+BM-1)/BM, 1);
            mma3_gemm<4,true,false><<<g,256,SMEMB>>>(
                aoh, aol, lowh, lowl, ob, h, h, nullptr, nullptr,
                NTOK, EMBED, EMBED, EMBED, EMBED, EMBED, EMBED,
                Z0,Z0,Z0,Z0,Z0,Z0,Z0,Z0, 1);
        }

        // y = LN2(h) -> split
        ln_kernel<<<NTOK,256>>>(h, n2s + l*EMBED, n2b + l*EMBED, nullptr, yh, yl, EMBED);

        // mlp = gelu(y @ w1^T + b1) -> split
        {
            dim3 g((MLPH+BN-1)/BN, (NTOK+BM-1)/BM, 1);
            mma3_gemm<2,true,true><<<g,256,SMEMB>>>(
                yh, yl, lw1h, lw1l, b1, nullptr, nullptr, mlph, mlpl,
                NTOK, MLPH, EMBED, EMBED, EMBED, MLPH, 0,
                Z0,Z0,Z0,Z0,Z0,Z0,Z0,Z0, 1);
        }

        // h = h + mlp @ w2^T + b2
        {
            dim3 g((EMBED+BN-1)/BN, (NTOK+BM-1)/BM, 1);
            mma3_gemm<4,true,false><<<g,256,SMEMB>>>(
                mlph, mlpl, lw2h, lw2l, b2, h, h, nullptr, nullptr,
                NTOK, EMBED, MLPH, MLPH, MLPH, EMBED, EMBED,
                Z0,Z0,Z0,Z0,Z0,Z0,Z0,Z0, 1);
        }
    }

    // ---- pooled head ----
    pool_kernel<<<(BATCH*EMBED + 255)/256, 256>>>();
    ln_kernel<<<BATCH,256>>>(pool, fns, fnb, pln, nullptr, nullptr, EMBED);
    head_kernel<<<(BATCH*1000*32 + 255)/256, 256>>>(head_w, head_b, out);
}

// round 5
// speedup vs baseline: 1.0394x; 1.0394x over previous
#include <cuda_runtime.h>
#include <cuda_bf16.h>
#include <math.h>
#include <stdint.h>

#define EMBED   768
#define HEADS   8
#define HDIM    96
#define DEPTH   12
#define MLPH    3072
#define NP      1568
#define BATCH   2
#define NTOK    (BATCH*NP)      // 3136
#define KPATCH  1536

typedef __nv_bfloat16 bf16;

// ---------------- scratch (device globals: allocation-free) ----------------
__device__ __align__(256) bf16  g_imh [NTOK*KPATCH];
__device__ __align__(256) bf16  g_iml [NTOK*KPATCH];
__device__ __align__(256) float g_h   [NTOK*EMBED];
__device__ __align__(256) bf16  g_yh  [NTOK*EMBED];
__device__ __align__(256) bf16  g_yl  [NTOK*EMBED];
__device__ __align__(256) bf16  g_qkvh[NTOK*3*EMBED];
__device__ __align__(256) bf16  g_qkvl[NTOK*3*EMBED];
__device__ __align__(256) float g_attn[39337984];     // 2*8*1568^2 fp32
__device__ __align__(256) bf16  g_Ph  [39337984];
__device__ __align__(256) bf16  g_Pl  [39337984];
__device__ __align__(256) bf16  g_vth [16*HDIM*NP];   // V^T per (b,h): [96][1568]
__device__ __align__(256) bf16  g_vtl [16*HDIM*NP];
__device__ __align__(256) bf16  g_aoh [NTOK*EMBED];
__device__ __align__(256) bf16  g_aol [NTOK*EMBED];
__device__ __align__(256) bf16  g_mlph[NTOK*MLPH];
__device__ __align__(256) bf16  g_mlpl[NTOK*MLPH];
__device__ float g_pool[BATCH*EMBED];
__device__ float g_pln [BATCH*EMBED];
__device__ double g_freq[EMBED/2];
// weight splits
__device__ __align__(256) bf16 g_cwh[EMBED*KPATCH];
__device__ __align__(256) bf16 g_cwl[EMBED*KPATCH];
__device__ __align__(256) bf16 g_qwh[DEPTH*3*EMBED*EMBED];
__device__ __align__(256) bf16 g_qwl[DEPTH*3*EMBED*EMBED];
__device__ __align__(256) bf16 g_owh[DEPTH*EMBED*EMBED];
__device__ __align__(256) bf16 g_owl[DEPTH*EMBED*EMBED];
__device__ __align__(256) bf16 g_w1h[DEPTH*MLPH*EMBED];
__device__ __align__(256) bf16 g_w1l[DEPTH*MLPH*EMBED];
__device__ __align__(256) bf16 g_w2h[DEPTH*EMBED*MLPH];
__device__ __align__(256) bf16 g_w2l[DEPTH*EMBED*MLPH];

__device__ __forceinline__ void split_bf16(float v, bf16& h, bf16& l)
{
    h = __float2bfloat16(v);
    l = __float2bfloat16(v - __bfloat162float(h));
}

// ================= GEMM v5: pre-split bf16, 3-stage cp.async, HMMA =========
// C = A @ B^T (+EPI). A[M,K] k-contig hi/lo, B[N,K] k-contig hi/lo.
// Block: 128 x BNT, BK=32. 8 warps = 4m x 2n, warp tile 32 x (BNT/2).
// EPI: 0 none | 1 +bias | 2 +bias,gelu | 4 +bias,+residual
#define BK 32
#define SA 40           // padded k-stride (elems); conflict-free LDSM (verified R2)

#define LDSM4(R, addr) \
    asm volatile("ldmatrix.sync.aligned.m8n8.x4.shared.b16 {%0,%1,%2,%3},[%4];" \
        : "=r"((R)[0]), "=r"((R)[1]), "=r"((R)[2]), "=r"((R)[3]) : "r"(addr))

#define MMA16816(C, A, B0, B1) \
    asm volatile("mma.sync.aligned.m16n8k16.row.col.f32.bf16.bf16.f32 " \
        "{%0,%1,%2,%3},{%4,%5,%6,%7},{%8,%9},{%0,%1,%2,%3};" \
        : "+f"((C)[0]), "+f"((C)[1]), "+f"((C)[2]), "+f"((C)[3]) \
        : "r"((A)[0]), "r"((A)[1]), "r"((A)[2]), "r"((A)[3]), "r"(B0), "r"(B1))

__device__ __forceinline__ void cpa16(uint32_t dst, const void* src, bool p)
{
    int sz = p ? 16 : 0;
    asm volatile("cp.async.cg.shared.global [%0],[%1],16,%2;\n"
                 :: "r"(dst), "l"(src), "r"(sz));
}

template<int EPI, bool SPLITOUT, int BNT>
__global__ void __launch_bounds__(256)
mma5_gemm(const bf16* __restrict__ Agh, const bf16* __restrict__ Agl,
          const bf16* __restrict__ Bgh, const bf16* __restrict__ Bgl,
          const float* __restrict__ bias, const float* __restrict__ R,
          float* __restrict__ Cf, bf16* __restrict__ Ch, bf16* __restrict__ Cl,
          int M, int N, int K, int lda, int ldb, int ldc, int ldr,
          long long zab, long long zah, long long zbb, long long zbh,
          long long zcb, long long zch, long long zrb, long long zrh, int H)
{
    constexpr int WN    = BNT / 2;        // warp n-span
    constexpr int NPR   = WN / 16;        // 16-col ldsm tiles per warp
    constexpr int OFFAL = 128 * SA;
    constexpr int OFFBH = 2 * 128 * SA;
    constexpr int STAGE = (2 * 128 + 2 * BNT) * SA;   // elems per stage

    const int z  = blockIdx.z;
    const int bb = z / H, hh = z % H;
    Agh += bb*zab + hh*zah;  Agl += bb*zab + hh*zah;
    Bgh += bb*zbb + hh*zbh;  Bgl += bb*zbb + hh*zbh;
    const long long coff = bb*zcb + hh*zch;
    if (SPLITOUT) { Ch += coff; Cl += coff; } else { Cf += coff; }
    if (EPI >= 3) R += bb*zrb + hh*zrh;

    extern __shared__ __align__(16) bf16 smem[];
    const uint32_t su = (uint32_t)__cvta_generic_to_shared(smem);

    const int tid  = threadIdx.x;
    const int lane = tid & 31;
    const int w    = tid >> 5;
    const int wm   = w >> 1;              // 0..3
    const int wn   = w & 1;               // 0..1
    const int m0   = blockIdx.y * 128;
    const int n0   = blockIdx.x * BNT;

    float c[2][2*NPR][4];
    #pragma unroll
    for (int i = 0; i < 2; i++)
        #pragma unroll
        for (int j = 0; j < 2*NPR; j++)
            #pragma unroll
            for (int q = 0; q < 4; q++) c[i][j][q] = 0.f;

    const int lrow = lane & 15;
    const int lcol = (lane >> 4) * 8;
    const uint32_t aoffA = (uint32_t)(((wm*32 + lrow)*SA + lcol) * 2);
    const uint32_t boffB = (uint32_t)(((wn*WN + lrow)*SA + lcol) * 2);

    const int T = K / BK;

    auto issue = [&](int t, int s) {
        const int k0 = t * BK;
        const uint32_t sb = su + (uint32_t)(s * STAGE) * 2u;
        #pragma unroll
        for (int i = 0; i < 4; i++) {                 // A hi/lo: 512 chunks each
            const int hl  = i >> 1;
            const int ch  = ((i & 1) << 8) + tid;
            const int row = ch >> 2;
            const int kc  = (ch & 3) << 3;
            const bool p  = (m0 + row) < M;
            const bf16* src = (hl ? Agl : Agh)
                            + (long long)(p ? (m0 + row) : 0) * lda + k0 + kc;
            cpa16(sb + (uint32_t)((hl ? OFFAL : 0) + row*SA + kc) * 2u, src, p);
        }
        constexpr int BI = BNT / 64;
        #pragma unroll
        for (int i = 0; i < 2*BI; i++) {              // B hi/lo
            const int hl  = i / BI;
            const int ch  = (i % BI) * 256 + tid;
            const int row = ch >> 2;
            const int kc  = (ch & 3) << 3;
            const bool p  = (n0 + row) < N;
            const bf16* src = (hl ? Bgl : Bgh)
                            + (long long)(p ? (n0 + row) : 0) * ldb + k0 + kc;
            cpa16(sb + (uint32_t)(OFFBH + hl*BNT*SA + row*SA + kc) * 2u, src, p);
        }
    };

    issue(0, 0);
    asm volatile("cp.async.commit_group;");
    if (T > 1) { issue(1, 1); asm volatile("cp.async.commit_group;"); }

    for (int t = 0; t < T; t++) {
        if (t + 1 < T) asm volatile("cp.async.wait_group 1;");
        else           asm volatile("cp.async.wait_group 0;");
        __syncthreads();

        if (t + 2 < T) {
            issue(t + 2, (t + 2) % 3);
            asm volatile("cp.async.commit_group;");
        }

        const int s = t % 3;
        const uint32_t sb  = su + (uint32_t)(s * STAGE) * 2u;
        const uint32_t aHb = sb + aoffA;
        const uint32_t aLb = aHb + (uint32_t)OFFAL * 2u;
        const uint32_t bHb = sb + (uint32_t)OFFBH * 2u + boffB;
        const uint32_t bLb = bHb + (uint32_t)(BNT*SA) * 2u;

        #pragma unroll
        for (int kk2 = 0; kk2 < 2; kk2++) {
            const uint32_t kb = (uint32_t)(kk2 * 32);      // 16 elems * 2B
            uint32_t Ahf[2][4], Alf[2][4], Bhf[NPR][4], Blf[NPR][4];
            #pragma unroll
            for (int mi = 0; mi < 2; mi++) {
                LDSM4(Ahf[mi], aHb + (uint32_t)(mi*16*SA*2) + kb);
                LDSM4(Alf[mi], aLb + (uint32_t)(mi*16*SA*2) + kb);
            }
            #pragma unroll
            for (int pr = 0; pr < NPR; pr++) {
                LDSM4(Bhf[pr], bHb + (uint32_t)(pr*16*SA*2) + kb);
                LDSM4(Blf[pr], bLb + (uint32_t)(pr*16*SA*2) + kb);
            }
            #pragma unroll
            for (int mi = 0; mi < 2; mi++) {
                #pragma unroll
                for (int pr = 0; pr < NPR; pr++) {
                    MMA16816(c[mi][2*pr  ], Ahf[mi], Bhf[pr][0], Bhf[pr][2]);
                    MMA16816(c[mi][2*pr  ], Ahf[mi], Blf[pr][0], Blf[pr][2]);
                    MMA16816(c[mi][2*pr  ], Alf[mi], Bhf[pr][0], Bhf[pr][2]);
                    MMA16816(c[mi][2*pr+1], Ahf[mi], Bhf[pr][1], Bhf[pr][3]);
                    MMA16816(c[mi][2*pr+1], Ahf[mi], Blf[pr][1], Blf[pr][3]);
                    MMA16816(c[mi][2*pr+1], Alf[mi], Bhf[pr][1], Bhf[pr][3]);
                }
            }
        }
    }

    // ---------------- epilogue (registers -> gmem, fused) ----------------
    const int g  = lane >> 2;
    const int tq = lane & 3;
    #pragma unroll
    for (int mi = 0; mi < 2; mi++) {
        #pragma unroll
        for (int nf = 0; nf < 2*NPR; nf++) {
            int col = n0 + wn*WN + nf*8 + tq*2;
            #pragma unroll
            for (int half = 0; half < 2; half++) {
                int row = m0 + wm*32 + mi*16 + g + half*8;
                if (row >= M || col >= N) continue;
                float v0 = c[mi][nf][half*2 + 0];
                float v1 = c[mi][nf][half*2 + 1];
                if (EPI == 1 || EPI == 2 || EPI == 4) { v0 += bias[col]; v1 += bias[col+1]; }
                if (EPI == 2) {
                    v0 = 0.5f * v0 * (1.0f + erff(v0 * 0.70710678118654752f));
                    v1 = 0.5f * v1 * (1.0f + erff(v1 * 0.70710678118654752f));
                }
                if (EPI >= 3) {
                    float2 r2 = *(const float2*)&R[(long long)row*ldr + col];
                    v0 += r2.x; v1 += r2.y;
                }
                if (SPLITOUT) {
                    bf16 h0,h1,l0,l1;
                    split_bf16(v0,h0,l0); split_bf16(v1,h1,l1);
                    __nv_bfloat162 ph; ph.x=h0; ph.y=h1;
                    __nv_bfloat162 pl; pl.x=l0; pl.y=l1;
                    *(__nv_bfloat162*)&Ch[(long long)row*ldc + col] = ph;
                    *(__nv_bfloat162*)&Cl[(long long)row*ldc + col] = pl;
                } else {
                    float2 o; o.x = v0; o.y = v1;
                    *(float2*)&Cf[(long long)row*ldc + col] = o;
                }
            }
        }
    }
}

// ---------------- V transpose: VT[z][n][k] = V[z][k][n] ----------------
__global__ void vtrans_kernel(const bf16* __restrict__ qh, const bf16* __restrict__ ql,
                              bf16* __restrict__ vth, bf16* __restrict__ vtl)
{
    __shared__ bf16 th[32][100];
    __shared__ bf16 tl[32][100];
    const int z = blockIdx.y, bb = z >> 3, hh = z & 7;
    const int k0 = blockIdx.x * 32;
    const int tid = threadIdx.x;
    const bf16* sh = qh + ((long long)(bb*NP) + k0)*(3*EMBED) + 2*EMBED + hh*HDIM;
    const bf16* sl = ql + ((long long)(bb*NP) + k0)*(3*EMBED) + 2*EMBED + hh*HDIM;
    for (int idx = tid; idx < 32*HDIM; idx += 256) {
        int kk = idx / HDIM, nn = idx % HDIM;
        th[kk][nn] = sh[(long long)kk*(3*EMBED) + nn];
        tl[kk][nn] = sl[(long long)kk*(3*EMBED) + nn];
    }
    __syncthreads();
    bf16* dh = vth + (long long)z*HDIM*NP + k0;
    bf16* dl = vtl + (long long)z*HDIM*NP + k0;
    for (int idx = tid; idx < 32*HDIM; idx += 256) {
        int nn = idx >> 5, kk = idx & 31;
        dh[(long long)nn*NP + kk] = th[kk][nn];
        dl[(long long)nn*NP + kk] = tl[kk][nn];
    }
}

// ---------------- fp32 -> bf16 hi/lo split ----------------
__global__ void split_kernel(const float* __restrict__ s, bf16* __restrict__ h,
                             bf16* __restrict__ l, long long n)
{
    long long i = ((long long)blockIdx.x*256 + threadIdx.x)*4;
    if (i >= n) return;
    float4 v = *(const float4*)&s[i];
    bf16 h0,h1,h2,h3,l0,l1,l2,l3;
    split_bf16(v.x,h0,l0); split_bf16(v.y,h1,l1);
    split_bf16(v.z,h2,l2); split_bf16(v.w,h3,l3);
    __nv_bfloat162 p;
    p.x=h0;p.y=h1; *(__nv_bfloat162*)&h[i  ]=p;
    p.x=h2;p.y=h3; *(__nv_bfloat162*)&h[i+2]=p;
    p.x=l0;p.y=l1; *(__nv_bfloat162*)&l[i  ]=p;
    p.x=l2;p.y=l3; *(__nv_bfloat162*)&l[i+2]=p;
}

// ---------------- layernorm ----------------
__global__ void ln_kernel(const float* __restrict__ X, const float* __restrict__ sc,
                          const float* __restrict__ bi, float* __restrict__ Yf,
                          bf16* __restrict__ Yh, bf16* __restrict__ Yl, int Cn)
{
    const float* x = X + (long long)blockIdx.x * Cn;
    __shared__ float sh1[32], sh2[32];
    int tid = threadIdx.x;
    float s = 0.f, s2 = 0.f;
    for (int i = tid; i < Cn; i += 256) { float v = x[i]; s += v; s2 += v*v; }
    #pragma unroll
    for (int o = 16; o > 0; o >>= 1) {
        s  += __shfl_xor_sync(0xffffffffu, s,  o);
        s2 += __shfl_xor_sync(0xffffffffu, s2, o);
    }
    if ((tid & 31) == 0) { sh1[tid>>5] = s; sh2[tid>>5] = s2; }
    __syncthreads();
    if (tid < 32) {
        float a = (tid < 8) ? sh1[tid] : 0.f;
        float b = (tid < 8) ? sh2[tid] : 0.f;
        #pragma unroll
        for (int o = 4; o > 0; o >>= 1) {
            a += __shfl_xor_sync(0xffffffffu, a, o);
            b += __shfl_xor_sync(0xffffffffu, b, o);
        }
        if (tid == 0) { sh1[0] = a; sh2[0] = b; }
    }
    __syncthreads();
    float mean = sh1[0] / Cn;
    float var  = sh2[0] / Cn - mean*mean;
    float inv  = rsqrtf(var + 1e-5f);
    for (int i = tid; i < Cn; i += 256) {
        float v = (x[i] - mean) * inv * sc[i] + bi[i];
        if (Yf) Yf[(long long)blockIdx.x*Cn + i] = v;
        if (Yh) {
            bf16 h, l; split_bf16(v, h, l);
            Yh[(long long)blockIdx.x*Cn + i] = h;
            Yl[(long long)blockIdx.x*Cn + i] = l;
        }
    }
}

// ---------------- softmax (fp32 in, split bf16 out) ----------------
__global__ void softmax_kernel(const float* __restrict__ S,
                               bf16* __restrict__ Ph, bf16* __restrict__ Pl)
{
    const float* p = S + (long long)blockIdx.x * NP;
    bf16* ph = Ph + (long long)blockIdx.x * NP;
    bf16* pl = Pl + (long long)blockIdx.x * NP;
    __shared__ float sh[32];
    int tid = threadIdx.x;
    const int IT = (NP + 255) / 256;
    float vals[(NP + 255) / 256];
    float mx = -1e30f;
    #pragma unroll
    for (int it = 0; it < IT; it++) {
        int i = tid + it*256;
        float v = (i < NP) ? p[i] : -1e30f;
        vals[it] = v;
        mx = fmaxf(mx, v);
    }
    #pragma unroll
    for (int o = 16; o > 0; o >>= 1) mx = fmaxf(mx, __shfl_xor_sync(0xffffffffu, mx, o));
    if ((tid & 31) == 0) sh[tid>>5] = mx;
    __syncthreads();
    if (tid < 32) {
        float v = (tid < 8) ? sh[tid] : -1e30f;
        #pragma unroll
        for (int o = 4; o > 0; o >>= 1) v = fmaxf(v, __shfl_xor_sync(0xffffffffu, v, o));
        if (tid == 0) sh[0] = v;
    }
    __syncthreads();
    mx = sh[0];
    __syncthreads();
    float sum = 0.f;
    #pragma unroll
    for (int it = 0; it < IT; it++) {
        int i = tid + it*256;
        float e = (i < NP) ? expf(vals[it] - mx) : 0.f;
        vals[it] = e;
        sum += e;
    }
    #pragma unroll
    for (int o = 16; o > 0; o >>= 1) sum += __shfl_xor_sync(0xffffffffu, sum, o);
    if ((tid & 31) == 0) sh[tid>>5] = sum;
    __syncthreads();
    if (tid < 32) {
        float v = (tid < 8) ? sh[tid] : 0.f;
        #pragma unroll
        for (int o = 4; o > 0; o >>= 1) v += __shfl_xor_sync(0xffffffffu, v, o);
        if (tid == 0) sh[0] = v;
    }
    __syncthreads();
    float inv = 1.0f / sh[0];
    #pragma unroll
    for (int it = 0; it < IT; it++) {
        int i = tid + it*256;
        if (i < NP) {
            float v = vals[it] * inv;
            bf16 h, l; split_bf16(v, h, l);
            ph[i] = h; pl[i] = l;
        }
    }
}

// ---------------- im2col (writes split bf16) ----------------
__global__ void im2col_kernel(const float* __restrict__ x)
{
    long long idx = (long long)blockIdx.x * 256 + threadIdx.x;
    if (idx >= (long long)NTOK * KPATCH) return;
    int j = (int)(idx % KPATCH);
    int m = (int)(idx / KPATCH);
    int b = m / NP, n = m % NP;
    int t = n / 196, r = n % 196, yy = r / 14, xx = r % 14;
    int i  = j / 512, r2 = j % 512;
    int dt = r2 / 256, r3 = r2 % 256;
    int dy = r3 / 16,  dx = r3 % 16;
    long long off = ((((long long)(b*3 + i)*16 + (2*t + dt))*224) + (16*yy + dy))*224 + (16*xx + dx);
    float v = x[off];
    bf16 h, l; split_bf16(v, h, l);
    g_imh[idx] = h; g_iml[idx] = l;
}

// ---------------- positional encoding ----------------
__global__ void freq_kernel()
{
    int c2 = threadIdx.x;
    if (c2 < EMBED/2) g_freq[c2] = pow(10000.0, -2.0 * c2 / (double)EMBED);
}
__global__ void posadd_kernel()
{
    int idx = blockIdx.x * 256 + threadIdx.x;
    if (idx >= NP*EMBED) return;
    int n = idx / EMBED, c = idx % EMBED;
    double a = (double)n * g_freq[c >> 1];
    const double TWO_PI = 6.283185307179586476925286766559;
    int k = (int)(a * (1.0 / TWO_PI) + 0.5);
    float rf = (float)(a - (double)k * TWO_PI);
    float v = (c & 1) ? cosf(rf) : sinf(rf);
    g_h[idx]            += v;
    g_h[idx + NP*EMBED] += v;
}

// ---------------- mean pool ----------------
__global__ void pool_kernel()
{
    int idx = blockIdx.x * 256 + threadIdx.x;
    if (idx >= BATCH*EMBED) return;
    int b = idx / EMBED, c = idx % EMBED;
    const float* base = g_h + (long long)b*NP*EMBED + c;
    float s = 0.f;
    for (int n = 0; n < NP; n++) s += base[(long long)n*EMBED];
    g_pool[idx] = s * (1.0f / NP);
}

// ---------------- classifier head ----------------
__global__ void head_kernel(const float* __restrict__ W, const float* __restrict__ hb,
                            float* __restrict__ out)
{
    int g = blockIdx.x * 256 + threadIdx.x;
    int warp = g >> 5, lane = g & 31;
    if (warp >= BATCH*1000) return;
    int b = warp / 1000, j = warp % 1000;
    float s = 0.f;
    for (int c = lane; c < EMBED; c += 32)
        s += g_pln[b*EMBED + c] * W[j*EMBED + c];
    #pragma unroll
    for (int o = 16; o > 0; o >>= 1) s += __shfl_xor_sync(0xffffffffu, s, o);
    if (lane == 0) out[warp] = s + hb[j];
}

// ---------------- host orchestration ----------------
#define DS128 ((2*128 + 2*128)*SA*2*3)   // 122880 B
#define DS64  ((2*128 + 2*64 )*SA*2*3)   //  92160 B

extern "C" void kernel_launch(void* const* d_in, const int* in_sizes, int n_in,
                              void* d_out, int out_size)
{
    const float* x      = (const float*)d_in[0];
    const float* conv_w = (const float*)d_in[1];
    const float* conv_b = (const float*)d_in[2];
    const float* n1s    = (const float*)d_in[3];
    const float* n1b    = (const float*)d_in[4];
    const float* qkv_w  = (const float*)d_in[5];
    const float* out_w  = (const float*)d_in[6];
    const float* out_b  = (const float*)d_in[7];
    const float* n2s    = (const float*)d_in[8];
    const float* n2b    = (const float*)d_in[9];
    const float* fc1_w  = (const float*)d_in[10];
    const float* fc1_b  = (const float*)d_in[11];
    const float* fc2_w  = (const float*)d_in[12];
    const float* fc2_b  = (const float*)d_in[13];
    const float* fns    = (const float*)d_in[14];
    const float* fnb    = (const float*)d_in[15];
    const float* head_w = (const float*)d_in[16];
    const float* head_b = (const float*)d_in[17];
    float* out = (float*)d_out;

    float *h, *attn, *pool, *pln;
    bf16 *imh,*iml,*yh,*yl,*qkvh,*qkvl,*Ph,*Pl,*vth,*vtl,*aoh,*aol,*mlph,*mlpl;
    bf16 *cwh,*cwl,*qwh,*qwl,*owh,*owl,*w1h,*w1l,*w2h,*w2l;
    cudaGetSymbolAddress((void**)&h,    g_h);
    cudaGetSymbolAddress((void**)&attn, g_attn);
    cudaGetSymbolAddress((void**)&pool, g_pool);
    cudaGetSymbolAddress((void**)&pln,  g_pln);
    cudaGetSymbolAddress((void**)&imh,  g_imh);   cudaGetSymbolAddress((void**)&iml, g_iml);
    cudaGetSymbolAddress((void**)&yh,   g_yh);    cudaGetSymbolAddress((void**)&yl,  g_yl);
    cudaGetSymbolAddress((void**)&qkvh, g_qkvh);  cudaGetSymbolAddress((void**)&qkvl,g_qkvl);
    cudaGetSymbolAddress((void**)&Ph,   g_Ph);    cudaGetSymbolAddress((void**)&Pl,  g_Pl);
    cudaGetSymbolAddress((void**)&vth,  g_vth);   cudaGetSymbolAddress((void**)&vtl, g_vtl);
    cudaGetSymbolAddress((void**)&aoh,  g_aoh);   cudaGetSymbolAddress((void**)&aol, g_aol);
    cudaGetSymbolAddress((void**)&mlph, g_mlph);  cudaGetSymbolAddress((void**)&mlpl,g_mlpl);
    cudaGetSymbolAddress((void**)&cwh,  g_cwh);   cudaGetSymbolAddress((void**)&cwl, g_cwl);
    cudaGetSymbolAddress((void**)&qwh,  g_qwh);   cudaGetSymbolAddress((void**)&qwl, g_qwl);
    cudaGetSymbolAddress((void**)&owh,  g_owh);   cudaGetSymbolAddress((void**)&owl, g_owl);
    cudaGetSymbolAddress((void**)&w1h,  g_w1h);   cudaGetSymbolAddress((void**)&w1l, g_w1l);
    cudaGetSymbolAddress((void**)&w2h,  g_w2h);   cudaGetSymbolAddress((void**)&w2l, g_w2l);

    cudaFuncSetAttribute(mma5_gemm<1,false,64 >, cudaFuncAttributeMaxDynamicSharedMemorySize, DS64);
    cudaFuncSetAttribute(mma5_gemm<0,true ,128>, cudaFuncAttributeMaxDynamicSharedMemorySize, DS128);
    cudaFuncSetAttribute(mma5_gemm<0,false,128>, cudaFuncAttributeMaxDynamicSharedMemorySize, DS128);
    cudaFuncSetAttribute(mma5_gemm<4,false,64 >, cudaFuncAttributeMaxDynamicSharedMemorySize, DS64);
    cudaFuncSetAttribute(mma5_gemm<2,true ,128>, cudaFuncAttributeMaxDynamicSharedMemorySize, DS128);

    const long long Z0 = 0;

    // ---- weight splits ----
    {
        long long n;
        n = (long long)EMBED*KPATCH;
        split_kernel<<<(int)((n/4+255)/256),256>>>(conv_w, cwh, cwl, n);
        n = (long long)DEPTH*3*EMBED*EMBED;
        split_kernel<<<(int)((n/4+255)/256),256>>>(qkv_w, qwh, qwl, n);
        n = (long long)DEPTH*EMBED*EMBED;
        split_kernel<<<(int)((n/4+255)/256),256>>>(out_w, owh, owl, n);
        n = (long long)DEPTH*MLPH*EMBED;
        split_kernel<<<(int)((n/4+255)/256),256>>>(fc1_w, w1h, w1l, n);
        n = (long long)DEPTH*EMBED*MLPH;
        split_kernel<<<(int)((n/4+255)/256),256>>>(fc2_w, w2h, w2l, n);
    }

    // ---- patch embed ----
    im2col_kernel<<<(int)(((long long)NTOK*KPATCH + 255)/256), 256>>>(x);
    {
        dim3 g(EMBED/64, (NTOK+127)/128, 1);
        mma5_gemm<1,false,64><<<g,256,DS64>>>(
            imh, iml, cwh, cwl, conv_b, nullptr, h, nullptr, nullptr,
            NTOK, EMBED, KPATCH, KPATCH, KPATCH, EMBED, 0,
            Z0,Z0,Z0,Z0,Z0,Z0,Z0,Z0, 1);
    }
    freq_kernel<<<1, EMBED/2>>>();
    posadd_kernel<<<(NP*EMBED + 255)/256, 256>>>();

    // ---- transformer blocks ----
    for (int l = 0; l < DEPTH; l++) {
        bf16* lqwh = qwh + (long long)l*3*EMBED*EMBED;
        bf16* lqwl = qwl + (long long)l*3*EMBED*EMBED;
        bf16* lowh = owh + (long long)l*EMBED*EMBED;
        bf16* lowl = owl + (long long)l*EMBED*EMBED;
        bf16* lw1h = w1h + (long long)l*MLPH*EMBED;
        bf16* lw1l = w1l + (long long)l*MLPH*EMBED;
        bf16* lw2h = w2h + (long long)l*EMBED*MLPH;
        bf16* lw2l = w2l + (long long)l*EMBED*MLPH;
        const float* ob = out_b + (long long)l*EMBED;
        const float* b1 = fc1_b + (long long)l*MLPH;
        const float* b2 = fc2_b + (long long)l*EMBED;

        ln_kernel<<<NTOK,256>>>(h, n1s + l*EMBED, n1b + l*EMBED, nullptr, yh, yl, EMBED);

        {   // qkv = y @ qw^T  -> split
            dim3 g((3*EMBED)/128, (NTOK+127)/128, 1);
            mma5_gemm<0,true,128><<<g,256,DS128>>>(
                yh, yl, lqwh, lqwl, nullptr, nullptr, nullptr, qkvh, qkvl,
                NTOK, 3*EMBED, EMBED, EMBED, EMBED, 3*EMBED, 0,
                Z0,Z0,Z0,Z0,Z0,Z0,Z0,Z0, 1);
        }

        {   // V^T per (b,h)
            dim3 g(NP/32, BATCH*HEADS, 1);
            vtrans_kernel<<<g,256>>>(qkvh, qkvl, vth, vtl);
        }

        {   // S = Q @ K^T  fp32
            dim3 g((NP+127)/128, (NP+127)/128, BATCH*HEADS);
            mma5_gemm<0,false,128><<<g,256,DS128>>>(
                qkvh, qkvl, qkvh + EMBED, qkvl + EMBED, nullptr, nullptr,
                attn, nullptr, nullptr,
                NP, NP, HDIM, 3*EMBED, 3*EMBED, NP, 0,
                (long long)NP*3*EMBED, (long long)HDIM,
                (long long)NP*3*EMBED, (long long)HDIM,
                (long long)HEADS*NP*NP, (long long)NP*NP,
                Z0, Z0, HEADS);
        }

        softmax_kernel<<<BATCH*HEADS*NP, 256>>>(attn, Ph, Pl);

        {   // ao = P @ VT^T  -> split  (N=96)
            dim3 g(1, (NP+127)/128, BATCH*HEADS);
            mma5_gemm<0,true,128><<<g,256,DS128>>>(
                Ph, Pl, vth, vtl, nullptr, nullptr, nullptr, aoh, aol,
                NP, HDIM, NP, NP, NP, EMBED, 0,
                (long long)HEADS*NP*NP, (long long)NP*NP,
                (long long)HEADS*HDIM*NP, (long long)HDIM*NP,
                (long long)NP*EMBED, (long long)HDIM,
                Z0, Z0, HEADS);
        }

        {   // h = h + ao @ ow^T + ob
            dim3 g(EMBED/64, (NTOK+127)/128, 1);
            mma5_gemm<4,false,64><<<g,256,DS64>>>(
                aoh, aol, lowh, lowl, ob, h, h, nullptr, nullptr,
                NTOK, EMBED, EMBED, EMBED, EMBED, EMBED, EMBED,
                Z0,Z0,Z0,Z0,Z0,Z0,Z0,Z0, 1);
        }

        ln_kernel<<<NTOK,256>>>(h, n2s + l*EMBED, n2b + l*EMBED, nullptr, yh, yl, EMBED);

        {   // mlp = gelu(y @ w1^T + b1) -> split
            dim3 g(MLPH/128, (NTOK+127)/128, 1);
            mma5_gemm<2,true,128><<<g,256,DS128>>>(
                yh, yl, lw1h, lw1l, b1, nullptr, nullptr, mlph, mlpl,
                NTOK, MLPH, EMBED, EMBED, EMBED, MLPH, 0,
                Z0,Z0,Z0,Z0,Z0,Z0,Z0,Z0, 1);
        }

        {   // h = h + mlp @ w2^T + b2
            dim3 g(EMBED/64, (NTOK+127)/128, 1);
            mma5_gemm<4,false,64><<<g,256,DS64>>>(
                mlph, mlpl, lw2h, lw2l, b2, h, h, nullptr, nullptr,
                NTOK, EMBED, MLPH, MLPH, MLPH, EMBED, EMBED,
                Z0,Z0,Z0,Z0,Z0,Z0,Z0,Z0, 1);
        }
    }

    // ---- pooled head ----
    pool_kernel<<<(BATCH*EMBED + 255)/256, 256>>>();
    ln_kernel<<<BATCH,256>>>(pool, fns, fnb, pln, nullptr, nullptr, EMBED);
    head_kernel<<<(BATCH*1000*32 + 255)/256, 256>>>(head_w, head_b, out);
}

// round 6
// speedup vs baseline: 1.0772x; 1.0364x over previous
#include <cuda_runtime.h>
#include <cuda_fp16.h>
#include <math.h>
#include <stdint.h>

#define EMBED   768
#define HEADS   8
#define HDIM    96
#define DEPTH   12
#define MLPH    3072
#define NP      1568
#define BATCH   2
#define NTOK    (BATCH*NP)      // 3136
#define KPATCH  1536

typedef __half h16;

// ---------------- scratch (device globals: allocation-free) ----------------
__device__ __align__(256) h16   g_imh [NTOK*KPATCH];
__device__ __align__(256) h16   g_iml [NTOK*KPATCH];
__device__ __align__(256) float g_h   [NTOK*EMBED];
__device__ __align__(256) h16   g_yh  [NTOK*EMBED];
__device__ __align__(256) h16   g_yl  [NTOK*EMBED];
__device__ __align__(256) h16   g_qkvh[NTOK*3*EMBED];
__device__ __align__(256) h16   g_qkvl[NTOK*3*EMBED];
__device__ __align__(256) float g_attn[39337984];     // 2*8*1568^2 fp32
__device__ __align__(256) h16   g_Ph  [39337984];
__device__ __align__(256) h16   g_Pl  [39337984];
__device__ __align__(256) h16   g_vth [16*HDIM*NP];   // V^T per (b,h): [96][1568]
__device__ __align__(256) h16   g_vtl [16*HDIM*NP];
__device__ __align__(256) h16   g_aoh [NTOK*EMBED];
__device__ __align__(256) h16   g_aol [NTOK*EMBED];
__device__ __align__(256) h16   g_mlph[NTOK*MLPH];
__device__ __align__(256) h16   g_mlpl[NTOK*MLPH];
__device__ float g_pool[BATCH*EMBED];
__device__ float g_pln [BATCH*EMBED];
__device__ double g_freq[EMBED/2];
// weight splits
__device__ __align__(256) h16 g_cwh[EMBED*KPATCH];
__device__ __align__(256) h16 g_cwl[EMBED*KPATCH];
__device__ __align__(256) h16 g_qwh[DEPTH*3*EMBED*EMBED];
__device__ __align__(256) h16 g_qwl[DEPTH*3*EMBED*EMBED];
__device__ __align__(256) h16 g_owh[DEPTH*EMBED*EMBED];
__device__ __align__(256) h16 g_owl[DEPTH*EMBED*EMBED];
__device__ __align__(256) h16 g_w1h[DEPTH*MLPH*EMBED];
__device__ __align__(256) h16 g_w1l[DEPTH*MLPH*EMBED];
__device__ __align__(256) h16 g_w2h[DEPTH*EMBED*MLPH];
__device__ __align__(256) h16 g_w2l[DEPTH*EMBED*MLPH];

__device__ __forceinline__ void split_f16(float v, h16& h, h16& l)
{
    h = __float2half_rn(v);
    l = __float2half_rn(v - __half2float(h));
}

// ================= GEMM v6: fp16 hi/lo, f16-accum corrections ==============
// C = A @ B^T (+EPI). A[M,K] k-contig hi/lo, B[N,K] k-contig hi/lo.
// Block: 128 x BNT, BK=32. 8 warps = 4m x 2n, warp tile 32 x (BNT/2).
// Main: f16xf16->f32. Corrections (Ah*Bl + Al*Bh): f16xf16->f16 shared accum.
// EPI: 0 none | 1 +bias | 2 +bias,gelu | 4 +bias,+residual
#define BK 32
#define SA 40           // padded k-stride (elems); conflict-free LDSM

#define LDSM4(R, addr) \
    asm volatile("ldmatrix.sync.aligned.m8n8.x4.shared.b16 {%0,%1,%2,%3},[%4];" \
        : "=r"((R)[0]), "=r"((R)[1]), "=r"((R)[2]), "=r"((R)[3]) : "r"(addr))

#define MMA_F32(C, A, B0, B1) \
    asm volatile("mma.sync.aligned.m16n8k16.row.col.f32.f16.f16.f32 " \
        "{%0,%1,%2,%3},{%4,%5,%6,%7},{%8,%9},{%0,%1,%2,%3};" \
        : "+f"((C)[0]), "+f"((C)[1]), "+f"((C)[2]), "+f"((C)[3]) \
        : "r"((A)[0]), "r"((A)[1]), "r"((A)[2]), "r"((A)[3]), "r"(B0), "r"(B1))

#define MMA_F16(C, A, B0, B1) \
    asm volatile("mma.sync.aligned.m16n8k16.row.col.f16.f16.f16.f16 " \
        "{%0,%1},{%2,%3,%4,%5},{%6,%7},{%0,%1};" \
        : "+r"((C)[0]), "+r"((C)[1]) \
        : "r"((A)[0]), "r"((A)[1]), "r"((A)[2]), "r"((A)[3]), "r"(B0), "r"(B1))

__device__ __forceinline__ void cpa16(uint32_t dst, const void* src, bool p)
{
    int sz = p ? 16 : 0;
    asm volatile("cp.async.cg.shared.global [%0],[%1],16,%2;\n"
                 :: "r"(dst), "l"(src), "r"(sz));
}

template<int EPI, bool SPLITOUT, int BNT>
__global__ void __launch_bounds__(256)
mma6_gemm(const h16* __restrict__ Agh, const h16* __restrict__ Agl,
          const h16* __restrict__ Bgh, const h16* __restrict__ Bgl,
          const float* __restrict__ bias, const float* __restrict__ R,
          float* __restrict__ Cf, h16* __restrict__ Ch, h16* __restrict__ Cl,
          int M, int N, int K, int lda, int ldb, int ldc, int ldr,
          long long zab, long long zah, long long zbb, long long zbh,
          long long zcb, long long zch, long long zrb, long long zrh, int H)
{
    constexpr int WN    = BNT / 2;        // warp n-span
    constexpr int NPR   = WN / 16;        // 16-col ldsm tiles per warp
    constexpr int OFFAL = 128 * SA;
    constexpr int OFFBH = 2 * 128 * SA;
    constexpr int STAGE = (2 * 128 + 2 * BNT) * SA;   // elems per stage

    const int z  = blockIdx.z;
    const int bb = z / H, hh = z % H;
    Agh += bb*zab + hh*zah;  Agl += bb*zab + hh*zah;
    Bgh += bb*zbb + hh*zbh;  Bgl += bb*zbb + hh*zbh;
    const long long coff = bb*zcb + hh*zch;
    if (SPLITOUT) { Ch += coff; Cl += coff; } else { Cf += coff; }
    if (EPI >= 3) R += bb*zrb + hh*zrh;

    extern __shared__ __align__(16) h16 smem[];
    const uint32_t su = (uint32_t)__cvta_generic_to_shared(smem);

    const int tid  = threadIdx.x;
    const int lane = tid & 31;
    const int w    = tid >> 5;
    const int wm   = w >> 1;              // 0..3
    const int wn   = w & 1;               // 0..1
    const int m0   = blockIdx.y * 128;
    const int n0   = blockIdx.x * BNT;

    float    c [2][2*NPR][4];
    uint32_t cc[2][2*NPR][2];
    #pragma unroll
    for (int i = 0; i < 2; i++)
        #pragma unroll
        for (int j = 0; j < 2*NPR; j++) {
            #pragma unroll
            for (int q = 0; q < 4; q++) c[i][j][q] = 0.f;
            cc[i][j][0] = 0u; cc[i][j][1] = 0u;
        }

    const int lrow = lane & 15;
    const int lcol = (lane >> 4) * 8;
    const uint32_t aoffA = (uint32_t)(((wm*32 + lrow)*SA + lcol) * 2);
    const uint32_t boffB = (uint32_t)(((wn*WN + lrow)*SA + lcol) * 2);

    const int T = K / BK;

    auto issue = [&](int t, int s) {
        const int k0 = t * BK;
        const uint32_t sb = su + (uint32_t)(s * STAGE) * 2u;
        #pragma unroll
        for (int i = 0; i < 4; i++) {                 // A hi/lo: 512 chunks each
            const int hl  = i >> 1;
            const int ch  = ((i & 1) << 8) + tid;
            const int row = ch >> 2;
            const int kc  = (ch & 3) << 3;
            const bool p  = (m0 + row) < M;
            const h16* src = (hl ? Agl : Agh)
                           + (long long)(p ? (m0 + row) : 0) * lda + k0 + kc;
            cpa16(sb + (uint32_t)((hl ? OFFAL : 0) + row*SA + kc) * 2u, src, p);
        }
        constexpr int BCH = BNT / 32;                 // B chunk iterations
        #pragma unroll
        for (int i = 0; i < BCH; i++) {               // B hi/lo: 2*BNT*4 chunks
            const int ch  = i*256 + tid;
            const int hl  = ch / (BNT*4);
            const int rem = ch % (BNT*4);
            const int row = rem >> 2;
            const int kc  = (rem & 3) << 3;
            const bool p  = (n0 + row) < N;
            const h16* src = (hl ? Bgl : Bgh)
                           + (long long)(p ? (n0 + row) : 0) * ldb + k0 + kc;
            cpa16(sb + (uint32_t)(OFFBH + hl*BNT*SA + row*SA + kc) * 2u, src, p);
        }
    };

    issue(0, 0);
    asm volatile("cp.async.commit_group;");
    if (T > 1) { issue(1, 1); asm volatile("cp.async.commit_group;"); }

    for (int t = 0; t < T; t++) {
        if (t + 1 < T) asm volatile("cp.async.wait_group 1;");
        else           asm volatile("cp.async.wait_group 0;");
        __syncthreads();

        if (t + 2 < T) {
            issue(t + 2, (t + 2) % 3);
            asm volatile("cp.async.commit_group;");
        }

        const int s = t % 3;
        const uint32_t sb  = su + (uint32_t)(s * STAGE) * 2u;
        const uint32_t aHb = sb + aoffA;
        const uint32_t aLb = aHb + (uint32_t)OFFAL * 2u;
        const uint32_t bHb = sb + (uint32_t)OFFBH * 2u + boffB;
        const uint32_t bLb = bHb + (uint32_t)(BNT*SA) * 2u;

        #pragma unroll
        for (int kk2 = 0; kk2 < 2; kk2++) {
            const uint32_t kb = (uint32_t)(kk2 * 32);      // 16 elems * 2B
            uint32_t Ahf[2][4], Alf[2][4], Bhf[NPR][4], Blf[NPR][4];
            #pragma unroll
            for (int mi = 0; mi < 2; mi++) {
                LDSM4(Ahf[mi], aHb + (uint32_t)(mi*16*SA*2) + kb);
                LDSM4(Alf[mi], aLb + (uint32_t)(mi*16*SA*2) + kb);
            }
            #pragma unroll
            for (int pr = 0; pr < NPR; pr++) {
                LDSM4(Bhf[pr], bHb + (uint32_t)(pr*16*SA*2) + kb);
                LDSM4(Blf[pr], bLb + (uint32_t)(pr*16*SA*2) + kb);
            }
            #pragma unroll
            for (int mi = 0; mi < 2; mi++) {
                #pragma unroll
                for (int pr = 0; pr < NPR; pr++) {
                    // main terms (f32 accum)
                    MMA_F32(c[mi][2*pr  ], Ahf[mi], Bhf[pr][0], Bhf[pr][2]);
                    MMA_F32(c[mi][2*pr+1], Ahf[mi], Bhf[pr][1], Bhf[pr][3]);
                    // corrections (shared f16 accum)
                    MMA_F16(cc[mi][2*pr  ], Ahf[mi], Blf[pr][0], Blf[pr][2]);
                    MMA_F16(cc[mi][2*pr  ], Alf[mi], Bhf[pr][0], Bhf[pr][2]);
                    MMA_F16(cc[mi][2*pr+1], Ahf[mi], Blf[pr][1], Blf[pr][3]);
                    MMA_F16(cc[mi][2*pr+1], Alf[mi], Bhf[pr][1], Bhf[pr][3]);
                }
            }
        }
    }

    // ---------------- epilogue (registers -> gmem, fused) ----------------
    const int g  = lane >> 2;
    const int tq = lane & 3;
    #pragma unroll
    for (int mi = 0; mi < 2; mi++) {
        #pragma unroll
        for (int nf = 0; nf < 2*NPR; nf++) {
            int col = n0 + wn*WN + nf*8 + tq*2;
            #pragma unroll
            for (int half = 0; half < 2; half++) {
                int row = m0 + wm*32 + mi*16 + g + half*8;
                if (row >= M || col >= N) continue;
                __half2 corr = *(__half2*)&cc[mi][nf][half];
                float v0 = c[mi][nf][half*2 + 0] + __low2float(corr);
                float v1 = c[mi][nf][half*2 + 1] + __high2float(corr);
                if (EPI == 1 || EPI == 2 || EPI == 4) { v0 += bias[col]; v1 += bias[col+1]; }
                if (EPI == 2) {
                    v0 = 0.5f * v0 * (1.0f + erff(v0 * 0.70710678118654752f));
                    v1 = 0.5f * v1 * (1.0f + erff(v1 * 0.70710678118654752f));
                }
                if (EPI >= 3) {
                    float2 r2 = *(const float2*)&R[(long long)row*ldr + col];
                    v0 += r2.x; v1 += r2.y;
                }
                if (SPLITOUT) {
                    h16 h0,h1,l0,l1;
                    split_f16(v0,h0,l0); split_f16(v1,h1,l1);
                    *(__half2*)&Ch[(long long)row*ldc + col] = __halves2half2(h0,h1);
                    *(__half2*)&Cl[(long long)row*ldc + col] = __halves2half2(l0,l1);
                } else {
                    float2 o; o.x = v0; o.y = v1;
                    *(float2*)&Cf[(long long)row*ldc + col] = o;
                }
            }
        }
    }
}

// ---------------- V transpose: VT[z][n][k] = V[z][k][n] ----------------
__global__ void vtrans_kernel(const h16* __restrict__ qh, const h16* __restrict__ ql,
                              h16* __restrict__ vth, h16* __restrict__ vtl)
{
    __shared__ h16 th[32][100];
    __shared__ h16 tl[32][100];
    const int z = blockIdx.y, bb = z >> 3, hh = z & 7;
    const int k0 = blockIdx.x * 32;
    const int tid = threadIdx.x;
    const h16* sh = qh + ((long long)(bb*NP) + k0)*(3*EMBED) + 2*EMBED + hh*HDIM;
    const h16* sl = ql + ((long long)(bb*NP) + k0)*(3*EMBED) + 2*EMBED + hh*HDIM;
    for (int idx = tid; idx < 32*HDIM; idx += 256) {
        int kk = idx / HDIM, nn = idx % HDIM;
        th[kk][nn] = sh[(long long)kk*(3*EMBED) + nn];
        tl[kk][nn] = sl[(long long)kk*(3*EMBED) + nn];
    }
    __syncthreads();
    h16* dh = vth + (long long)z*HDIM*NP + k0;
    h16* dl = vtl + (long long)z*HDIM*NP + k0;
    for (int idx = tid; idx < 32*HDIM; idx += 256) {
        int nn = idx >> 5, kk = idx & 31;
        dh[(long long)nn*NP + kk] = th[kk][nn];
        dl[(long long)nn*NP + kk] = tl[kk][nn];
    }
}

// ---------------- fp32 -> fp16 hi/lo split ----------------
__global__ void split_kernel(const float* __restrict__ s, h16* __restrict__ h,
                             h16* __restrict__ l, long long n)
{
    long long i = ((long long)blockIdx.x*256 + threadIdx.x)*4;
    if (i >= n) return;
    float4 v = *(const float4*)&s[i];
    h16 h0,h1,h2,h3,l0,l1,l2,l3;
    split_f16(v.x,h0,l0); split_f16(v.y,h1,l1);
    split_f16(v.z,h2,l2); split_f16(v.w,h3,l3);
    *(__half2*)&h[i  ] = __halves2half2(h0,h1);
    *(__half2*)&h[i+2] = __halves2half2(h2,h3);
    *(__half2*)&l[i  ] = __halves2half2(l0,l1);
    *(__half2*)&l[i+2] = __halves2half2(l2,l3);
}

// ---------------- layernorm ----------------
__global__ void ln_kernel(const float* __restrict__ X, const float* __restrict__ sc,
                          const float* __restrict__ bi, float* __restrict__ Yf,
                          h16* __restrict__ Yh, h16* __restrict__ Yl, int Cn)
{
    const float* x = X + (long long)blockIdx.x * Cn;
    __shared__ float sh1[32], sh2[32];
    int tid = threadIdx.x;
    float s = 0.f, s2 = 0.f;
    for (int i = tid; i < Cn; i += 256) { float v = x[i]; s += v; s2 += v*v; }
    #pragma unroll
    for (int o = 16; o > 0; o >>= 1) {
        s  += __shfl_xor_sync(0xffffffffu, s,  o);
        s2 += __shfl_xor_sync(0xffffffffu, s2, o);
    }
    if ((tid & 31) == 0) { sh1[tid>>5] = s; sh2[tid>>5] = s2; }
    __syncthreads();
    if (tid < 32) {
        float a = (tid < 8) ? sh1[tid] : 0.f;
        float b = (tid < 8) ? sh2[tid] : 0.f;
        #pragma unroll
        for (int o = 4; o > 0; o >>= 1) {
            a += __shfl_xor_sync(0xffffffffu, a, o);
            b += __shfl_xor_sync(0xffffffffu, b, o);
        }
        if (tid == 0) { sh1[0] = a; sh2[0] = b; }
    }
    __syncthreads();
    float mean = sh1[0] / Cn;
    float var  = sh2[0] / Cn - mean*mean;
    float inv  = rsqrtf(var + 1e-5f);
    for (int i = tid; i < Cn; i += 256) {
        float v = (x[i] - mean) * inv * sc[i] + bi[i];
        if (Yf) Yf[(long long)blockIdx.x*Cn + i] = v;
        if (Yh) {
            h16 h, l; split_f16(v, h, l);
            Yh[(long long)blockIdx.x*Cn + i] = h;
            Yl[(long long)blockIdx.x*Cn + i] = l;
        }
    }
}

// ---------------- softmax (fp32 in, split fp16 out) ----------------
__global__ void softmax_kernel(const float* __restrict__ S,
                               h16* __restrict__ Ph, h16* __restrict__ Pl)
{
    const float* p = S + (long long)blockIdx.x * NP;
    h16* ph = Ph + (long long)blockIdx.x * NP;
    h16* pl = Pl + (long long)blockIdx.x * NP;
    __shared__ float sh[32];
    int tid = threadIdx.x;
    const int IT = (NP + 255) / 256;
    float vals[(NP + 255) / 256];
    float mx = -1e30f;
    #pragma unroll
    for (int it = 0; it < IT; it++) {
        int i = tid + it*256;
        float v = (i < NP) ? p[i] : -1e30f;
        vals[it] = v;
        mx = fmaxf(mx, v);
    }
    #pragma unroll
    for (int o = 16; o > 0; o >>= 1) mx = fmaxf(mx, __shfl_xor_sync(0xffffffffu, mx, o));
    if ((tid & 31) == 0) sh[tid>>5] = mx;
    __syncthreads();
    if (tid < 32) {
        float v = (tid < 8) ? sh[tid] : -1e30f;
        #pragma unroll
        for (int o = 4; o > 0; o >>= 1) v = fmaxf(v, __shfl_xor_sync(0xffffffffu, v, o));
        if (tid == 0) sh[0] = v;
    }
    __syncthreads();
    mx = sh[0];
    __syncthreads();
    float sum = 0.f;
    #pragma unroll
    for (int it = 0; it < IT; it++) {
        int i = tid + it*256;
        float e = (i < NP) ? expf(vals[it] - mx) : 0.f;
        vals[it] = e;
        sum += e;
    }
    #pragma unroll
    for (int o = 16; o > 0; o >>= 1) sum += __shfl_xor_sync(0xffffffffu, sum, o);
    if ((tid & 31) == 0) sh[tid>>5] = sum;
    __syncthreads();
    if (tid < 32) {
        float v = (tid < 8) ? sh[tid] : 0.f;
        #pragma unroll
        for (int o = 4; o > 0; o >>= 1) v += __shfl_xor_sync(0xffffffffu, v, o);
        if (tid == 0) sh[0] = v;
    }
    __syncthreads();
    float inv = 1.0f / sh[0];
    #pragma unroll
    for (int it = 0; it < IT; it++) {
        int i = tid + it*256;
        if (i < NP) {
            float v = vals[it] * inv;
            h16 h, l; split_f16(v, h, l);
            ph[i] = h; pl[i] = l;
        }
    }
}

// ---------------- im2col (writes split fp16) ----------------
__global__ void im2col_kernel(const float* __restrict__ x)
{
    long long idx = (long long)blockIdx.x * 256 + threadIdx.x;
    if (idx >= (long long)NTOK * KPATCH) return;
    int j = (int)(idx % KPATCH);
    int m = (int)(idx / KPATCH);
    int b = m / NP, n = m % NP;
    int t = n / 196, r = n % 196, yy = r / 14, xx = r % 14;
    int i  = j / 512, r2 = j % 512;
    int dt = r2 / 256, r3 = r2 % 256;
    int dy = r3 / 16,  dx = r3 % 16;
    long long off = ((((long long)(b*3 + i)*16 + (2*t + dt))*224) + (16*yy + dy))*224 + (16*xx + dx);
    float v = x[off];
    h16 h, l; split_f16(v, h, l);
    g_imh[idx] = h; g_iml[idx] = l;
}

// ---------------- positional encoding ----------------
__global__ void freq_kernel()
{
    int c2 = threadIdx.x;
    if (c2 < EMBED/2) g_freq[c2] = pow(10000.0, -2.0 * c2 / (double)EMBED);
}
__global__ void posadd_kernel()
{
    int idx = blockIdx.x * 256 + threadIdx.x;
    if (idx >= NP*EMBED) return;
    int n = idx / EMBED, c = idx % EMBED;
    double a = (double)n * g_freq[c >> 1];
    const double TWO_PI = 6.283185307179586476925286766559;
    int k = (int)(a * (1.0 / TWO_PI) + 0.5);
    float rf = (float)(a - (double)k * TWO_PI);
    float v = (c & 1) ? cosf(rf) : sinf(rf);
    g_h[idx]            += v;
    g_h[idx + NP*EMBED] += v;
}

// ---------------- mean pool ----------------
__global__ void pool_kernel()
{
    int idx = blockIdx.x * 256 + threadIdx.x;
    if (idx >= BATCH*EMBED) return;
    int b = idx / EMBED, c = idx % EMBED;
    const float* base = g_h + (long long)b*NP*EMBED + c;
    float s = 0.f;
    for (int n = 0; n < NP; n++) s += base[(long long)n*EMBED];
    g_pool[idx] = s * (1.0f / NP);
}

// ---------------- classifier head ----------------
__global__ void head_kernel(const float* __restrict__ W, const float* __restrict__ hb,
                            float* __restrict__ out)
{
    int g = blockIdx.x * 256 + threadIdx.x;
    int warp = g >> 5, lane = g & 31;
    if (warp >= BATCH*1000) return;
    int b = warp / 1000, j = warp % 1000;
    float s = 0.f;
    for (int c = lane; c < EMBED; c += 32)
        s += g_pln[b*EMBED + c] * W[j*EMBED + c];
    #pragma unroll
    for (int o = 16; o > 0; o >>= 1) s += __shfl_xor_sync(0xffffffffu, s, o);
    if (lane == 0) out[warp] = s + hb[j];
}

// ---------------- host orchestration ----------------
#define DS128 ((2*128 + 2*128)*SA*2*3)   // 122880 B
#define DS96  ((2*128 + 2*96 )*SA*2*3)   // 107520 B
#define DS64  ((2*128 + 2*64 )*SA*2*3)   //  92160 B

extern "C" void kernel_launch(void* const* d_in, const int* in_sizes, int n_in,
                              void* d_out, int out_size)
{
    const float* x      = (const float*)d_in[0];
    const float* conv_w = (const float*)d_in[1];
    const float* conv_b = (const float*)d_in[2];
    const float* n1s    = (const float*)d_in[3];
    const float* n1b    = (const float*)d_in[4];
    const float* qkv_w  = (const float*)d_in[5];
    const float* out_w  = (const float*)d_in[6];
    const float* out_b  = (const float*)d_in[7];
    const float* n2s    = (const float*)d_in[8];
    const float* n2b    = (const float*)d_in[9];
    const float* fc1_w  = (const float*)d_in[10];
    const float* fc1_b  = (const float*)d_in[11];
    const float* fc2_w  = (const float*)d_in[12];
    const float* fc2_b  = (const float*)d_in[13];
    const float* fns    = (const float*)d_in[14];
    const float* fnb    = (const float*)d_in[15];
    const float* head_w = (const float*)d_in[16];
    const float* head_b = (const float*)d_in[17];
    float* out = (float*)d_out;

    float *h, *attn, *pool, *pln;
    h16 *imh,*iml,*yh,*yl,*qkvh,*qkvl,*Ph,*Pl,*vth,*vtl,*aoh,*aol,*mlph,*mlpl;
    h16 *cwh,*cwl,*qwh,*qwl,*owh,*owl,*w1h,*w1l,*w2h,*w2l;
    cudaGetSymbolAddress((void**)&h,    g_h);
    cudaGetSymbolAddress((void**)&attn, g_attn);
    cudaGetSymbolAddress((void**)&pool, g_pool);
    cudaGetSymbolAddress((void**)&pln,  g_pln);
    cudaGetSymbolAddress((void**)&imh,  g_imh);   cudaGetSymbolAddress((void**)&iml, g_iml);
    cudaGetSymbolAddress((void**)&yh,   g_yh);    cudaGetSymbolAddress((void**)&yl,  g_yl);
    cudaGetSymbolAddress((void**)&qkvh, g_qkvh);  cudaGetSymbolAddress((void**)&qkvl,g_qkvl);
    cudaGetSymbolAddress((void**)&Ph,   g_Ph);    cudaGetSymbolAddress((void**)&Pl,  g_Pl);
    cudaGetSymbolAddress((void**)&vth,  g_vth);   cudaGetSymbolAddress((void**)&vtl, g_vtl);
    cudaGetSymbolAddress((void**)&aoh,  g_aoh);   cudaGetSymbolAddress((void**)&aol, g_aol);
    cudaGetSymbolAddress((void**)&mlph, g_mlph);  cudaGetSymbolAddress((void**)&mlpl,g_mlpl);
    cudaGetSymbolAddress((void**)&cwh,  g_cwh);   cudaGetSymbolAddress((void**)&cwl, g_cwl);
    cudaGetSymbolAddress((void**)&qwh,  g_qwh);   cudaGetSymbolAddress((void**)&qwl, g_qwl);
    cudaGetSymbolAddress((void**)&owh,  g_owh);   cudaGetSymbolAddress((void**)&owl, g_owl);
    cudaGetSymbolAddress((void**)&w1h,  g_w1h);   cudaGetSymbolAddress((void**)&w1l, g_w1l);
    cudaGetSymbolAddress((void**)&w2h,  g_w2h);   cudaGetSymbolAddress((void**)&w2l, g_w2l);

    cudaFuncSetAttribute(mma6_gemm<1,false,64 >, cudaFuncAttributeMaxDynamicSharedMemorySize, DS64);
    cudaFuncSetAttribute(mma6_gemm<0,true ,128>, cudaFuncAttributeMaxDynamicSharedMemorySize, DS128);
    cudaFuncSetAttribute(mma6_gemm<0,false,128>, cudaFuncAttributeMaxDynamicSharedMemorySize, DS128);
    cudaFuncSetAttribute(mma6_gemm<0,true ,96 >, cudaFuncAttributeMaxDynamicSharedMemorySize, DS96);
    cudaFuncSetAttribute(mma6_gemm<4,false,64 >, cudaFuncAttributeMaxDynamicSharedMemorySize, DS64);
    cudaFuncSetAttribute(mma6_gemm<2,true ,128>, cudaFuncAttributeMaxDynamicSharedMemorySize, DS128);

    const long long Z0 = 0;

    // ---- weight splits ----
    {
        long long n;
        n = (long long)EMBED*KPATCH;
        split_kernel<<<(int)((n/4+255)/256),256>>>(conv_w, cwh, cwl, n);
        n = (long long)DEPTH*3*EMBED*EMBED;
        split_kernel<<<(int)((n/4+255)/256),256>>>(qkv_w, qwh, qwl, n);
        n = (long long)DEPTH*EMBED*EMBED;
        split_kernel<<<(int)((n/4+255)/256),256>>>(out_w, owh, owl, n);
        n = (long long)DEPTH*MLPH*EMBED;
        split_kernel<<<(int)((n/4+255)/256),256>>>(fc1_w, w1h, w1l, n);
        n = (long long)DEPTH*EMBED*MLPH;
        split_kernel<<<(int)((n/4+255)/256),256>>>(fc2_w, w2h, w2l, n);
    }

    // ---- patch embed ----
    im2col_kernel<<<(int)(((long long)NTOK*KPATCH + 255)/256), 256>>>(x);
    {
        dim3 g(EMBED/64, (NTOK+127)/128, 1);
        mma6_gemm<1,false,64><<<g,256,DS64>>>(
            imh, iml, cwh, cwl, conv_b, nullptr, h, nullptr, nullptr,
            NTOK, EMBED, KPATCH, KPATCH, KPATCH, EMBED, 0,
            Z0,Z0,Z0,Z0,Z0,Z0,Z0,Z0, 1);
    }
    freq_kernel<<<1, EMBED/2>>>();
    posadd_kernel<<<(NP*EMBED + 255)/256, 256>>>();

    // ---- transformer blocks ----
    for (int l = 0; l < DEPTH; l++) {
        h16* lqwh = qwh + (long long)l*3*EMBED*EMBED;
        h16* lqwl = qwl + (long long)l*3*EMBED*EMBED;
        h16* lowh = owh + (long long)l*EMBED*EMBED;
        h16* lowl = owl + (long long)l*EMBED*EMBED;
        h16* lw1h = w1h + (long long)l*MLPH*EMBED;
        h16* lw1l = w1l + (long long)l*MLPH*EMBED;
        h16* lw2h = w2h + (long long)l*EMBED*MLPH;
        h16* lw2l = w2l + (long long)l*EMBED*MLPH;
        const float* ob = out_b + (long long)l*EMBED;
        const float* b1 = fc1_b + (long long)l*MLPH;
        const float* b2 = fc2_b + (long long)l*EMBED;

        ln_kernel<<<NTOK,256>>>(h, n1s + l*EMBED, n1b + l*EMBED, nullptr, yh, yl, EMBED);

        {   // qkv = y @ qw^T  -> split
            dim3 g((3*EMBED)/128, (NTOK+127)/128, 1);
            mma6_gemm<0,true,128><<<g,256,DS128>>>(
                yh, yl, lqwh, lqwl, nullptr, nullptr, nullptr, qkvh, qkvl,
                NTOK, 3*EMBED, EMBED, EMBED, EMBED, 3*EMBED, 0,
                Z0,Z0,Z0,Z0,Z0,Z0,Z0,Z0, 1);
        }

        {   // V^T per (b,h)
            dim3 g(NP/32, BATCH*HEADS, 1);
            vtrans_kernel<<<g,256>>>(qkvh, qkvl, vth, vtl);
        }

        {   // S = Q @ K^T  fp32
            dim3 g((NP+127)/128, (NP+127)/128, BATCH*HEADS);
            mma6_gemm<0,false,128><<<g,256,DS128>>>(
                qkvh, qkvl, qkvh + EMBED, qkvl + EMBED, nullptr, nullptr,
                attn, nullptr, nullptr,
                NP, NP, HDIM, 3*EMBED, 3*EMBED, NP, 0,
                (long long)NP*3*EMBED, (long long)HDIM,
                (long long)NP*3*EMBED, (long long)HDIM,
                (long long)HEADS*NP*NP, (long long)NP*NP,
                Z0, Z0, HEADS);
        }

        softmax_kernel<<<BATCH*HEADS*NP, 256>>>(attn, Ph, Pl);

        {   // ao = P @ VT^T  -> split  (N=96, BNT=96)
            dim3 g(1, (NP+127)/128, BATCH*HEADS);
            mma6_gemm<0,true,96><<<g,256,DS96>>>(
                Ph, Pl, vth, vtl, nullptr, nullptr, nullptr, aoh, aol,
                NP, HDIM, NP, NP, NP, EMBED, 0,
                (long long)HEADS*NP*NP, (long long)NP*NP,
                (long long)HEADS*HDIM*NP, (long long)HDIM*NP,
                (long long)NP*EMBED, (long long)HDIM,
                Z0, Z0, HEADS);
        }

        {   // h = h + ao @ ow^T + ob
            dim3 g(EMBED/64, (NTOK+127)/128, 1);
            mma6_gemm<4,false,64><<<g,256,DS64>>>(
                aoh, aol, lowh, lowl, ob, h, h, nullptr, nullptr,
                NTOK, EMBED, EMBED, EMBED, EMBED, EMBED, EMBED,
                Z0,Z0,Z0,Z0,Z0,Z0,Z0,Z0, 1);
        }

        ln_kernel<<<NTOK,256>>>(h, n2s + l*EMBED, n2b + l*EMBED, nullptr, yh, yl, EMBED);

        {   // mlp = gelu(y @ w1^T + b1) -> split
            dim3 g(MLPH/128, (NTOK+127)/128, 1);
            mma6_gemm<2,true,128><<<g,256,DS128>>>(
                yh, yl, lw1h, lw1l, b1, nullptr, nullptr, mlph, mlpl,
                NTOK, MLPH, EMBED, EMBED, EMBED, MLPH, 0,
                Z0,Z0,Z0,Z0,Z0,Z0,Z0,Z0, 1);
        }

        {   // h = h + mlp @ w2^T + b2
            dim3 g(EMBED/64, (NTOK+127)/128, 1);
            mma6_gemm<4,false,64><<<g,256,DS64>>>(
                mlph, mlpl, lw2h, lw2l, b2, h, h, nullptr, nullptr,
                NTOK, EMBED, MLPH, MLPH, MLPH, EMBED, EMBED,
                Z0,Z0,Z0,Z0,Z0,Z0,Z0,Z0, 1);
        }
    }

    // ---- pooled head ----
    pool_kernel<<<(BATCH*EMBED + 255)/256, 256>>>();
    ln_kernel<<<BATCH,256>>>(pool, fns, fnb, pln, nullptr, nullptr, EMBED);
    head_kernel<<<(BATCH*1000*32 + 255)/256, 256>>>(head_w, head_b, out);
}

// round 7
// speedup vs baseline: 1.5022x; 1.3946x over previous
#include <cuda_runtime.h>
#include <cuda_fp16.h>
#include <math.h>
#include <stdint.h>

#define EMBED   768
#define HEADS   8
#define HDIM    96
#define DEPTH   12
#define MLPH    3072
#define NP      1568
#define BATCH   2
#define NTOK    (BATCH*NP)      // 3136
#define KPATCH  1536

typedef __half h16;

// ---------------- scratch (device globals: allocation-free) ----------------
__device__ __align__(256) h16   g_imh [NTOK*KPATCH];
__device__ __align__(256) float g_h   [NTOK*EMBED];
__device__ __align__(256) h16   g_yh  [NTOK*EMBED];
__device__ __align__(256) h16   g_qkvh[NTOK*3*EMBED];
__device__ __align__(256) h16   g_qkvl[NTOK*3*EMBED];
__device__ __align__(256) float g_attn[39337984];     // 2*8*1568^2 fp32
__device__ __align__(256) h16   g_Ph  [39337984];
__device__ __align__(256) h16   g_vth [16*HDIM*NP];   // V^T per (b,h): [96][1568]
__device__ __align__(256) h16   g_vtl [16*HDIM*NP];
__device__ __align__(256) h16   g_aoh [NTOK*EMBED];
__device__ __align__(256) h16   g_mlph[NTOK*MLPH];
__device__ float g_pool[BATCH*EMBED];
__device__ float g_pln [BATCH*EMBED];
__device__ double g_freq[EMBED/2];
// weight splits (weights are always B-side: need hi+lo)
__device__ __align__(256) h16 g_cwh[EMBED*KPATCH];
__device__ __align__(256) h16 g_cwl[EMBED*KPATCH];
__device__ __align__(256) h16 g_qwh[DEPTH*3*EMBED*EMBED];
__device__ __align__(256) h16 g_qwl[DEPTH*3*EMBED*EMBED];
__device__ __align__(256) h16 g_owh[DEPTH*EMBED*EMBED];
__device__ __align__(256) h16 g_owl[DEPTH*EMBED*EMBED];
__device__ __align__(256) h16 g_w1h[DEPTH*MLPH*EMBED];
__device__ __align__(256) h16 g_w1l[DEPTH*MLPH*EMBED];
__device__ __align__(256) h16 g_w2h[DEPTH*EMBED*MLPH];
__device__ __align__(256) h16 g_w2l[DEPTH*EMBED*MLPH];

__device__ __forceinline__ void split_f16(float v, h16& h, h16& l)
{
    h = __float2half_rn(v);
    l = __float2half_rn(v - __half2float(h));
}

// ================= GEMM v7: fp16 split, 2-term (3-term for QK) =============
// C = A @ B^T (+EPI). A[M,K] k-contig (hi [,lo if TERMS=3]), B[N,K] hi/lo.
// All terms f32-accum into one accumulator:
//   TERMS=2: C = Ah*Bh + Ah*Bl          (drops Al*Bh, ~1.4e-4 statistical)
//   TERMS=3: C = Ah*Bh + Ah*Bl + Al*Bh
// Block: 128 x BNT, BK=32. 8 warps = 4m x 2n, warp tile 32 x (BNT/2).
// EPI: 0 none | 1 +bias | 2 +bias,gelu | 4 +bias,+residual
// OUT: 0 fp32 | 1 fp16 hi only | 2 fp16 hi+lo
#define BK 32
#define SA 40           // padded k-stride (elems); conflict-free LDSM

#define LDSM4(R, addr) \
    asm volatile("ldmatrix.sync.aligned.m8n8.x4.shared.b16 {%0,%1,%2,%3},[%4];" \
        : "=r"((R)[0]), "=r"((R)[1]), "=r"((R)[2]), "=r"((R)[3]) : "r"(addr))

#define MMA_F32(C, A, B0, B1) \
    asm volatile("mma.sync.aligned.m16n8k16.row.col.f32.f16.f16.f32 " \
        "{%0,%1,%2,%3},{%4,%5,%6,%7},{%8,%9},{%0,%1,%2,%3};" \
        : "+f"((C)[0]), "+f"((C)[1]), "+f"((C)[2]), "+f"((C)[3]) \
        : "r"((A)[0]), "r"((A)[1]), "r"((A)[2]), "r"((A)[3]), "r"(B0), "r"(B1))

__device__ __forceinline__ void cpa16(uint32_t dst, const void* src, bool p)
{
    int sz = p ? 16 : 0;
    asm volatile("cp.async.cg.shared.global [%0],[%1],16,%2;\n"
                 :: "r"(dst), "l"(src), "r"(sz));
}

template<int EPI, int OUT, int TERMS, int BNT>
__global__ void __launch_bounds__(256)
mma7_gemm(const h16* __restrict__ Agh, const h16* __restrict__ Agl,
          const h16* __restrict__ Bgh, const h16* __restrict__ Bgl,
          const float* __restrict__ bias, const float* __restrict__ R,
          float* __restrict__ Cf, h16* __restrict__ Ch, h16* __restrict__ Cl,
          int M, int N, int K, int lda, int ldb, int ldc, int ldr,
          long long zab, long long zah, long long zbb, long long zbh,
          long long zcb, long long zch, long long zrb, long long zrh, int H)
{
    constexpr int WN    = BNT / 2;
    constexpr int NPR   = WN / 16;
    constexpr int ANB   = (TERMS == 3) ? 2 : 1;
    constexpr int OFFAL = 128 * SA;
    constexpr int OFFB  = ANB * 128 * SA;
    constexpr int STAGE = (ANB * 128 + 2 * BNT) * SA;

    const int z  = blockIdx.z;
    const int bb = z / H, hh = z % H;
    Agh += bb*zab + hh*zah;
    if (TERMS == 3) Agl += bb*zab + hh*zah;
    Bgh += bb*zbb + hh*zbh;  Bgl += bb*zbb + hh*zbh;
    const long long coff = bb*zcb + hh*zch;
    if (OUT == 0) Cf += coff; else { Ch += coff; if (OUT == 2) Cl += coff; }
    if (EPI >= 3) R += bb*zrb + hh*zrh;

    extern __shared__ __align__(16) h16 smem[];
    const uint32_t su = (uint32_t)__cvta_generic_to_shared(smem);

    const int tid  = threadIdx.x;
    const int lane = tid & 31;
    const int w    = tid >> 5;
    const int wm   = w >> 1;              // 0..3
    const int wn   = w & 1;               // 0..1
    const int m0   = blockIdx.y * 128;
    const int n0   = blockIdx.x * BNT;

    float c[2][2*NPR][4];
    #pragma unroll
    for (int i = 0; i < 2; i++)
        #pragma unroll
        for (int j = 0; j < 2*NPR; j++)
            #pragma unroll
            for (int q = 0; q < 4; q++) c[i][j][q] = 0.f;

    const int lrow = lane & 15;
    const int lcol = (lane >> 4) * 8;
    const uint32_t aoffA = (uint32_t)(((wm*32 + lrow)*SA + lcol) * 2);
    const uint32_t boffB = (uint32_t)(((wn*WN + lrow)*SA + lcol) * 2);

    const int T = K / BK;

    auto issue = [&](int t, int s) {
        const int k0 = t * BK;
        const uint32_t sb = su + (uint32_t)(s * STAGE) * 2u;
        #pragma unroll
        for (int i = 0; i < 2*ANB; i++) {             // A: 512 chunks per buf
            const int hl  = i >> 1;
            const int ch  = ((i & 1) << 8) + tid;
            const int row = ch >> 2;
            const int kc  = (ch & 3) << 3;
            const bool p  = (m0 + row) < M;
            const h16* src = (hl ? Agl : Agh)
                           + (long long)(p ? (m0 + row) : 0) * lda + k0 + kc;
            cpa16(sb + (uint32_t)((hl ? OFFAL : 0) + row*SA + kc) * 2u, src, p);
        }
        constexpr int BCH = BNT / 32;
        #pragma unroll
        for (int i = 0; i < BCH; i++) {               // B hi/lo: 2*BNT*4 chunks
            const int ch  = i*256 + tid;
            const int hl  = ch / (BNT*4);
            const int rem = ch % (BNT*4);
            const int row = rem >> 2;
            const int kc  = (rem & 3) << 3;
            const bool p  = (n0 + row) < N;
            const h16* src = (hl ? Bgl : Bgh)
                           + (long long)(p ? (n0 + row) : 0) * ldb + k0 + kc;
            cpa16(sb + (uint32_t)(OFFB + hl*BNT*SA + row*SA + kc) * 2u, src, p);
        }
    };

    issue(0, 0);
    asm volatile("cp.async.commit_group;");
    if (T > 1) { issue(1, 1); asm volatile("cp.async.commit_group;"); }

    for (int t = 0; t < T; t++) {
        if (t + 1 < T) asm volatile("cp.async.wait_group 1;");
        else           asm volatile("cp.async.wait_group 0;");
        __syncthreads();

        if (t + 2 < T) {
            issue(t + 2, (t + 2) % 3);
            asm volatile("cp.async.commit_group;");
        }

        const int s = t % 3;
        const uint32_t sb  = su + (uint32_t)(s * STAGE) * 2u;
        const uint32_t aHb = sb + aoffA;
        const uint32_t aLb = aHb + (uint32_t)OFFAL * 2u;
        const uint32_t bHb = sb + (uint32_t)OFFB * 2u + boffB;
        const uint32_t bLb = bHb + (uint32_t)(BNT*SA) * 2u;

        #pragma unroll
        for (int kk2 = 0; kk2 < 2; kk2++) {
            const uint32_t kb = (uint32_t)(kk2 * 32);      // 16 elems * 2B
            uint32_t Ahf[2][4], Alf[2][4], Bhf[NPR][4], Blf[NPR][4];
            #pragma unroll
            for (int mi = 0; mi < 2; mi++) {
                LDSM4(Ahf[mi], aHb + (uint32_t)(mi*16*SA*2) + kb);
                if (TERMS == 3)
                    LDSM4(Alf[mi], aLb + (uint32_t)(mi*16*SA*2) + kb);
            }
            #pragma unroll
            for (int pr = 0; pr < NPR; pr++) {
                LDSM4(Bhf[pr], bHb + (uint32_t)(pr*16*SA*2) + kb);
                LDSM4(Blf[pr], bLb + (uint32_t)(pr*16*SA*2) + kb);
            }
            #pragma unroll
            for (int mi = 0; mi < 2; mi++) {
                #pragma unroll
                for (int pr = 0; pr < NPR; pr++) {
                    MMA_F32(c[mi][2*pr  ], Ahf[mi], Bhf[pr][0], Bhf[pr][2]);
                    MMA_F32(c[mi][2*pr  ], Ahf[mi], Blf[pr][0], Blf[pr][2]);
                    MMA_F32(c[mi][2*pr+1], Ahf[mi], Bhf[pr][1], Bhf[pr][3]);
                    MMA_F32(c[mi][2*pr+1], Ahf[mi], Blf[pr][1], Blf[pr][3]);
                    if (TERMS == 3) {
                        MMA_F32(c[mi][2*pr  ], Alf[mi], Bhf[pr][0], Bhf[pr][2]);
                        MMA_F32(c[mi][2*pr+1], Alf[mi], Bhf[pr][1], Bhf[pr][3]);
                    }
                }
            }
        }
    }

    // ---------------- epilogue (registers -> gmem, fused) ----------------
    const int g  = lane >> 2;
    const int tq = lane & 3;
    #pragma unroll
    for (int mi = 0; mi < 2; mi++) {
        #pragma unroll
        for (int nf = 0; nf < 2*NPR; nf++) {
            int col = n0 + wn*WN + nf*8 + tq*2;
            #pragma unroll
            for (int half = 0; half < 2; half++) {
                int row = m0 + wm*32 + mi*16 + g + half*8;
                if (row >= M || col >= N) continue;
                float v0 = c[mi][nf][half*2 + 0];
                float v1 = c[mi][nf][half*2 + 1];
                if (EPI == 1 || EPI == 2 || EPI == 4) { v0 += bias[col]; v1 += bias[col+1]; }
                if (EPI == 2) {
                    v0 = 0.5f * v0 * (1.0f + erff(v0 * 0.70710678118654752f));
                    v1 = 0.5f * v1 * (1.0f + erff(v1 * 0.70710678118654752f));
                }
                if (EPI >= 3) {
                    float2 r2 = *(const float2*)&R[(long long)row*ldr + col];
                    v0 += r2.x; v1 += r2.y;
                }
                if (OUT == 0) {
                    float2 o; o.x = v0; o.y = v1;
                    *(float2*)&Cf[(long long)row*ldc + col] = o;
                } else if (OUT == 1) {
                    *(__half2*)&Ch[(long long)row*ldc + col] =
                        __halves2half2(__float2half_rn(v0), __float2half_rn(v1));
                } else {
                    h16 h0,h1,l0,l1;
                    split_f16(v0,h0,l0); split_f16(v1,h1,l1);
                    *(__half2*)&Ch[(long long)row*ldc + col] = __halves2half2(h0,h1);
                    *(__half2*)&Cl[(long long)row*ldc + col] = __halves2half2(l0,l1);
                }
            }
        }
    }
}

// ---------------- V transpose: VT[z][n][k] = V[z][k][n] ----------------
__global__ void vtrans_kernel(const h16* __restrict__ qh, const h16* __restrict__ ql,
                              h16* __restrict__ vth, h16* __restrict__ vtl)
{
    __shared__ h16 th[32][100];
    __shared__ h16 tl[32][100];
    const int z = blockIdx.y, bb = z >> 3, hh = z & 7;
    const int k0 = blockIdx.x * 32;
    const int tid = threadIdx.x;
    const h16* sh = qh + ((long long)(bb*NP) + k0)*(3*EMBED) + 2*EMBED + hh*HDIM;
    const h16* sl = ql + ((long long)(bb*NP) + k0)*(3*EMBED) + 2*EMBED + hh*HDIM;
    for (int idx = tid; idx < 32*HDIM; idx += 256) {
        int kk = idx / HDIM, nn = idx % HDIM;
        th[kk][nn] = sh[(long long)kk*(3*EMBED) + nn];
        tl[kk][nn] = sl[(long long)kk*(3*EMBED) + nn];
    }
    __syncthreads();
    h16* dh = vth + (long long)z*HDIM*NP + k0;
    h16* dl = vtl + (long long)z*HDIM*NP + k0;
    for (int idx = tid; idx < 32*HDIM; idx += 256) {
        int nn = idx >> 5, kk = idx & 31;
        dh[(long long)nn*NP + kk] = th[kk][nn];
        dl[(long long)nn*NP + kk] = tl[kk][nn];
    }
}

// ---------------- fp32 -> fp16 hi/lo split (weights) ----------------
__global__ void split_kernel(const float* __restrict__ s, h16* __restrict__ h,
                             h16* __restrict__ l, long long n)
{
    long long i = ((long long)blockIdx.x*256 + threadIdx.x)*4;
    if (i >= n) return;
    float4 v = *(const float4*)&s[i];
    h16 h0,h1,h2,h3,l0,l1,l2,l3;
    split_f16(v.x,h0,l0); split_f16(v.y,h1,l1);
    split_f16(v.z,h2,l2); split_f16(v.w,h3,l3);
    *(__half2*)&h[i  ] = __halves2half2(h0,h1);
    *(__half2*)&h[i+2] = __halves2half2(h2,h3);
    *(__half2*)&l[i  ] = __halves2half2(l0,l1);
    *(__half2*)&l[i+2] = __halves2half2(l2,l3);
}

// ---------------- layernorm (fp32 out OR fp16-hi out) ----------------
__global__ void ln_kernel(const float* __restrict__ X, const float* __restrict__ sc,
                          const float* __restrict__ bi, float* __restrict__ Yf,
                          h16* __restrict__ Yh, int Cn)
{
    const float* x = X + (long long)blockIdx.x * Cn;
    __shared__ float sh1[32], sh2[32];
    int tid = threadIdx.x;
    float s = 0.f, s2 = 0.f;
    for (int i = tid; i < Cn; i += 256) { float v = x[i]; s += v; s2 += v*v; }
    #pragma unroll
    for (int o = 16; o > 0; o >>= 1) {
        s  += __shfl_xor_sync(0xffffffffu, s,  o);
        s2 += __shfl_xor_sync(0xffffffffu, s2, o);
    }
    if ((tid & 31) == 0) { sh1[tid>>5] = s; sh2[tid>>5] = s2; }
    __syncthreads();
    if (tid < 32) {
        float a = (tid < 8) ? sh1[tid] : 0.f;
        float b = (tid < 8) ? sh2[tid] : 0.f;
        #pragma unroll
        for (int o = 4; o > 0; o >>= 1) {
            a += __shfl_xor_sync(0xffffffffu, a, o);
            b += __shfl_xor_sync(0xffffffffu, b, o);
        }
        if (tid == 0) { sh1[0] = a; sh2[0] = b; }
    }
    __syncthreads();
    float mean = sh1[0] / Cn;
    float var  = sh2[0] / Cn - mean*mean;
    float inv  = rsqrtf(var + 1e-5f);
    for (int i = tid; i < Cn; i += 256) {
        float v = (x[i] - mean) * inv * sc[i] + bi[i];
        if (Yf) Yf[(long long)blockIdx.x*Cn + i] = v;
        else    Yh[(long long)blockIdx.x*Cn + i] = __float2half_rn(v);
    }
}

// ---------------- softmax (fp32 in, fp16-hi out) ----------------
__global__ void softmax_kernel(const float* __restrict__ S, h16* __restrict__ Ph)
{
    const float* p = S + (long long)blockIdx.x * NP;
    h16* ph = Ph + (long long)blockIdx.x * NP;
    __shared__ float sh[32];
    int tid = threadIdx.x;
    const int IT = (NP + 255) / 256;
    float vals[(NP + 255) / 256];
    float mx = -1e30f;
    #pragma unroll
    for (int it = 0; it < IT; it++) {
        int i = tid + it*256;
        float v = (i < NP) ? p[i] : -1e30f;
        vals[it] = v;
        mx = fmaxf(mx, v);
    }
    #pragma unroll
    for (int o = 16; o > 0; o >>= 1) mx = fmaxf(mx, __shfl_xor_sync(0xffffffffu, mx, o));
    if ((tid & 31) == 0) sh[tid>>5] = mx;
    __syncthreads();
    if (tid < 32) {
        float v = (tid < 8) ? sh[tid] : -1e30f;
        #pragma unroll
        for (int o = 4; o > 0; o >>= 1) v = fmaxf(v, __shfl_xor_sync(0xffffffffu, v, o));
        if (tid == 0) sh[0] = v;
    }
    __syncthreads();
    mx = sh[0];
    __syncthreads();
    float sum = 0.f;
    #pragma unroll
    for (int it = 0; it < IT; it++) {
        int i = tid + it*256;
        float e = (i < NP) ? expf(vals[it] - mx) : 0.f;
        vals[it] = e;
        sum += e;
    }
    #pragma unroll
    for (int o = 16; o > 0; o >>= 1) sum += __shfl_xor_sync(0xffffffffu, sum, o);
    if ((tid & 31) == 0) sh[tid>>5] = sum;
    __syncthreads();
    if (tid < 32) {
        float v = (tid < 8) ? sh[tid] : 0.f;
        #pragma unroll
        for (int o = 4; o > 0; o >>= 1) v += __shfl_xor_sync(0xffffffffu, v, o);
        if (tid == 0) sh[0] = v;
    }
    __syncthreads();
    float inv = 1.0f / sh[0];
    #pragma unroll
    for (int it = 0; it < IT; it++) {
        int i = tid + it*256;
        if (i < NP) ph[i] = __float2half_rn(vals[it] * inv);
    }
}

// ---------------- im2col (writes fp16 hi only) ----------------
__global__ void im2col_kernel(const float* __restrict__ x)
{
    long long idx = (long long)blockIdx.x * 256 + threadIdx.x;
    if (idx >= (long long)NTOK * KPATCH) return;
    int j = (int)(idx % KPATCH);
    int m = (int)(idx / KPATCH);
    int b = m / NP, n = m % NP;
    int t = n / 196, r = n % 196, yy = r / 14, xx = r % 14;
    int i  = j / 512, r2 = j % 512;
    int dt = r2 / 256, r3 = r2 % 256;
    int dy = r3 / 16,  dx = r3 % 16;
    long long off = ((((long long)(b*3 + i)*16 + (2*t + dt))*224) + (16*yy + dy))*224 + (16*xx + dx);
    g_imh[idx] = __float2half_rn(x[off]);
}

// ---------------- positional encoding ----------------
__global__ void freq_kernel()
{
    int c2 = threadIdx.x;
    if (c2 < EMBED/2) g_freq[c2] = pow(10000.0, -2.0 * c2 / (double)EMBED);
}
__global__ void posadd_kernel()
{
    int idx = blockIdx.x * 256 + threadIdx.x;
    if (idx >= NP*EMBED) return;
    int n = idx / EMBED, c = idx % EMBED;
    double a = (double)n * g_freq[c >> 1];
    const double TWO_PI = 6.283185307179586476925286766559;
    int k = (int)(a * (1.0 / TWO_PI) + 0.5);
    float rf = (float)(a - (double)k * TWO_PI);
    float v = (c & 1) ? cosf(rf) : sinf(rf);
    g_h[idx]            += v;
    g_h[idx + NP*EMBED] += v;
}

// ---------------- mean pool ----------------
__global__ void pool_kernel()
{
    int idx = blockIdx.x * 256 + threadIdx.x;
    if (idx >= BATCH*EMBED) return;
    int b = idx / EMBED, c = idx % EMBED;
    const float* base = g_h + (long long)b*NP*EMBED + c;
    float s = 0.f;
    for (int n = 0; n < NP; n++) s += base[(long long)n*EMBED];
    g_pool[idx] = s * (1.0f / NP);
}

// ---------------- classifier head ----------------
__global__ void head_kernel(const float* __restrict__ W, const float* __restrict__ hb,
                            float* __restrict__ out)
{
    int g = blockIdx.x * 256 + threadIdx.x;
    int warp = g >> 5, lane = g & 31;
    if (warp >= BATCH*1000) return;
    int b = warp / 1000, j = warp % 1000;
    float s = 0.f;
    for (int c = lane; c < EMBED; c += 32)
        s += g_pln[b*EMBED + c] * W[j*EMBED + c];
    #pragma unroll
    for (int o = 16; o > 0; o >>= 1) s += __shfl_xor_sync(0xffffffffu, s, o);
    if (lane == 0) out[warp] = s + hb[j];
}

// ---------------- host orchestration ----------------
#define DSZ(anb,bnt) (((anb)*128 + 2*(bnt))*SA*2*3)

extern "C" void kernel_launch(void* const* d_in, const int* in_sizes, int n_in,
                              void* d_out, int out_size)
{
    const float* x      = (const float*)d_in[0];
    const float* conv_w = (const float*)d_in[1];
    const float* conv_b = (const float*)d_in[2];
    const float* n1s    = (const float*)d_in[3];
    const float* n1b    = (const float*)d_in[4];
    const float* qkv_w  = (const float*)d_in[5];
    const float* out_w  = (const float*)d_in[6];
    const float* out_b  = (const float*)d_in[7];
    const float* n2s    = (const float*)d_in[8];
    const float* n2b    = (const float*)d_in[9];
    const float* fc1_w  = (const float*)d_in[10];
    const float* fc1_b  = (const float*)d_in[11];
    const float* fc2_w  = (const float*)d_in[12];
    const float* fc2_b  = (const float*)d_in[13];
    const float* fns    = (const float*)d_in[14];
    const float* fnb    = (const float*)d_in[15];
    const float* head_w = (const float*)d_in[16];
    const float* head_b = (const float*)d_in[17];
    float* out = (float*)d_out;

    float *h, *attn, *pool, *pln;
    h16 *imh,*yh,*qkvh,*qkvl,*Ph,*vth,*vtl,*aoh,*mlph;
    h16 *cwh,*cwl,*qwh,*qwl,*owh,*owl,*w1h,*w1l,*w2h,*w2l;
    cudaGetSymbolAddress((void**)&h,    g_h);
    cudaGetSymbolAddress((void**)&attn, g_attn);
    cudaGetSymbolAddress((void**)&pool, g_pool);
    cudaGetSymbolAddress((void**)&pln,  g_pln);
    cudaGetSymbolAddress((void**)&imh,  g_imh);
    cudaGetSymbolAddress((void**)&yh,   g_yh);
    cudaGetSymbolAddress((void**)&qkvh, g_qkvh);  cudaGetSymbolAddress((void**)&qkvl,g_qkvl);
    cudaGetSymbolAddress((void**)&Ph,   g_Ph);
    cudaGetSymbolAddress((void**)&vth,  g_vth);   cudaGetSymbolAddress((void**)&vtl, g_vtl);
    cudaGetSymbolAddress((void**)&aoh,  g_aoh);
    cudaGetSymbolAddress((void**)&mlph, g_mlph);
    cudaGetSymbolAddress((void**)&cwh,  g_cwh);   cudaGetSymbolAddress((void**)&cwl, g_cwl);
    cudaGetSymbolAddress((void**)&qwh,  g_qwh);   cudaGetSymbolAddress((void**)&qwl, g_qwl);
    cudaGetSymbolAddress((void**)&owh,  g_owh);   cudaGetSymbolAddress((void**)&owl, g_owl);
    cudaGetSymbolAddress((void**)&w1h,  g_w1h);   cudaGetSymbolAddress((void**)&w1l, g_w1l);
    cudaGetSymbolAddress((void**)&w2h,  g_w2h);   cudaGetSymbolAddress((void**)&w2l, g_w2l);

    cudaFuncSetAttribute(mma7_gemm<1,0,2,64 >, cudaFuncAttributeMaxDynamicSharedMemorySize, DSZ(1,64));
    cudaFuncSetAttribute(mma7_gemm<0,2,2,128>, cudaFuncAttributeMaxDynamicSharedMemorySize, DSZ(1,128));
    cudaFuncSetAttribute(mma7_gemm<0,0,3,128>, cudaFuncAttributeMaxDynamicSharedMemorySize, DSZ(2,128));
    cudaFuncSetAttribute(mma7_gemm<0,1,2,96 >, cudaFuncAttributeMaxDynamicSharedMemorySize, DSZ(1,96));
    cudaFuncSetAttribute(mma7_gemm<4,0,2,64 >, cudaFuncAttributeMaxDynamicSharedMemorySize, DSZ(1,64));
    cudaFuncSetAttribute(mma7_gemm<2,1,2,128>, cudaFuncAttributeMaxDynamicSharedMemorySize, DSZ(1,128));

    const long long Z0 = 0;

    // ---- weight splits ----
    {
        long long n;
        n = (long long)EMBED*KPATCH;
        split_kernel<<<(int)((n/4+255)/256),256>>>(conv_w, cwh, cwl, n);
        n = (long long)DEPTH*3*EMBED*EMBED;
        split_kernel<<<(int)((n/4+255)/256),256>>>(qkv_w, qwh, qwl, n);
        n = (long long)DEPTH*EMBED*EMBED;
        split_kernel<<<(int)((n/4+255)/256),256>>>(out_w, owh, owl, n);
        n = (long long)DEPTH*MLPH*EMBED;
        split_kernel<<<(int)((n/4+255)/256),256>>>(fc1_w, w1h, w1l, n);
        n = (long long)DEPTH*EMBED*MLPH;
        split_kernel<<<(int)((n/4+255)/256),256>>>(fc2_w, w2h, w2l, n);
    }

    // ---- patch embed ----
    im2col_kernel<<<(int)(((long long)NTOK*KPATCH + 255)/256), 256>>>(x);
    {
        dim3 g(EMBED/64, (NTOK+127)/128, 1);
        mma7_gemm<1,0,2,64><<<g,256,DSZ(1,64)>>>(
            imh, nullptr, cwh, cwl, conv_b, nullptr, h, nullptr, nullptr,
            NTOK, EMBED, KPATCH, KPATCH, KPATCH, EMBED, 0,
            Z0,Z0,Z0,Z0,Z0,Z0,Z0,Z0, 1);
    }
    freq_kernel<<<1, EMBED/2>>>();
    posadd_kernel<<<(NP*EMBED + 255)/256, 256>>>();

    // ---- transformer blocks ----
    for (int l = 0; l < DEPTH; l++) {
        h16* lqwh = qwh + (long long)l*3*EMBED*EMBED;
        h16* lqwl = qwl + (long long)l*3*EMBED*EMBED;
        h16* lowh = owh + (long long)l*EMBED*EMBED;
        h16* lowl = owl + (long long)l*EMBED*EMBED;
        h16* lw1h = w1h + (long long)l*MLPH*EMBED;
        h16* lw1l = w1l + (long long)l*MLPH*EMBED;
        h16* lw2h = w2h + (long long)l*EMBED*MLPH;
        h16* lw2l = w2l + (long long)l*EMBED*MLPH;
        const float* ob = out_b + (long long)l*EMBED;
        const float* b1 = fc1_b + (long long)l*MLPH;
        const float* b2 = fc2_b + (long long)l*EMBED;

        // y = LN1(h) -> fp16 hi
        ln_kernel<<<NTOK,256>>>(h, n1s + l*EMBED, n1b + l*EMBED, nullptr, yh, EMBED);

        {   // qkv = y @ qw^T  -> fp16 hi+lo (K,V need lo as B; Q needs lo for 3-term QK)
            dim3 g((3*EMBED)/128, (NTOK+127)/128, 1);
            mma7_gemm<0,2,2,128><<<g,256,DSZ(1,128)>>>(
                yh, nullptr, lqwh, lqwl, nullptr, nullptr, nullptr, qkvh, qkvl,
                NTOK, 3*EMBED, EMBED, EMBED, EMBED, 3*EMBED, 0,
                Z0,Z0,Z0,Z0,Z0,Z0,Z0,Z0, 1);
        }

        {   // V^T per (b,h)
            dim3 g(NP/32, BATCH*HEADS, 1);
            vtrans_kernel<<<g,256>>>(qkvh, qkvl, vth, vtl);
        }

        {   // S = Q @ K^T  fp32 (3-term: softmax is error-sensitive, logits unscaled)
            dim3 g((NP+127)/128, (NP+127)/128, BATCH*HEADS);
            mma7_gemm<0,0,3,128><<<g,256,DSZ(2,128)>>>(
                qkvh, qkvl, qkvh + EMBED, qkvl + EMBED, nullptr, nullptr,
                attn, nullptr, nullptr,
                NP, NP, HDIM, 3*EMBED, 3*EMBED, NP, 0,
                (long long)NP*3*EMBED, (long long)HDIM,
                (long long)NP*3*EMBED, (long long)HDIM,
                (long long)HEADS*NP*NP, (long long)NP*NP,
                Z0, Z0, HEADS);
        }

        softmax_kernel<<<BATCH*HEADS*NP, 256>>>(attn, Ph);

        {   // ao = P @ VT^T  -> fp16 hi (N=96)
            dim3 g(1, (NP+127)/128, BATCH*HEADS);
            mma7_gemm<0,1,2,96><<<g,256,DSZ(1,96)>>>(
                Ph, nullptr, vth, vtl, nullptr, nullptr, nullptr, aoh, nullptr,
                NP, HDIM, NP, NP, NP, EMBED, 0,
                (long long)HEADS*NP*NP, (long long)NP*NP,
                (long long)HEADS*HDIM*NP, (long long)HDIM*NP,
                (long long)NP*EMBED, (long long)HDIM,
                Z0, Z0, HEADS);
        }

        {   // h = h + ao @ ow^T + ob
            dim3 g(EMBED/64, (NTOK+127)/128, 1);
            mma7_gemm<4,0,2,64><<<g,256,DSZ(1,64)>>>(
                aoh, nullptr, lowh, lowl, ob, h, h, nullptr, nullptr,
                NTOK, EMBED, EMBED, EMBED, EMBED, EMBED, EMBED,
                Z0,Z0,Z0,Z0,Z0,Z0,Z0,Z0, 1);
        }

        // y = LN2(h) -> fp16 hi
        ln_kernel<<<NTOK,256>>>(h, n2s + l*EMBED, n2b + l*EMBED, nullptr, yh, EMBED);

        {   // mlp = gelu(y @ w1^T + b1) -> fp16 hi
            dim3 g(MLPH/128, (NTOK+127)/128, 1);
            mma7_gemm<2,1,2,128><<<g,256,DSZ(1,128)>>>(
                yh, nullptr, lw1h, lw1l, b1, nullptr, nullptr, mlph, nullptr,
                NTOK, MLPH, EMBED, EMBED, EMBED, MLPH, 0,
                Z0,Z0,Z0,Z0,Z0,Z0,Z0,Z0, 1);
        }

        {   // h = h + mlp @ w2^T + b2
            dim3 g(EMBED/64, (NTOK+127)/128, 1);
            mma7_gemm<4,0,2,64><<<g,256,DSZ(1,64)>>>(
                mlph, nullptr, lw2h, lw2l, b2, h, h, nullptr, nullptr,
                NTOK, EMBED, MLPH, MLPH, MLPH, EMBED, EMBED,
                Z0,Z0,Z0,Z0,Z0,Z0,Z0,Z0, 1);
        }
    }

    // ---- pooled head ----
    pool_kernel<<<(BATCH*EMBED + 255)/256, 256>>>();
    ln_kernel<<<BATCH,256>>>(pool, fns, fnb, pln, nullptr, EMBED);
    head_kernel<<<(BATCH*1000*32 + 255)/256, 256>>>(head_w, head_b, out);
}

// round 8
// speedup vs baseline: 1.8620x; 1.2395x over previous
#include <cuda_runtime.h>
#include <cuda_fp16.h>
#include <math.h>
#include <stdint.h>

#define EMBED   768
#define HEADS   8
#define HDIM    96
#define DEPTH   12
#define MLPH    3072
#define NP      1568
#define BATCH   2
#define NTOK    (BATCH*NP)      // 3136
#define KPATCH  1536

typedef __half h16;

// ---------------- scratch (device globals: allocation-free) ----------------
__device__ __align__(256) h16   g_imh [NTOK*KPATCH];
__device__ __align__(256) float g_h   [NTOK*EMBED];
__device__ __align__(256) h16   g_yh  [NTOK*EMBED];
__device__ __align__(256) h16   g_qkvh[NTOK*3*EMBED];
__device__ __align__(256) h16   g_qkvl[NTOK*3*EMBED];
__device__ __align__(256) float g_attn[39337984];     // 2*8*1568^2 fp32
__device__ __align__(256) h16   g_Ph  [39337984];
__device__ __align__(256) h16   g_vth [16*HDIM*NP];   // V^T per (b,h): [96][1568]
__device__ __align__(256) h16   g_vtl [16*HDIM*NP];
__device__ __align__(256) h16   g_aoh [NTOK*EMBED];
__device__ __align__(256) h16   g_mlph[NTOK*MLPH];
__device__ float g_pool[BATCH*EMBED];
__device__ float g_pln [BATCH*EMBED];
__device__ double g_freq[EMBED/2];
// weights: conv needs hi+lo (2-term); qkv/out/fc1/fc2 hi only (1-term)
__device__ __align__(256) h16 g_cwh[EMBED*KPATCH];
__device__ __align__(256) h16 g_cwl[EMBED*KPATCH];
__device__ __align__(256) h16 g_qwh[DEPTH*3*EMBED*EMBED];
__device__ __align__(256) h16 g_owh[DEPTH*EMBED*EMBED];
__device__ __align__(256) h16 g_w1h[DEPTH*MLPH*EMBED];
__device__ __align__(256) h16 g_w2h[DEPTH*EMBED*MLPH];

__device__ __forceinline__ void split_f16(float v, h16& h, h16& l)
{
    h = __float2half_rn(v);
    l = __float2half_rn(v - __half2float(h));
}

// ================= GEMM v8: fp16 split, TERMS in {1,2,3} ===================
// C = A @ B^T (+EPI). A[M,K] k-contig (hi [,lo if TERMS=3]).
// B[N,K] k-contig (hi [,lo if TERMS>=2]). All terms f32-accum:
//   TERMS=1: Ah*Bh
//   TERMS=2: Ah*Bh + Ah*Bl
//   TERMS=3: Ah*Bh + Ah*Bl + Al*Bh
// Block: 128 x BNT, BK=32. 8 warps = 4m x 2n, warp tile 32 x (BNT/2).
// EPI: 0 none | 1 +bias | 2 +bias,gelu | 4 +bias,+residual
// OUT: 0 fp32 | 1 fp16 hi only | 2 fp16 hi+lo
#define BK 32
#define SA 40           // padded k-stride (elems); conflict-free LDSM

#define LDSM4(R, addr) \
    asm volatile("ldmatrix.sync.aligned.m8n8.x4.shared.b16 {%0,%1,%2,%3},[%4];" \
        : "=r"((R)[0]), "=r"((R)[1]), "=r"((R)[2]), "=r"((R)[3]) : "r"(addr))

#define MMA_F32(C, A, B0, B1) \
    asm volatile("mma.sync.aligned.m16n8k16.row.col.f32.f16.f16.f32 " \
        "{%0,%1,%2,%3},{%4,%5,%6,%7},{%8,%9},{%0,%1,%2,%3};" \
        : "+f"((C)[0]), "+f"((C)[1]), "+f"((C)[2]), "+f"((C)[3]) \
        : "r"((A)[0]), "r"((A)[1]), "r"((A)[2]), "r"((A)[3]), "r"(B0), "r"(B1))

__device__ __forceinline__ void cpa16(uint32_t dst, const void* src, bool p)
{
    int sz = p ? 16 : 0;
    asm volatile("cp.async.cg.shared.global [%0],[%1],16,%2;\n"
                 :: "r"(dst), "l"(src), "r"(sz));
}

template<int EPI, int OUT, int TERMS, int BNT>
__global__ void __launch_bounds__(256)
mma8_gemm(const h16* __restrict__ Agh, const h16* __restrict__ Agl,
          const h16* __restrict__ Bgh, const h16* __restrict__ Bgl,
          const float* __restrict__ bias, const float* __restrict__ R,
          float* __restrict__ Cf, h16* __restrict__ Ch, h16* __restrict__ Cl,
          int M, int N, int K, int lda, int ldb, int ldc, int ldr,
          long long zab, long long zah, long long zbb, long long zbh,
          long long zcb, long long zch, long long zrb, long long zrh, int H)
{
    constexpr int WN    = BNT / 2;
    constexpr int NPR   = WN / 16;
    constexpr int ANB   = (TERMS == 3) ? 2 : 1;
    constexpr int BNB   = (TERMS >= 2) ? 2 : 1;
    constexpr int OFFAL = 128 * SA;
    constexpr int OFFB  = ANB * 128 * SA;
    constexpr int STAGE = (ANB * 128 + BNB * BNT) * SA;

    const int z  = blockIdx.z;
    const int bb = z / H, hh = z % H;
    Agh += bb*zab + hh*zah;
    if (TERMS == 3) Agl += bb*zab + hh*zah;
    Bgh += bb*zbb + hh*zbh;
    if (TERMS >= 2) Bgl += bb*zbb + hh*zbh;
    const long long coff = bb*zcb + hh*zch;
    if (OUT == 0) Cf += coff; else { Ch += coff; if (OUT == 2) Cl += coff; }
    if (EPI >= 3) R += bb*zrb + hh*zrh;

    extern __shared__ __align__(16) h16 smem[];
    const uint32_t su = (uint32_t)__cvta_generic_to_shared(smem);

    const int tid  = threadIdx.x;
    const int lane = tid & 31;
    const int w    = tid >> 5;
    const int wm   = w >> 1;              // 0..3
    const int wn   = w & 1;               // 0..1
    const int m0   = blockIdx.y * 128;
    const int n0   = blockIdx.x * BNT;

    float c[2][2*NPR][4];
    #pragma unroll
    for (int i = 0; i < 2; i++)
        #pragma unroll
        for (int j = 0; j < 2*NPR; j++)
            #pragma unroll
            for (int q = 0; q < 4; q++) c[i][j][q] = 0.f;

    const int lrow = lane & 15;
    const int lcol = (lane >> 4) * 8;
    const uint32_t aoffA = (uint32_t)(((wm*32 + lrow)*SA + lcol) * 2);
    const uint32_t boffB = (uint32_t)(((wn*WN + lrow)*SA + lcol) * 2);

    const int T = K / BK;

    auto issue = [&](int t, int s) {
        const int k0 = t * BK;
        const uint32_t sb = su + (uint32_t)(s * STAGE) * 2u;
        #pragma unroll
        for (int i = 0; i < 2*ANB; i++) {             // A: 512 chunks per buf
            const int hl  = i >> 1;
            const int ch  = ((i & 1) << 8) + tid;
            const int row = ch >> 2;
            const int kc  = (ch & 3) << 3;
            const bool p  = (m0 + row) < M;
            const h16* src = (hl ? Agl : Agh)
                           + (long long)(p ? (m0 + row) : 0) * lda + k0 + kc;
            cpa16(sb + (uint32_t)((hl ? OFFAL : 0) + row*SA + kc) * 2u, src, p);
        }
        constexpr int BCH = (BNB * BNT) / 64;         // 256-chunk iterations
        #pragma unroll
        for (int i = 0; i < BCH; i++) {
            const int ch  = i*256 + tid;
            const int hl  = ch / (BNT*4);
            const int rem = ch % (BNT*4);
            const int row = rem >> 2;
            const int kc  = (rem & 3) << 3;
            const bool p  = (n0 + row) < N;
            const h16* src = (hl ? Bgl : Bgh)
                           + (long long)(p ? (n0 + row) : 0) * ldb + k0 + kc;
            cpa16(sb + (uint32_t)(OFFB + hl*BNT*SA + row*SA + kc) * 2u, src, p);
        }
    };

    issue(0, 0);
    asm volatile("cp.async.commit_group;");
    if (T > 1) { issue(1, 1); asm volatile("cp.async.commit_group;"); }

    for (int t = 0; t < T; t++) {
        if (t + 1 < T) asm volatile("cp.async.wait_group 1;");
        else           asm volatile("cp.async.wait_group 0;");
        __syncthreads();

        if (t + 2 < T) {
            issue(t + 2, (t + 2) % 3);
            asm volatile("cp.async.commit_group;");
        }

        const int s = t % 3;
        const uint32_t sb  = su + (uint32_t)(s * STAGE) * 2u;
        const uint32_t aHb = sb + aoffA;
        const uint32_t aLb = aHb + (uint32_t)OFFAL * 2u;
        const uint32_t bHb = sb + (uint32_t)OFFB * 2u + boffB;
        const uint32_t bLb = bHb + (uint32_t)(BNT*SA) * 2u;

        #pragma unroll
        for (int kk2 = 0; kk2 < 2; kk2++) {
            const uint32_t kb = (uint32_t)(kk2 * 32);      // 16 elems * 2B
            uint32_t Ahf[2][4], Alf[2][4], Bhf[NPR][4], Blf[NPR][4];
            #pragma unroll
            for (int mi = 0; mi < 2; mi++) {
                LDSM4(Ahf[mi], aHb + (uint32_t)(mi*16*SA*2) + kb);
                if (TERMS == 3)
                    LDSM4(Alf[mi], aLb + (uint32_t)(mi*16*SA*2) + kb);
            }
            #pragma unroll
            for (int pr = 0; pr < NPR; pr++) {
                LDSM4(Bhf[pr], bHb + (uint32_t)(pr*16*SA*2) + kb);
                if (TERMS >= 2)
                    LDSM4(Blf[pr], bLb + (uint32_t)(pr*16*SA*2) + kb);
            }
            #pragma unroll
            for (int mi = 0; mi < 2; mi++) {
                #pragma unroll
                for (int pr = 0; pr < NPR; pr++) {
                    MMA_F32(c[mi][2*pr  ], Ahf[mi], Bhf[pr][0], Bhf[pr][2]);
                    MMA_F32(c[mi][2*pr+1], Ahf[mi], Bhf[pr][1], Bhf[pr][3]);
                    if (TERMS >= 2) {
                        MMA_F32(c[mi][2*pr  ], Ahf[mi], Blf[pr][0], Blf[pr][2]);
                        MMA_F32(c[mi][2*pr+1], Ahf[mi], Blf[pr][1], Blf[pr][3]);
                    }
                    if (TERMS == 3) {
                        MMA_F32(c[mi][2*pr  ], Alf[mi], Bhf[pr][0], Bhf[pr][2]);
                        MMA_F32(c[mi][2*pr+1], Alf[mi], Bhf[pr][1], Bhf[pr][3]);
                    }
                }
            }
        }
    }

    // ---------------- epilogue (registers -> gmem, fused) ----------------
    const int g  = lane >> 2;
    const int tq = lane & 3;
    #pragma unroll
    for (int mi = 0; mi < 2; mi++) {
        #pragma unroll
        for (int nf = 0; nf < 2*NPR; nf++) {
            int col = n0 + wn*WN + nf*8 + tq*2;
            #pragma unroll
            for (int half = 0; half < 2; half++) {
                int row = m0 + wm*32 + mi*16 + g + half*8;
                if (row >= M || col >= N) continue;
                float v0 = c[mi][nf][half*2 + 0];
                float v1 = c[mi][nf][half*2 + 1];
                if (EPI == 1 || EPI == 2 || EPI == 4) { v0 += bias[col]; v1 += bias[col+1]; }
                if (EPI == 2) {
                    v0 = 0.5f * v0 * (1.0f + erff(v0 * 0.70710678118654752f));
                    v1 = 0.5f * v1 * (1.0f + erff(v1 * 0.70710678118654752f));
                }
                if (EPI >= 3) {
                    float2 r2 = *(const float2*)&R[(long long)row*ldr + col];
                    v0 += r2.x; v1 += r2.y;
                }
                if (OUT == 0) {
                    float2 o; o.x = v0; o.y = v1;
                    *(float2*)&Cf[(long long)row*ldc + col] = o;
                } else if (OUT == 1) {
                    *(__half2*)&Ch[(long long)row*ldc + col] =
                        __halves2half2(__float2half_rn(v0), __float2half_rn(v1));
                } else {
                    h16 h0,h1,l0,l1;
                    split_f16(v0,h0,l0); split_f16(v1,h1,l1);
                    *(__half2*)&Ch[(long long)row*ldc + col] = __halves2half2(h0,h1);
                    *(__half2*)&Cl[(long long)row*ldc + col] = __halves2half2(l0,l1);
                }
            }
        }
    }
}

// ---------------- V transpose: VT[z][n][k] = V[z][k][n] ----------------
__global__ void vtrans_kernel(const h16* __restrict__ qh, const h16* __restrict__ ql,
                              h16* __restrict__ vth, h16* __restrict__ vtl)
{
    __shared__ h16 th[32][100];
    __shared__ h16 tl[32][100];
    const int z = blockIdx.y, bb = z >> 3, hh = z & 7;
    const int k0 = blockIdx.x * 32;
    const int tid = threadIdx.x;
    const h16* sh = qh + ((long long)(bb*NP) + k0)*(3*EMBED) + 2*EMBED + hh*HDIM;
    const h16* sl = ql + ((long long)(bb*NP) + k0)*(3*EMBED) + 2*EMBED + hh*HDIM;
    for (int idx = tid; idx < 32*HDIM; idx += 256) {
        int kk = idx / HDIM, nn = idx % HDIM;
        th[kk][nn] = sh[(long long)kk*(3*EMBED) + nn];
        tl[kk][nn] = sl[(long long)kk*(3*EMBED) + nn];
    }
    __syncthreads();
    h16* dh = vth + (long long)z*HDIM*NP + k0;
    h16* dl = vtl + (long long)z*HDIM*NP + k0;
    for (int idx = tid; idx < 32*HDIM; idx += 256) {
        int nn = idx >> 5, kk = idx & 31;
        dh[(long long)nn*NP + kk] = th[kk][nn];
        dl[(long long)nn*NP + kk] = tl[kk][nn];
    }
}

// ---------------- fp32 -> fp16 hi/lo split (conv weight) ----------------
__global__ void split_kernel(const float* __restrict__ s, h16* __restrict__ h,
                             h16* __restrict__ l, long long n)
{
    long long i = ((long long)blockIdx.x*256 + threadIdx.x)*4;
    if (i >= n) return;
    float4 v = *(const float4*)&s[i];
    h16 h0,h1,h2,h3,l0,l1,l2,l3;
    split_f16(v.x,h0,l0); split_f16(v.y,h1,l1);
    split_f16(v.z,h2,l2); split_f16(v.w,h3,l3);
    *(__half2*)&h[i  ] = __halves2half2(h0,h1);
    *(__half2*)&h[i+2] = __halves2half2(h2,h3);
    *(__half2*)&l[i  ] = __halves2half2(l0,l1);
    *(__half2*)&l[i+2] = __halves2half2(l2,l3);
}

// ---------------- fp32 -> fp16 convert (hi only, 1-term weights) ----------
__global__ void tohalf_kernel(const float* __restrict__ s, h16* __restrict__ h,
                              long long n)
{
    long long i = ((long long)blockIdx.x*256 + threadIdx.x)*4;
    if (i >= n) return;
    float4 v = *(const float4*)&s[i];
    *(__half2*)&h[i  ] = __halves2half2(__float2half_rn(v.x), __float2half_rn(v.y));
    *(__half2*)&h[i+2] = __halves2half2(__float2half_rn(v.z), __float2half_rn(v.w));
}

// ---------------- layernorm (fp32 out OR fp16-hi out) ----------------
__global__ void ln_kernel(const float* __restrict__ X, const float* __restrict__ sc,
                          const float* __restrict__ bi, float* __restrict__ Yf,
                          h16* __restrict__ Yh, int Cn)
{
    const float* x = X + (long long)blockIdx.x * Cn;
    __shared__ float sh1[32], sh2[32];
    int tid = threadIdx.x;
    float s = 0.f, s2 = 0.f;
    for (int i = tid; i < Cn; i += 256) { float v = x[i]; s += v; s2 += v*v; }
    #pragma unroll
    for (int o = 16; o > 0; o >>= 1) {
        s  += __shfl_xor_sync(0xffffffffu, s,  o);
        s2 += __shfl_xor_sync(0xffffffffu, s2, o);
    }
    if ((tid & 31) == 0) { sh1[tid>>5] = s; sh2[tid>>5] = s2; }
    __syncthreads();
    if (tid < 32) {
        float a = (tid < 8) ? sh1[tid] : 0.f;
        float b = (tid < 8) ? sh2[tid] : 0.f;
        #pragma unroll
        for (int o = 4; o > 0; o >>= 1) {
            a += __shfl_xor_sync(0xffffffffu, a, o);
            b += __shfl_xor_sync(0xffffffffu, b, o);
        }
        if (tid == 0) { sh1[0] = a; sh2[0] = b; }
    }
    __syncthreads();
    float mean = sh1[0] / Cn;
    float var  = sh2[0] / Cn - mean*mean;
    float inv  = rsqrtf(var + 1e-5f);
    for (int i = tid; i < Cn; i += 256) {
        float v = (x[i] - mean) * inv * sc[i] + bi[i];
        if (Yf) Yf[(long long)blockIdx.x*Cn + i] = v;
        else    Yh[(long long)blockIdx.x*Cn + i] = __float2half_rn(v);
    }
}

// ---------------- softmax (fp32 in, fp16-hi out) ----------------
__global__ void softmax_kernel(const float* __restrict__ S, h16* __restrict__ Ph)
{
    const float* p = S + (long long)blockIdx.x * NP;
    h16* ph = Ph + (long long)blockIdx.x * NP;
    __shared__ float sh[32];
    int tid = threadIdx.x;
    const int IT = (NP + 255) / 256;
    float vals[(NP + 255) / 256];
    float mx = -1e30f;
    #pragma unroll
    for (int it = 0; it < IT; it++) {
        int i = tid + it*256;
        float v = (i < NP) ? p[i] : -1e30f;
        vals[it] = v;
        mx = fmaxf(mx, v);
    }
    #pragma unroll
    for (int o = 16; o > 0; o >>= 1) mx = fmaxf(mx, __shfl_xor_sync(0xffffffffu, mx, o));
    if ((tid & 31) == 0) sh[tid>>5] = mx;
    __syncthreads();
    if (tid < 32) {
        float v = (tid < 8) ? sh[tid] : -1e30f;
        #pragma unroll
        for (int o = 4; o > 0; o >>= 1) v = fmaxf(v, __shfl_xor_sync(0xffffffffu, v, o));
        if (tid == 0) sh[0] = v;
    }
    __syncthreads();
    mx = sh[0];
    __syncthreads();
    float sum = 0.f;
    #pragma unroll
    for (int it = 0; it < IT; it++) {
        int i = tid + it*256;
        float e = (i < NP) ? expf(vals[it] - mx) : 0.f;
        vals[it] = e;
        sum += e;
    }
    #pragma unroll
    for (int o = 16; o > 0; o >>= 1) sum += __shfl_xor_sync(0xffffffffu, sum, o);
    if ((tid & 31) == 0) sh[tid>>5] = sum;
    __syncthreads();
    if (tid < 32) {
        float v = (tid < 8) ? sh[tid] : 0.f;
        #pragma unroll
        for (int o = 4; o > 0; o >>= 1) v += __shfl_xor_sync(0xffffffffu, v, o);
        if (tid == 0) sh[0] = v;
    }
    __syncthreads();
    float inv = 1.0f / sh[0];
    #pragma unroll
    for (int it = 0; it < IT; it++) {
        int i = tid + it*256;
        if (i < NP) ph[i] = __float2half_rn(vals[it] * inv);
    }
}

// ---------------- im2col (writes fp16 hi only) ----------------
__global__ void im2col_kernel(const float* __restrict__ x)
{
    long long idx = (long long)blockIdx.x * 256 + threadIdx.x;
    if (idx >= (long long)NTOK * KPATCH) return;
    int j = (int)(idx % KPATCH);
    int m = (int)(idx / KPATCH);
    int b = m / NP, n = m % NP;
    int t = n / 196, r = n % 196, yy = r / 14, xx = r % 14;
    int i  = j / 512, r2 = j % 512;
    int dt = r2 / 256, r3 = r2 % 256;
    int dy = r3 / 16,  dx = r3 % 16;
    long long off = ((((long long)(b*3 + i)*16 + (2*t + dt))*224) + (16*yy + dy))*224 + (16*xx + dx);
    g_imh[idx] = __float2half_rn(x[off]);
}

// ---------------- positional encoding ----------------
__global__ void freq_kernel()
{
    int c2 = threadIdx.x;
    if (c2 < EMBED/2) g_freq[c2] = pow(10000.0, -2.0 * c2 / (double)EMBED);
}
__global__ void posadd_kernel()
{
    int idx = blockIdx.x * 256 + threadIdx.x;
    if (idx >= NP*EMBED) return;
    int n = idx / EMBED, c = idx % EMBED;
    double a = (double)n * g_freq[c >> 1];
    const double TWO_PI = 6.283185307179586476925286766559;
    int k = (int)(a * (1.0 / TWO_PI) + 0.5);
    float rf = (float)(a - (double)k * TWO_PI);
    float v = (c & 1) ? cosf(rf) : sinf(rf);
    g_h[idx]            += v;
    g_h[idx + NP*EMBED] += v;
}

// ---------------- mean pool ----------------
__global__ void pool_kernel()
{
    int idx = blockIdx.x * 256 + threadIdx.x;
    if (idx >= BATCH*EMBED) return;
    int b = idx / EMBED, c = idx % EMBED;
    const float* base = g_h + (long long)b*NP*EMBED + c;
    float s = 0.f;
    for (int n = 0; n < NP; n++) s += base[(long long)n*EMBED];
    g_pool[idx] = s * (1.0f / NP);
}

// ---------------- classifier head ----------------
__global__ void head_kernel(const float* __restrict__ W, const float* __restrict__ hb,
                            float* __restrict__ out)
{
    int g = blockIdx.x * 256 + threadIdx.x;
    int warp = g >> 5, lane = g & 31;
    if (warp >= BATCH*1000) return;
    int b = warp / 1000, j = warp % 1000;
    float s = 0.f;
    for (int c = lane; c < EMBED; c += 32)
        s += g_pln[b*EMBED + c] * W[j*EMBED + c];
    #pragma unroll
    for (int o = 16; o > 0; o >>= 1) s += __shfl_xor_sync(0xffffffffu, s, o);
    if (lane == 0) out[warp] = s + hb[j];
}

// ---------------- host orchestration ----------------
#define DSZ(anb,bnb,bnt) (((anb)*128 + (bnb)*(bnt))*SA*2*3)

extern "C" void kernel_launch(void* const* d_in, const int* in_sizes, int n_in,
                              void* d_out, int out_size)
{
    const float* x      = (const float*)d_in[0];
    const float* conv_w = (const float*)d_in[1];
    const float* conv_b = (const float*)d_in[2];
    const float* n1s    = (const float*)d_in[3];
    const float* n1b    = (const float*)d_in[4];
    const float* qkv_w  = (const float*)d_in[5];
    const float* out_w  = (const float*)d_in[6];
    const float* out_b  = (const float*)d_in[7];
    const float* n2s    = (const float*)d_in[8];
    const float* n2b    = (const float*)d_in[9];
    const float* fc1_w  = (const float*)d_in[10];
    const float* fc1_b  = (const float*)d_in[11];
    const float* fc2_w  = (const float*)d_in[12];
    const float* fc2_b  = (const float*)d_in[13];
    const float* fns    = (const float*)d_in[14];
    const float* fnb    = (const float*)d_in[15];
    const float* head_w = (const float*)d_in[16];
    const float* head_b = (const float*)d_in[17];
    float* out = (float*)d_out;

    float *h, *attn, *pool, *pln;
    h16 *imh,*yh,*qkvh,*qkvl,*Ph,*vth,*vtl,*aoh,*mlph;
    h16 *cwh,*cwl,*qwh,*owh,*w1h,*w2h;
    cudaGetSymbolAddress((void**)&h,    g_h);
    cudaGetSymbolAddress((void**)&attn, g_attn);
    cudaGetSymbolAddress((void**)&pool, g_pool);
    cudaGetSymbolAddress((void**)&pln,  g_pln);
    cudaGetSymbolAddress((void**)&imh,  g_imh);
    cudaGetSymbolAddress((void**)&yh,   g_yh);
    cudaGetSymbolAddress((void**)&qkvh, g_qkvh);  cudaGetSymbolAddress((void**)&qkvl,g_qkvl);
    cudaGetSymbolAddress((void**)&Ph,   g_Ph);
    cudaGetSymbolAddress((void**)&vth,  g_vth);   cudaGetSymbolAddress((void**)&vtl, g_vtl);
    cudaGetSymbolAddress((void**)&aoh,  g_aoh);
    cudaGetSymbolAddress((void**)&mlph, g_mlph);
    cudaGetSymbolAddress((void**)&cwh,  g_cwh);   cudaGetSymbolAddress((void**)&cwl, g_cwl);
    cudaGetSymbolAddress((void**)&qwh,  g_qwh);
    cudaGetSymbolAddress((void**)&owh,  g_owh);
    cudaGetSymbolAddress((void**)&w1h,  g_w1h);
    cudaGetSymbolAddress((void**)&w2h,  g_w2h);

    cudaFuncSetAttribute(mma8_gemm<1,0,2,64 >, cudaFuncAttributeMaxDynamicSharedMemorySize, DSZ(1,2,64));
    cudaFuncSetAttribute(mma8_gemm<0,2,1,128>, cudaFuncAttributeMaxDynamicSharedMemorySize, DSZ(1,1,128));
    cudaFuncSetAttribute(mma8_gemm<0,0,3,128>, cudaFuncAttributeMaxDynamicSharedMemorySize, DSZ(2,2,128));
    cudaFuncSetAttribute(mma8_gemm<0,1,2,96 >, cudaFuncAttributeMaxDynamicSharedMemorySize, DSZ(1,2,96));
    cudaFuncSetAttribute(mma8_gemm<4,0,1,64 >, cudaFuncAttributeMaxDynamicSharedMemorySize, DSZ(1,1,64));
    cudaFuncSetAttribute(mma8_gemm<2,1,1,128>, cudaFuncAttributeMaxDynamicSharedMemorySize, DSZ(1,1,128));

    const long long Z0 = 0;

    // ---- weight prep ----
    {
        long long n;
        n = (long long)EMBED*KPATCH;
        split_kernel<<<(int)((n/4+255)/256),256>>>(conv_w, cwh, cwl, n);
        n = (long long)DEPTH*3*EMBED*EMBED;
        tohalf_kernel<<<(int)((n/4+255)/256),256>>>(qkv_w, qwh, n);
        n = (long long)DEPTH*EMBED*EMBED;
        tohalf_kernel<<<(int)((n/4+255)/256),256>>>(out_w, owh, n);
        n = (long long)DEPTH*MLPH*EMBED;
        tohalf_kernel<<<(int)((n/4+255)/256),256>>>(fc1_w, w1h, n);
        n = (long long)DEPTH*EMBED*MLPH;
        tohalf_kernel<<<(int)((n/4+255)/256),256>>>(fc2_w, w2h, n);
    }

    // ---- patch embed ----
    im2col_kernel<<<(int)(((long long)NTOK*KPATCH + 255)/256), 256>>>(x);
    {
        dim3 g(EMBED/64, (NTOK+127)/128, 1);
        mma8_gemm<1,0,2,64><<<g,256,DSZ(1,2,64)>>>(
            imh, nullptr, cwh, cwl, conv_b, nullptr, h, nullptr, nullptr,
            NTOK, EMBED, KPATCH, KPATCH, KPATCH, EMBED, 0,
            Z0,Z0,Z0,Z0,Z0,Z0,Z0,Z0, 1);
    }
    freq_kernel<<<1, EMBED/2>>>();
    posadd_kernel<<<(NP*EMBED + 255)/256, 256>>>();

    // ---- transformer blocks ----
    for (int l = 0; l < DEPTH; l++) {
        h16* lqwh = qwh + (long long)l*3*EMBED*EMBED;
        h16* lowh = owh + (long long)l*EMBED*EMBED;
        h16* lw1h = w1h + (long long)l*MLPH*EMBED;
        h16* lw2h = w2h + (long long)l*EMBED*MLPH;
        const float* ob = out_b + (long long)l*EMBED;
        const float* b1 = fc1_b + (long long)l*MLPH;
        const float* b2 = fc2_b + (long long)l*EMBED;

        // y = LN1(h) -> fp16 hi
        ln_kernel<<<NTOK,256>>>(h, n1s + l*EMBED, n1b + l*EMBED, nullptr, yh, EMBED);

        {   // qkv = y @ qw^T  (1-term) -> fp16 hi+lo (Q/K lo for QK; V lo for PV)
            dim3 g((3*EMBED)/128, (NTOK+127)/128, 1);
            mma8_gemm<0,2,1,128><<<g,256,DSZ(1,1,128)>>>(
                yh, nullptr, lqwh, nullptr, nullptr, nullptr, nullptr, qkvh, qkvl,
                NTOK, 3*EMBED, EMBED, EMBED, EMBED, 3*EMBED, 0,
                Z0,Z0,Z0,Z0,Z0,Z0,Z0,Z0, 1);
        }

        {   // V^T per (b,h)
            dim3 g(NP/32, BATCH*HEADS, 1);
            vtrans_kernel<<<g,256>>>(qkvh, qkvl, vth, vtl);
        }

        {   // S = Q @ K^T  fp32 (3-term: logits unscaled, softmax-sensitive)
            dim3 g((NP+127)/128, (NP+127)/128, BATCH*HEADS);
            mma8_gemm<0,0,3,128><<<g,256,DSZ(2,2,128)>>>(
                qkvh, qkvl, qkvh + EMBED, qkvl + EMBED, nullptr, nullptr,
                attn, nullptr, nullptr,
                NP, NP, HDIM, 3*EMBED, 3*EMBED, NP, 0,
                (long long)NP*3*EMBED, (long long)HDIM,
                (long long)NP*3*EMBED, (long long)HDIM,
                (long long)HEADS*NP*NP, (long long)NP*NP,
                Z0, Z0, HEADS);
        }

        softmax_kernel<<<BATCH*HEADS*NP, 256>>>(attn, Ph);

        {   // ao = P @ VT^T  (2-term) -> fp16 hi (N=96)
            dim3 g(1, (NP+127)/128, BATCH*HEADS);
            mma8_gemm<0,1,2,96><<<g,256,DSZ(1,2,96)>>>(
                Ph, nullptr, vth, vtl, nullptr, nullptr, nullptr, aoh, nullptr,
                NP, HDIM, NP, NP, NP, EMBED, 0,
                (long long)HEADS*NP*NP, (long long)NP*NP,
                (long long)HEADS*HDIM*NP, (long long)HDIM*NP,
                (long long)NP*EMBED, (long long)HDIM,
                Z0, Z0, HEADS);
        }

        {   // h = h + ao @ ow^T + ob  (1-term)
            dim3 g(EMBED/64, (NTOK+127)/128, 1);
            mma8_gemm<4,0,1,64><<<g,256,DSZ(1,1,64)>>>(
                aoh, nullptr, lowh, nullptr, ob, h, h, nullptr, nullptr,
                NTOK, EMBED, EMBED, EMBED, EMBED, EMBED, EMBED,
                Z0,Z0,Z0,Z0,Z0,Z0,Z0,Z0, 1);
        }

        // y = LN2(h) -> fp16 hi
        ln_kernel<<<NTOK,256>>>(h, n2s + l*EMBED, n2b + l*EMBED, nullptr, yh, EMBED);

        {   // mlp = gelu(y @ w1^T + b1)  (1-term) -> fp16 hi
            dim3 g(MLPH/128, (NTOK+127)/128, 1);
            mma8_gemm<2,1,1,128><<<g,256,DSZ(1,1,128)>>>(
                yh, nullptr, lw1h, nullptr, b1, nullptr, nullptr, mlph, nullptr,
                NTOK, MLPH, EMBED, EMBED, EMBED, MLPH, 0,
                Z0,Z0,Z0,Z0,Z0,Z0,Z0,Z0, 1);
        }

        {   // h = h + mlp @ w2^T + b2  (1-term)
            dim3 g(EMBED/64, (NTOK+127)/128, 1);
            mma8_gemm<4,0,1,64><<<g,256,DSZ(1,1,64)>>>(
                mlph, nullptr, lw2h, nullptr, b2, h, h, nullptr, nullptr,
                NTOK, EMBED, MLPH, MLPH, MLPH, EMBED, EMBED,
                Z0,Z0,Z0,Z0,Z0,Z0,Z0,Z0, 1);
        }
    }

    // ---- pooled head ----
    pool_kernel<<<(BATCH*EMBED + 255)/256, 256>>>();
    ln_kernel<<<BATCH,256>>>(pool, fns, fnb, pln, nullptr, EMBED);
    head_kernel<<<(BATCH*1000*32 + 255)/256, 256>>>(head_w, head_b, out);
}

// round 11
// speedup vs baseline: 1.9990x; 1.0736x over previous
#include <cuda_runtime.h>
#include <cuda_fp16.h>
#include <math.h>
#include <stdint.h>

#define EMBED   768
#define HEADS   8
#define HDIM    96
#define DEPTH   12
#define MLPH    3072
#define NP      1568
#define BATCH   2
#define NTOK    (BATCH*NP)      // 3136
#define KPATCH  1536

typedef __half h16;

// ---------------- scratch (device globals: allocation-free) ----------------
__device__ __align__(256) h16   g_imh [NTOK*KPATCH];
__device__ __align__(256) float g_h   [NTOK*EMBED];
__device__ __align__(256) h16   g_yh  [NTOK*EMBED];
__device__ __align__(256) h16   g_qkvh[NTOK*3*EMBED];
__device__ __align__(256) h16   g_qkvl[NTOK*3*EMBED];
__device__ __align__(256) float g_attn[39337984];     // 2*8*1568^2 fp32
__device__ __align__(256) h16   g_Ph  [39337984];
__device__ __align__(256) h16   g_vth [16*HDIM*NP];   // V^T per (b,h): [96][1568]
__device__ __align__(256) h16   g_aoh [NTOK*EMBED];
__device__ __align__(256) h16   g_mlph[NTOK*MLPH];
__device__ float g_pool[BATCH*EMBED];
__device__ float g_pln [BATCH*EMBED];
__device__ double g_freq[EMBED/2];
// weights: conv hi+lo (2-term); qkv/out/fc1/fc2 hi only (1-term)
__device__ __align__(256) h16 g_cwh[EMBED*KPATCH];
__device__ __align__(256) h16 g_cwl[EMBED*KPATCH];
__device__ __align__(256) h16 g_qwh[DEPTH*3*EMBED*EMBED];
__device__ __align__(256) h16 g_owh[DEPTH*EMBED*EMBED];
__device__ __align__(256) h16 g_w1h[DEPTH*MLPH*EMBED];
__device__ __align__(256) h16 g_w2h[DEPTH*EMBED*MLPH];

__device__ __forceinline__ void split_f16(float v, h16& h, h16& l)
{
    h = __float2half_rn(v);
    l = __float2half_rn(v - __half2float(h));
}

// ================= GEMM: fp16 split, TERMS in {1,2,3} ======================
// C = A @ B^T (+EPI). A[M,K] k-contig (hi [,lo if TERMS=3]).
// B[N,K] k-contig (hi [,lo if TERMS>=2]). All terms f32-accum:
//   TERMS=1: Ah*Bh   TERMS=2: +Ah*Bl   TERMS=3: +Al*Bh
// Block: 128 x BNT, BK=32. 8 warps = 4m x 2n, warp tile 32 x (BNT/2).
// EPI: 0 none | 1 +bias | 2 +bias,gelu | 4 +bias,+residual
// OUT: 0 fp32 | 1 fp16 hi only | 2 fp16 hi+lo
#define BK 32
#define SA 40           // padded k-stride (elems); conflict-free LDSM

#define LDSM4(R, addr) \
    asm volatile("ldmatrix.sync.aligned.m8n8.x4.shared.b16 {%0,%1,%2,%3},[%4];" \
        : "=r"((R)[0]), "=r"((R)[1]), "=r"((R)[2]), "=r"((R)[3]) : "r"(addr))

#define MMA_F32(C, A, B0, B1) \
    asm volatile("mma.sync.aligned.m16n8k16.row.col.f32.f16.f16.f32 " \
        "{%0,%1,%2,%3},{%4,%5,%6,%7},{%8,%9},{%0,%1,%2,%3};" \
        : "+f"((C)[0]), "+f"((C)[1]), "+f"((C)[2]), "+f"((C)[3]) \
        : "r"((A)[0]), "r"((A)[1]), "r"((A)[2]), "r"((A)[3]), "r"(B0), "r"(B1))

__device__ __forceinline__ void cpa16(uint32_t dst, const void* src, bool p)
{
    int sz = p ? 16 : 0;
    asm volatile("cp.async.cg.shared.global [%0],[%1],16,%2;\n"
                 :: "r"(dst), "l"(src), "r"(sz));
}

template<int EPI, int OUT, int TERMS, int BNT>
__global__ void __launch_bounds__(256)
mma11_gemm(const h16* __restrict__ Agh, const h16* __restrict__ Agl,
           const h16* __restrict__ Bgh, const h16* __restrict__ Bgl,
           const float* __restrict__ bias, const float* __restrict__ R,
           float* __restrict__ Cf, h16* __restrict__ Ch, h16* __restrict__ Cl,
           int M, int N, int K, int lda, int ldb, int ldc, int ldr,
           long long zab, long long zah, long long zbb, long long zbh,
           long long zcb, long long zch, long long zrb, long long zrh, int H)
{
    constexpr int WN    = BNT / 2;
    constexpr int NPR   = WN / 16;
    constexpr int ANB   = (TERMS == 3) ? 2 : 1;
    constexpr int BNB   = (TERMS >= 2) ? 2 : 1;
    constexpr int OFFAL = 128 * SA;
    constexpr int OFFB  = ANB * 128 * SA;
    constexpr int STAGE = (ANB * 128 + BNB * BNT) * SA;

    const int z  = blockIdx.z;
    const int bb = z / H, hh = z % H;
    Agh += bb*zab + hh*zah;
    if (TERMS == 3) Agl += bb*zab + hh*zah;
    Bgh += bb*zbb + hh*zbh;
    if (TERMS >= 2) Bgl += bb*zbb + hh*zbh;
    const long long coff = bb*zcb + hh*zch;
    if (OUT == 0) Cf += coff; else { Ch += coff; if (OUT == 2) Cl += coff; }
    if (EPI >= 3) R += bb*zrb + hh*zrh;

    extern __shared__ __align__(16) h16 smem[];
    const uint32_t su = (uint32_t)__cvta_generic_to_shared(smem);

    const int tid  = threadIdx.x;
    const int lane = tid & 31;
    const int w    = tid >> 5;
    const int wm   = w >> 1;
    const int wn   = w & 1;
    const int m0   = blockIdx.y * 128;
    const int n0   = blockIdx.x * BNT;

    float c[2][2*NPR][4];
    #pragma unroll
    for (int i = 0; i < 2; i++)
        #pragma unroll
        for (int j = 0; j < 2*NPR; j++)
            #pragma unroll
            for (int q = 0; q < 4; q++) c[i][j][q] = 0.f;

    const int lrow = lane & 15;
    const int lcol = (lane >> 4) * 8;
    const uint32_t aoffA = (uint32_t)(((wm*32 + lrow)*SA + lcol) * 2);
    const uint32_t boffB = (uint32_t)(((wn*WN + lrow)*SA + lcol) * 2);

    const int T = K / BK;

    auto issue = [&](int t, int s) {
        const int k0 = t * BK;
        const uint32_t sb = su + (uint32_t)(s * STAGE) * 2u;
        #pragma unroll
        for (int i = 0; i < 2*ANB; i++) {             // A: exactly ANB*128*4 chunks
            const int hl  = i >> 1;
            const int ch  = ((i & 1) << 8) + tid;
            const int row = ch >> 2;
            const int kc  = (ch & 3) << 3;
            const bool p  = (m0 + row) < M;
            const h16* src = (hl ? Agl : Agh)
                           + (long long)(p ? (m0 + row) : 0) * lda + k0 + kc;
            cpa16(sb + (uint32_t)((hl ? OFFAL : 0) + row*SA + kc) * 2u, src, p);
        }
        // B: BNB*BNT*4 total 16B chunks (may not divide 256 evenly -> guard)
        constexpr int BTOT = BNB * BNT * 4;
        constexpr int BCH  = (BTOT + 255) / 256;
        #pragma unroll
        for (int i = 0; i < BCH; i++) {
            const int ch = i*256 + tid;
            if (BTOT % 256 != 0 && ch >= BTOT) break;
            const int hl  = ch / (BNT*4);
            const int rem = ch % (BNT*4);
            const int row = rem >> 2;
            const int kc  = (rem & 3) << 3;
            const bool p  = (n0 + row) < N;
            const h16* src = (hl ? Bgl : Bgh)
                           + (long long)(p ? (n0 + row) : 0) * ldb + k0 + kc;
            cpa16(sb + (uint32_t)(OFFB + hl*BNT*SA + row*SA + kc) * 2u, src, p);
        }
    };

    issue(0, 0);
    asm volatile("cp.async.commit_group;");
    if (T > 1) { issue(1, 1); asm volatile("cp.async.commit_group;"); }

    for (int t = 0; t < T; t++) {
        if (t + 1 < T) asm volatile("cp.async.wait_group 1;");
        else           asm volatile("cp.async.wait_group 0;");
        __syncthreads();

        if (t + 2 < T) {
            issue(t + 2, (t + 2) % 3);
            asm volatile("cp.async.commit_group;");
        }

        const int s = t % 3;
        const uint32_t sb  = su + (uint32_t)(s * STAGE) * 2u;
        const uint32_t aHb = sb + aoffA;
        const uint32_t aLb = aHb + (uint32_t)OFFAL * 2u;
        const uint32_t bHb = sb + (uint32_t)OFFB * 2u + boffB;
        const uint32_t bLb = bHb + (uint32_t)(BNT*SA) * 2u;

        #pragma unroll
        for (int kk2 = 0; kk2 < 2; kk2++) {
            const uint32_t kb = (uint32_t)(kk2 * 32);
            uint32_t Ahf[2][4], Alf[2][4], Bhf[NPR][4], Blf[NPR][4];
            #pragma unroll
            for (int mi = 0; mi < 2; mi++) {
                LDSM4(Ahf[mi], aHb + (uint32_t)(mi*16*SA*2) + kb);
                if (TERMS == 3)
                    LDSM4(Alf[mi], aLb + (uint32_t)(mi*16*SA*2) + kb);
            }
            #pragma unroll
            for (int pr = 0; pr < NPR; pr++) {
                LDSM4(Bhf[pr], bHb + (uint32_t)(pr*16*SA*2) + kb);
                if (TERMS >= 2)
                    LDSM4(Blf[pr], bLb + (uint32_t)(pr*16*SA*2) + kb);
            }
            #pragma unroll
            for (int mi = 0; mi < 2; mi++) {
                #pragma unroll
                for (int pr = 0; pr < NPR; pr++) {
                    MMA_F32(c[mi][2*pr  ], Ahf[mi], Bhf[pr][0], Bhf[pr][2]);
                    MMA_F32(c[mi][2*pr+1], Ahf[mi], Bhf[pr][1], Bhf[pr][3]);
                    if (TERMS >= 2) {
                        MMA_F32(c[mi][2*pr  ], Ahf[mi], Blf[pr][0], Blf[pr][2]);
                        MMA_F32(c[mi][2*pr+1], Ahf[mi], Blf[pr][1], Blf[pr][3]);
                    }
                    if (TERMS == 3) {
                        MMA_F32(c[mi][2*pr  ], Alf[mi], Bhf[pr][0], Bhf[pr][2]);
                        MMA_F32(c[mi][2*pr+1], Alf[mi], Bhf[pr][1], Bhf[pr][3]);
                    }
                }
            }
        }
    }

    // ---------------- epilogue ----------------
    const int g  = lane >> 2;
    const int tq = lane & 3;
    #pragma unroll
    for (int mi = 0; mi < 2; mi++) {
        #pragma unroll
        for (int nf = 0; nf < 2*NPR; nf++) {
            int col = n0 + wn*WN + nf*8 + tq*2;
            #pragma unroll
            for (int half = 0; half < 2; half++) {
                int row = m0 + wm*32 + mi*16 + g + half*8;
                if (row >= M || col >= N) continue;
                float v0 = c[mi][nf][half*2 + 0];
                float v1 = c[mi][nf][half*2 + 1];
                if (EPI == 1 || EPI == 2 || EPI == 4) { v0 += bias[col]; v1 += bias[col+1]; }
                if (EPI == 2) {
                    v0 = 0.5f * v0 * (1.0f + erff(v0 * 0.70710678118654752f));
                    v1 = 0.5f * v1 * (1.0f + erff(v1 * 0.70710678118654752f));
                }
                if (EPI >= 3) {
                    float2 r2 = *(const float2*)&R[(long long)row*ldr + col];
                    v0 += r2.x; v1 += r2.y;
                }
                if (OUT == 0) {
                    float2 o; o.x = v0; o.y = v1;
                    *(float2*)&Cf[(long long)row*ldc + col] = o;
                } else if (OUT == 1) {
                    *(__half2*)&Ch[(long long)row*ldc + col] =
                        __halves2half2(__float2half_rn(v0), __float2half_rn(v1));
                } else {
                    h16 h0,h1,l0,l1;
                    split_f16(v0,h0,l0); split_f16(v1,h1,l1);
                    *(__half2*)&Ch[(long long)row*ldc + col] = __halves2half2(h0,h1);
                    *(__half2*)&Cl[(long long)row*ldc + col] = __halves2half2(l0,l1);
                }
            }
        }
    }
}

// ---------------- V transpose (hi only): VT[z][n][k] = V[z][k][n] ----------
__global__ void vtrans_kernel(const h16* __restrict__ qh, h16* __restrict__ vth)
{
    __shared__ h16 th[32][100];
    const int z = blockIdx.y, bb = z >> 3, hh = z & 7;
    const int k0 = blockIdx.x * 32;
    const int tid = threadIdx.x;
    const h16* sh = qh + ((long long)(bb*NP) + k0)*(3*EMBED) + 2*EMBED + hh*HDIM;
    for (int idx = tid; idx < 32*HDIM; idx += 256) {
        int kk = idx / HDIM, nn = idx % HDIM;
        th[kk][nn] = sh[(long long)kk*(3*EMBED) + nn];
    }
    __syncthreads();
    h16* dh = vth + (long long)z*HDIM*NP + k0;
    for (int idx = tid; idx < 32*HDIM; idx += 256) {
        int nn = idx >> 5, kk = idx & 31;
        dh[(long long)nn*NP + kk] = th[kk][nn];
    }
}

// ---------------- fp32 -> fp16 hi/lo split (conv weight) ----------------
__global__ void split_kernel(const float* __restrict__ s, h16* __restrict__ h,
                             h16* __restrict__ l, long long n)
{
    long long i = ((long long)blockIdx.x*256 + threadIdx.x)*4;
    if (i >= n) return;
    float4 v = *(const float4*)&s[i];
    h16 h0,h1,h2,h3,l0,l1,l2,l3;
    split_f16(v.x,h0,l0); split_f16(v.y,h1,l1);
    split_f16(v.z,h2,l2); split_f16(v.w,h3,l3);
    *(__half2*)&h[i  ] = __halves2half2(h0,h1);
    *(__half2*)&h[i+2] = __halves2half2(h2,h3);
    *(__half2*)&l[i  ] = __halves2half2(l0,l1);
    *(__half2*)&l[i+2] = __halves2half2(l2,l3);
}

// ---------------- fp32 -> fp16 convert (hi only) ----------
__global__ void tohalf_kernel(const float* __restrict__ s, h16* __restrict__ h,
                              long long n)
{
    long long i = ((long long)blockIdx.x*256 + threadIdx.x)*4;
    if (i >= n) return;
    float4 v = *(const float4*)&s[i];
    *(__half2*)&h[i  ] = __halves2half2(__float2half_rn(v.x), __float2half_rn(v.y));
    *(__half2*)&h[i+2] = __halves2half2(__float2half_rn(v.z), __float2half_rn(v.w));
}

// ---------------- layernorm (fp32 out OR fp16-hi out) ----------------
__global__ void ln_kernel(const float* __restrict__ X, const float* __restrict__ sc,
                          const float* __restrict__ bi, float* __restrict__ Yf,
                          h16* __restrict__ Yh, int Cn)
{
    const float* x = X + (long long)blockIdx.x * Cn;
    __shared__ float sh1[32], sh2[32];
    int tid = threadIdx.x;
    float s = 0.f, s2 = 0.f;
    for (int i = tid; i < Cn; i += 256) { float v = x[i]; s += v; s2 += v*v; }
    #pragma unroll
    for (int o = 16; o > 0; o >>= 1) {
        s  += __shfl_xor_sync(0xffffffffu, s,  o);
        s2 += __shfl_xor_sync(0xffffffffu, s2, o);
    }
    if ((tid & 31) == 0) { sh1[tid>>5] = s; sh2[tid>>5] = s2; }
    __syncthreads();
    if (tid < 32) {
        float a = (tid < 8) ? sh1[tid] : 0.f;
        float b = (tid < 8) ? sh2[tid] : 0.f;
        #pragma unroll
        for (int o = 4; o > 0; o >>= 1) {
            a += __shfl_xor_sync(0xffffffffu, a, o);
            b += __shfl_xor_sync(0xffffffffu, b, o);
        }
        if (tid == 0) { sh1[0] = a; sh2[0] = b; }
    }
    __syncthreads();
    float mean = sh1[0] / Cn;
    float var  = sh2[0] / Cn - mean*mean;
    float inv  = rsqrtf(var + 1e-5f);
    for (int i = tid; i < Cn; i += 256) {
        float v = (x[i] - mean) * inv * sc[i] + bi[i];
        if (Yf) Yf[(long long)blockIdx.x*Cn + i] = v;
        else    Yh[(long long)blockIdx.x*Cn + i] = __float2half_rn(v);
    }
}

// ---------------- softmax: max-stabilized, __expf, one gmem read ----------
__global__ void softmax_kernel(const float* __restrict__ S, h16* __restrict__ Ph)
{
    const float* p = S + (long long)blockIdx.x * NP;
    h16* ph = Ph + (long long)blockIdx.x * NP;
    __shared__ float sh[32];
    int tid = threadIdx.x;
    const int IT = (NP + 255) / 256;   // 7
    float vals[(NP + 255) / 256];
    float mx = -1e30f;
    #pragma unroll
    for (int it = 0; it < IT; it++) {
        int i = tid + it*256;
        float v = (i < NP) ? p[i] : -1e30f;
        vals[it] = v;
        mx = fmaxf(mx, v);
    }
    #pragma unroll
    for (int o = 16; o > 0; o >>= 1) mx = fmaxf(mx, __shfl_xor_sync(0xffffffffu, mx, o));
    if ((tid & 31) == 0) sh[tid>>5] = mx;
    __syncthreads();
    if (tid < 32) {
        float v = (tid < 8) ? sh[tid] : -1e30f;
        #pragma unroll
        for (int o = 4; o > 0; o >>= 1) v = fmaxf(v, __shfl_xor_sync(0xffffffffu, v, o));
        if (tid == 0) sh[0] = v;
    }
    __syncthreads();
    mx = sh[0];
    __syncthreads();
    float sum = 0.f;
    #pragma unroll
    for (int it = 0; it < IT; it++) {
        int i = tid + it*256;
        float e = (i < NP) ? __expf(vals[it] - mx) : 0.f;   // arg <= 0: safe
        vals[it] = e;
        sum += e;
    }
    #pragma unroll
    for (int o = 16; o > 0; o >>= 1) sum += __shfl_xor_sync(0xffffffffu, sum, o);
    if ((tid & 31) == 0) sh[tid>>5] = sum;
    __syncthreads();
    if (tid < 32) {
        float v = (tid < 8) ? sh[tid] : 0.f;
        #pragma unroll
        for (int o = 4; o > 0; o >>= 1) v += __shfl_xor_sync(0xffffffffu, v, o);
        if (tid == 0) sh[0] = v;
    }
    __syncthreads();
    float inv = 1.0f / sh[0];
    #pragma unroll
    for (int it = 0; it < IT; it++) {
        int i = tid + it*256;
        if (i < NP) ph[i] = __float2half_rn(vals[it] * inv);
    }
}

// ---------------- im2col (writes fp16 hi only) ----------------
__global__ void im2col_kernel(const float* __restrict__ x)
{
    long long idx = (long long)blockIdx.x * 256 + threadIdx.x;
    if (idx >= (long long)NTOK * KPATCH) return;
    int j = (int)(idx % KPATCH);
    int m = (int)(idx / KPATCH);
    int b = m / NP, n = m % NP;
    int t = n / 196, r = n % 196, yy = r / 14, xx = r % 14;
    int i  = j / 512, r2 = j % 512;
    int dt = r2 / 256, r3 = r2 % 256;
    int dy = r3 / 16,  dx = r3 % 16;
    long long off = ((((long long)(b*3 + i)*16 + (2*t + dt))*224) + (16*yy + dy))*224 + (16*xx + dx);
    g_imh[idx] = __float2half_rn(x[off]);
}

// ---------------- positional encoding ----------------
__global__ void freq_kernel()
{
    int c2 = threadIdx.x;
    if (c2 < EMBED/2) g_freq[c2] = pow(10000.0, -2.0 * c2 / (double)EMBED);
}
__global__ void posadd_kernel()
{
    int idx = blockIdx.x * 256 + threadIdx.x;
    if (idx >= NP*EMBED) return;
    int n = idx / EMBED, c = idx % EMBED;
    double a = (double)n * g_freq[c >> 1];
    const double TWO_PI = 6.283185307179586476925286766559;
    int k = (int)(a * (1.0 / TWO_PI) + 0.5);
    float rf = (float)(a - (double)k * TWO_PI);
    float v = (c & 1) ? cosf(rf) : sinf(rf);
    g_h[idx]            += v;
    g_h[idx + NP*EMBED] += v;
}

// ---------------- mean pool: coalesced block reduce ----------------
__global__ void pool_kernel()
{
    __shared__ float acc[2][128];
    const int b  = blockIdx.y;
    const int c0 = blockIdx.x * 128;
    const int tg = threadIdx.x >> 7;
    const int c  = threadIdx.x & 127;
    const float* base = g_h + (long long)b*NP*EMBED + c0 + c;
    float s = 0.f;
    for (int n = tg; n < NP; n += 2)
        s += base[(long long)n*EMBED];
    acc[tg][c] = s;
    __syncthreads();
    if (tg == 0)
        g_pool[b*EMBED + c0 + c] = (acc[0][c] + acc[1][c]) * (1.0f / NP);
}

// ---------------- classifier head ----------------
__global__ void head_kernel(const float* __restrict__ W, const float* __restrict__ hb,
                            float* __restrict__ out)
{
    int g = blockIdx.x * 256 + threadIdx.x;
    int warp = g >> 5, lane = g & 31;
    if (warp >= BATCH*1000) return;
    int b = warp / 1000, j = warp % 1000;
    float s = 0.f;
    for (int c = lane; c < EMBED; c += 32)
        s += g_pln[b*EMBED + c] * W[j*EMBED + c];
    #pragma unroll
    for (int o = 16; o > 0; o >>= 1) s += __shfl_xor_sync(0xffffffffu, s, o);
    if (lane == 0) out[warp] = s + hb[j];
}

// ---------------- host orchestration ----------------
#define DSZ(anb,bnb,bnt) (((anb)*128 + (bnb)*(bnt))*SA*2*3)

extern "C" void kernel_launch(void* const* d_in, const int* in_sizes, int n_in,
                              void* d_out, int out_size)
{
    const float* x      = (const float*)d_in[0];
    const float* conv_w = (const float*)d_in[1];
    const float* conv_b = (const float*)d_in[2];
    const float* n1s    = (const float*)d_in[3];
    const float* n1b    = (const float*)d_in[4];
    const float* qkv_w  = (const float*)d_in[5];
    const float* out_w  = (const float*)d_in[6];
    const float* out_b  = (const float*)d_in[7];
    const float* n2s    = (const float*)d_in[8];
    const float* n2b    = (const float*)d_in[9];
    const float* fc1_w  = (const float*)d_in[10];
    const float* fc1_b  = (const float*)d_in[11];
    const float* fc2_w  = (const float*)d_in[12];
    const float* fc2_b  = (const float*)d_in[13];
    const float* fns    = (const float*)d_in[14];
    const float* fnb    = (const float*)d_in[15];
    const float* head_w = (const float*)d_in[16];
    const float* head_b = (const float*)d_in[17];
    float* out = (float*)d_out;

    float *h, *attn, *pool, *pln;
    h16 *imh,*yh,*qkvh,*qkvl,*Ph,*vth,*aoh,*mlph;
    h16 *cwh,*cwl,*qwh,*owh,*w1h,*w2h;
    cudaGetSymbolAddress((void**)&h,    g_h);
    cudaGetSymbolAddress((void**)&attn, g_attn);
    cudaGetSymbolAddress((void**)&pool, g_pool);
    cudaGetSymbolAddress((void**)&pln,  g_pln);
    cudaGetSymbolAddress((void**)&imh,  g_imh);
    cudaGetSymbolAddress((void**)&yh,   g_yh);
    cudaGetSymbolAddress((void**)&qkvh, g_qkvh);  cudaGetSymbolAddress((void**)&qkvl,g_qkvl);
    cudaGetSymbolAddress((void**)&Ph,   g_Ph);
    cudaGetSymbolAddress((void**)&vth,  g_vth);
    cudaGetSymbolAddress((void**)&aoh,  g_aoh);
    cudaGetSymbolAddress((void**)&mlph, g_mlph);
    cudaGetSymbolAddress((void**)&cwh,  g_cwh);   cudaGetSymbolAddress((void**)&cwl, g_cwl);
    cudaGetSymbolAddress((void**)&qwh,  g_qwh);
    cudaGetSymbolAddress((void**)&owh,  g_owh);
    cudaGetSymbolAddress((void**)&w1h,  g_w1h);
    cudaGetSymbolAddress((void**)&w2h,  g_w2h);

    cudaFuncSetAttribute(mma11_gemm<1,0,2,64 >, cudaFuncAttributeMaxDynamicSharedMemorySize, DSZ(1,2,64));
    cudaFuncSetAttribute(mma11_gemm<0,2,1,128>, cudaFuncAttributeMaxDynamicSharedMemorySize, DSZ(1,1,128));
    cudaFuncSetAttribute(mma11_gemm<0,0,3,128>, cudaFuncAttributeMaxDynamicSharedMemorySize, DSZ(2,2,128));
    cudaFuncSetAttribute(mma11_gemm<0,1,1,96 >, cudaFuncAttributeMaxDynamicSharedMemorySize, DSZ(1,1,96));
    cudaFuncSetAttribute(mma11_gemm<4,0,1,64 >, cudaFuncAttributeMaxDynamicSharedMemorySize, DSZ(1,1,64));
    cudaFuncSetAttribute(mma11_gemm<2,1,1,128>, cudaFuncAttributeMaxDynamicSharedMemorySize, DSZ(1,1,128));

    const long long Z0 = 0;

    // ---- weight prep ----
    {
        long long n;
        n = (long long)EMBED*KPATCH;
        split_kernel<<<(int)((n/4+255)/256),256>>>(conv_w, cwh, cwl, n);
        n = (long long)DEPTH*3*EMBED*EMBED;
        tohalf_kernel<<<(int)((n/4+255)/256),256>>>(qkv_w, qwh, n);
        n = (long long)DEPTH*EMBED*EMBED;
        tohalf_kernel<<<(int)((n/4+255)/256),256>>>(out_w, owh, n);
        n = (long long)DEPTH*MLPH*EMBED;
        tohalf_kernel<<<(int)((n/4+255)/256),256>>>(fc1_w, w1h, n);
        n = (long long)DEPTH*EMBED*MLPH;
        tohalf_kernel<<<(int)((n/4+255)/256),256>>>(fc2_w, w2h, n);
    }

    // ---- patch embed ----
    im2col_kernel<<<(int)(((long long)NTOK*KPATCH + 255)/256), 256>>>(x);
    {
        dim3 g(EMBED/64, (NTOK+127)/128, 1);
        mma11_gemm<1,0,2,64><<<g,256,DSZ(1,2,64)>>>(
            imh, nullptr, cwh, cwl, conv_b, nullptr, h, nullptr, nullptr,
            NTOK, EMBED, KPATCH, KPATCH, KPATCH, EMBED, 0,
            Z0,Z0,Z0,Z0,Z0,Z0,Z0,Z0, 1);
    }
    freq_kernel<<<1, EMBED/2>>>();
    posadd_kernel<<<(NP*EMBED + 255)/256, 256>>>();

    // ---- transformer blocks ----
    for (int l = 0; l < DEPTH; l++) {
        h16* lqwh = qwh + (long long)l*3*EMBED*EMBED;
        h16* lowh = owh + (long long)l*EMBED*EMBED;
        h16* lw1h = w1h + (long long)l*MLPH*EMBED;
        h16* lw2h = w2h + (long long)l*EMBED*MLPH;
        const float* ob = out_b + (long long)l*EMBED;
        const float* b1 = fc1_b + (long long)l*MLPH;
        const float* b2 = fc2_b + (long long)l*EMBED;

        // y = LN1(h) -> fp16 hi
        ln_kernel<<<NTOK,256>>>(h, n1s + l*EMBED, n1b + l*EMBED, nullptr, yh, EMBED);

        {   // qkv = y @ qw^T  (1-term) -> fp16 hi+lo (Q/K lo used by 3-term QK)
            dim3 g((3*EMBED)/128, (NTOK+127)/128, 1);
            mma11_gemm<0,2,1,128><<<g,256,DSZ(1,1,128)>>>(
                yh, nullptr, lqwh, nullptr, nullptr, nullptr, nullptr, qkvh, qkvl,
                NTOK, 3*EMBED, EMBED, EMBED, EMBED, 3*EMBED, 0,
                Z0,Z0,Z0,Z0,Z0,Z0,Z0,Z0, 1);
        }

        {   // V^T per (b,h), hi only
            dim3 g(NP/32, BATCH*HEADS, 1);
            vtrans_kernel<<<g,256>>>(qkvh, vth);
        }

        {   // S = Q @ K^T  fp32 (3-term: logits unscaled, softmax-sensitive)
            dim3 g((NP+127)/128, (NP+127)/128, BATCH*HEADS);
            mma11_gemm<0,0,3,128><<<g,256,DSZ(2,2,128)>>>(
                qkvh, qkvl, qkvh + EMBED, qkvl + EMBED, nullptr, nullptr,
                attn, nullptr, nullptr,
                NP, NP, HDIM, 3*EMBED, 3*EMBED, NP, 0,
                (long long)NP*3*EMBED, (long long)HDIM,
                (long long)NP*3*EMBED, (long long)HDIM,
                (long long)HEADS*NP*NP, (long long)NP*NP,
                Z0, Z0, HEADS);
        }

        softmax_kernel<<<BATCH*HEADS*NP, 256>>>(attn, Ph);

        {   // ao = P @ VT^T  (1-term) -> fp16 hi (N=96)
            dim3 g(1, (NP+127)/128, BATCH*HEADS);
            mma11_gemm<0,1,1,96><<<g,256,DSZ(1,1,96)>>>(
                Ph, nullptr, vth, nullptr, nullptr, nullptr, nullptr, aoh, nullptr,
                NP, HDIM, NP, NP, NP, EMBED, 0,
                (long long)HEADS*NP*NP, (long long)NP*NP,
                (long long)HEADS*HDIM*NP, (long long)HDIM*NP,
                (long long)NP*EMBED, (long long)HDIM,
                Z0, Z0, HEADS);
        }

        {   // h = h + ao @ ow^T + ob  (1-term)
            dim3 g(EMBED/64, (NTOK+127)/128, 1);
            mma11_gemm<4,0,1,64><<<g,256,DSZ(1,1,64)>>>(
                aoh, nullptr, lowh, nullptr, ob, h, h, nullptr, nullptr,
                NTOK, EMBED, EMBED, EMBED, EMBED, EMBED, EMBED,
                Z0,Z0,Z0,Z0,Z0,Z0,Z0,Z0, 1);
        }

        // y = LN2(h) -> fp16 hi
        ln_kernel<<<NTOK,256>>>(h, n2s + l*EMBED, n2b + l*EMBED, nullptr, yh, EMBED);

        {   // mlp = gelu(y @ w1^T + b1)  (1-term) -> fp16 hi
            dim3 g(MLPH/128, (NTOK+127)/128, 1);
            mma11_gemm<2,1,1,128><<<g,256,DSZ(1,1,128)>>>(
                yh, nullptr, lw1h, nullptr, b1, nullptr, nullptr, mlph, nullptr,
                NTOK, MLPH, EMBED, EMBED, EMBED, MLPH, 0,
                Z0,Z0,Z0,Z0,Z0,Z0,Z0,Z0, 1);
        }

        {   // h = h + mlp @ w2^T + b2  (1-term)
            dim3 g(EMBED/64, (NTOK+127)/128, 1);
            mma11_gemm<4,0,1,64><<<g,256,DSZ(1,1,64)>>>(
                mlph, nullptr, lw2h, nullptr, b2, h, h, nullptr, nullptr,
                NTOK, EMBED, MLPH, MLPH, MLPH, EMBED, EMBED,
                Z0,Z0,Z0,Z0,Z0,Z0,Z0,Z0, 1);
        }
    }

    // ---- pooled head ----
    {
        dim3 g(EMBED/128, BATCH);
        pool_kernel<<<g,256>>>();
    }
    ln_kernel<<<BATCH,256>>>(pool, fns, fnb, pln, nullptr, EMBED);
    head_kernel<<<(BATCH*1000*32 + 255)/256, 256>>>(head_w, head_b, out);
}

// round 12
// speedup vs baseline: 2.2040x; 1.1025x over previous
#include <cuda_runtime.h>
#include <cuda_fp16.h>
#include <math.h>
#include <stdint.h>

#define EMBED   768
#define HEADS   8
#define HDIM    96
#define DEPTH   12
#define MLPH    3072
#define NP      1568
#define BATCH   2
#define NTOK    (BATCH*NP)      // 3136
#define KPATCH  1536

typedef __half h16;

// ---------------- scratch (device globals: allocation-free) ----------------
__device__ __align__(256) h16   g_imh [NTOK*KPATCH];
__device__ __align__(256) float g_h   [NTOK*EMBED];
__device__ __align__(256) h16   g_yh  [NTOK*EMBED];
__device__ __align__(256) h16   g_qkvh[NTOK*3*EMBED];
__device__ __align__(256) h16   g_qkvl[NTOK*3*EMBED];
__device__ __align__(256) float g_attn[39337984];     // 2*8*1568^2 fp32
__device__ __align__(256) h16   g_Ph  [39337984];
__device__ __align__(256) h16   g_vth [16*HDIM*NP];   // V^T per (b,h): [96][1568]
__device__ __align__(256) h16   g_aoh [NTOK*EMBED];
__device__ __align__(256) h16   g_mlph[NTOK*MLPH];
__device__ float g_pool[BATCH*EMBED];
__device__ float g_pln [BATCH*EMBED];
__device__ double g_freq[EMBED/2];
// weights: conv hi+lo (2-term); qkv/out/fc1/fc2 hi only (1-term)
__device__ __align__(256) h16 g_cwh[EMBED*KPATCH];
__device__ __align__(256) h16 g_cwl[EMBED*KPATCH];
__device__ __align__(256) h16 g_qwh[DEPTH*3*EMBED*EMBED];
__device__ __align__(256) h16 g_owh[DEPTH*EMBED*EMBED];
__device__ __align__(256) h16 g_w1h[DEPTH*MLPH*EMBED];
__device__ __align__(256) h16 g_w2h[DEPTH*EMBED*MLPH];

__device__ __forceinline__ void split_f16(float v, h16& h, h16& l)
{
    h = __float2half_rn(v);
    l = __float2half_rn(v - __half2float(h));
}

// ================= GEMM: fp16 split, TERMS in {1,2,3} ======================
// C = A @ B^T (+EPI). A[M,K] k-contig (hi [,lo if TERMS=3]).
// B[N,K] k-contig (hi [,lo if TERMS>=2]). All terms f32-accum:
//   TERMS=1: Ah*Bh   TERMS=2: +Ah*Bl   TERMS=3: +Al*Bh
// Block: 128 x BNT, BK=32. 8 warps = 4m x 2n, warp tile 32 x (BNT/2).
// EPI: 0 none | 1 +bias | 2 +bias,gelu | 4 +bias,+residual
// OUT: 0 fp32 | 1 fp16 hi only | 2 fp16 hi+lo
#define BK 32
#define SA 40           // padded k-stride (elems); conflict-free LDSM

#define LDSM4(R, addr) \
    asm volatile("ldmatrix.sync.aligned.m8n8.x4.shared.b16 {%0,%1,%2,%3},[%4];" \
        : "=r"((R)[0]), "=r"((R)[1]), "=r"((R)[2]), "=r"((R)[3]) : "r"(addr))

#define MMA_F32(C, A, B0, B1) \
    asm volatile("mma.sync.aligned.m16n8k16.row.col.f32.f16.f16.f32 " \
        "{%0,%1,%2,%3},{%4,%5,%6,%7},{%8,%9},{%0,%1,%2,%3};" \
        : "+f"((C)[0]), "+f"((C)[1]), "+f"((C)[2]), "+f"((C)[3]) \
        : "r"((A)[0]), "r"((A)[1]), "r"((A)[2]), "r"((A)[3]), "r"(B0), "r"(B1))

__device__ __forceinline__ void cpa16(uint32_t dst, const void* src, bool p)
{
    int sz = p ? 16 : 0;
    asm volatile("cp.async.cg.shared.global [%0],[%1],16,%2;\n"
                 :: "r"(dst), "l"(src), "r"(sz));
}

template<int EPI, int OUT, int TERMS, int BNT>
__global__ void __launch_bounds__(256)
mma12_gemm(const h16* __restrict__ Agh, const h16* __restrict__ Agl,
           const h16* __restrict__ Bgh, const h16* __restrict__ Bgl,
           const float* __restrict__ bias, const float* __restrict__ R,
           float* __restrict__ Cf, h16* __restrict__ Ch, h16* __restrict__ Cl,
           int M, int N, int K, int lda, int ldb, int ldc, int ldr,
           long long zab, long long zah, long long zbb, long long zbh,
           long long zcb, long long zch, long long zrb, long long zrh, int H)
{
    constexpr int WN    = BNT / 2;
    constexpr int NPR   = WN / 16;
    constexpr int ANB   = (TERMS == 3) ? 2 : 1;
    constexpr int BNB   = (TERMS >= 2) ? 2 : 1;
    constexpr int OFFAL = 128 * SA;
    constexpr int OFFB  = ANB * 128 * SA;
    constexpr int STAGE = (ANB * 128 + BNB * BNT) * SA;

    const int z  = blockIdx.z;
    const int bb = z / H, hh = z % H;
    Agh += bb*zab + hh*zah;
    if (TERMS == 3) Agl += bb*zab + hh*zah;
    Bgh += bb*zbb + hh*zbh;
    if (TERMS >= 2) Bgl += bb*zbb + hh*zbh;
    const long long coff = bb*zcb + hh*zch;
    if (OUT == 0) Cf += coff; else { Ch += coff; if (OUT == 2) Cl += coff; }
    if (EPI >= 3) R += bb*zrb + hh*zrh;

    extern __shared__ __align__(16) h16 smem[];
    const uint32_t su = (uint32_t)__cvta_generic_to_shared(smem);

    const int tid  = threadIdx.x;
    const int lane = tid & 31;
    const int w    = tid >> 5;
    const int wm   = w >> 1;
    const int wn   = w & 1;
    const int m0   = blockIdx.y * 128;
    const int n0   = blockIdx.x * BNT;

    float c[2][2*NPR][4];
    #pragma unroll
    for (int i = 0; i < 2; i++)
        #pragma unroll
        for (int j = 0; j < 2*NPR; j++)
            #pragma unroll
            for (int q = 0; q < 4; q++) c[i][j][q] = 0.f;

    const int lrow = lane & 15;
    const int lcol = (lane >> 4) * 8;
    const uint32_t aoffA = (uint32_t)(((wm*32 + lrow)*SA + lcol) * 2);
    const uint32_t boffB = (uint32_t)(((wn*WN + lrow)*SA + lcol) * 2);

    const int T = K / BK;

    auto issue = [&](int t, int s) {
        const int k0 = t * BK;
        const uint32_t sb = su + (uint32_t)(s * STAGE) * 2u;
        #pragma unroll
        for (int i = 0; i < 2*ANB; i++) {             // A: exactly ANB*128*4 chunks
            const int hl  = i >> 1;
            const int ch  = ((i & 1) << 8) + tid;
            const int row = ch >> 2;
            const int kc  = (ch & 3) << 3;
            const bool p  = (m0 + row) < M;
            const h16* src = (hl ? Agl : Agh)
                           + (long long)(p ? (m0 + row) : 0) * lda + k0 + kc;
            cpa16(sb + (uint32_t)((hl ? OFFAL : 0) + row*SA + kc) * 2u, src, p);
        }
        // B: BNB*BNT*4 total 16B chunks (may not divide 256 evenly -> guard)
        constexpr int BTOT = BNB * BNT * 4;
        constexpr int BCH  = (BTOT + 255) / 256;
        #pragma unroll
        for (int i = 0; i < BCH; i++) {
            const int ch = i*256 + tid;
            if (BTOT % 256 != 0 && ch >= BTOT) break;
            const int hl  = ch / (BNT*4);
            const int rem = ch % (BNT*4);
            const int row = rem >> 2;
            const int kc  = (rem & 3) << 3;
            const bool p  = (n0 + row) < N;
            const h16* src = (hl ? Bgl : Bgh)
                           + (long long)(p ? (n0 + row) : 0) * ldb + k0 + kc;
            cpa16(sb + (uint32_t)(OFFB + hl*BNT*SA + row*SA + kc) * 2u, src, p);
        }
    };

    issue(0, 0);
    asm volatile("cp.async.commit_group;");
    if (T > 1) { issue(1, 1); asm volatile("cp.async.commit_group;"); }

    for (int t = 0; t < T; t++) {
        if (t + 1 < T) asm volatile("cp.async.wait_group 1;");
        else           asm volatile("cp.async.wait_group 0;");
        __syncthreads();

        if (t + 2 < T) {
            issue(t + 2, (t + 2) % 3);
            asm volatile("cp.async.commit_group;");
        }

        const int s = t % 3;
        const uint32_t sb  = su + (uint32_t)(s * STAGE) * 2u;
        const uint32_t aHb = sb + aoffA;
        const uint32_t aLb = aHb + (uint32_t)OFFAL * 2u;
        const uint32_t bHb = sb + (uint32_t)OFFB * 2u + boffB;
        const uint32_t bLb = bHb + (uint32_t)(BNT*SA) * 2u;

        #pragma unroll
        for (int kk2 = 0; kk2 < 2; kk2++) {
            const uint32_t kb = (uint32_t)(kk2 * 32);
            uint32_t Ahf[2][4], Alf[2][4], Bhf[NPR][4], Blf[NPR][4];
            #pragma unroll
            for (int mi = 0; mi < 2; mi++) {
                LDSM4(Ahf[mi], aHb + (uint32_t)(mi*16*SA*2) + kb);
                if (TERMS == 3)
                    LDSM4(Alf[mi], aLb + (uint32_t)(mi*16*SA*2) + kb);
            }
            #pragma unroll
            for (int pr = 0; pr < NPR; pr++) {
                LDSM4(Bhf[pr], bHb + (uint32_t)(pr*16*SA*2) + kb);
                if (TERMS >= 2)
                    LDSM4(Blf[pr], bLb + (uint32_t)(pr*16*SA*2) + kb);
            }
            #pragma unroll
            for (int mi = 0; mi < 2; mi++) {
                #pragma unroll
                for (int pr = 0; pr < NPR; pr++) {
                    MMA_F32(c[mi][2*pr  ], Ahf[mi], Bhf[pr][0], Bhf[pr][2]);
                    MMA_F32(c[mi][2*pr+1], Ahf[mi], Bhf[pr][1], Bhf[pr][3]);
                    if (TERMS >= 2) {
                        MMA_F32(c[mi][2*pr  ], Ahf[mi], Blf[pr][0], Blf[pr][2]);
                        MMA_F32(c[mi][2*pr+1], Ahf[mi], Blf[pr][1], Blf[pr][3]);
                    }
                    if (TERMS == 3) {
                        MMA_F32(c[mi][2*pr  ], Alf[mi], Bhf[pr][0], Bhf[pr][2]);
                        MMA_F32(c[mi][2*pr+1], Alf[mi], Bhf[pr][1], Bhf[pr][3]);
                    }
                }
            }
        }
    }

    // ---------------- epilogue ----------------
    const int g  = lane >> 2;
    const int tq = lane & 3;
    #pragma unroll
    for (int mi = 0; mi < 2; mi++) {
        #pragma unroll
        for (int nf = 0; nf < 2*NPR; nf++) {
            int col = n0 + wn*WN + nf*8 + tq*2;
            #pragma unroll
            for (int half = 0; half < 2; half++) {
                int row = m0 + wm*32 + mi*16 + g + half*8;
                if (row >= M || col >= N) continue;
                float v0 = c[mi][nf][half*2 + 0];
                float v1 = c[mi][nf][half*2 + 1];
                if (EPI == 1 || EPI == 2 || EPI == 4) { v0 += bias[col]; v1 += bias[col+1]; }
                if (EPI == 2) {
                    v0 = 0.5f * v0 * (1.0f + erff(v0 * 0.70710678118654752f));
                    v1 = 0.5f * v1 * (1.0f + erff(v1 * 0.70710678118654752f));
                }
                if (EPI >= 3) {
                    float2 r2 = *(const float2*)&R[(long long)row*ldr + col];
                    v0 += r2.x; v1 += r2.y;
                }
                if (OUT == 0) {
                    float2 o; o.x = v0; o.y = v1;
                    *(float2*)&Cf[(long long)row*ldc + col] = o;
                } else if (OUT == 1) {
                    *(__half2*)&Ch[(long long)row*ldc + col] =
                        __halves2half2(__float2half_rn(v0), __float2half_rn(v1));
                } else {
                    h16 h0,h1,l0,l1;
                    split_f16(v0,h0,l0); split_f16(v1,h1,l1);
                    *(__half2*)&Ch[(long long)row*ldc + col] = __halves2half2(h0,h1);
                    *(__half2*)&Cl[(long long)row*ldc + col] = __halves2half2(l0,l1);
                }
            }
        }
    }
}

// ---------------- V transpose (hi only): VT[z][n][k] = V[z][k][n] ----------
__global__ void vtrans_kernel(const h16* __restrict__ qh, h16* __restrict__ vth)
{
    __shared__ h16 th[32][100];
    const int z = blockIdx.y, bb = z >> 3, hh = z & 7;
    const int k0 = blockIdx.x * 32;
    const int tid = threadIdx.x;
    const h16* sh = qh + ((long long)(bb*NP) + k0)*(3*EMBED) + 2*EMBED + hh*HDIM;
    for (int idx = tid; idx < 32*HDIM; idx += 256) {
        int kk = idx / HDIM, nn = idx % HDIM;
        th[kk][nn] = sh[(long long)kk*(3*EMBED) + nn];
    }
    __syncthreads();
    h16* dh = vth + (long long)z*HDIM*NP + k0;
    for (int idx = tid; idx < 32*HDIM; idx += 256) {
        int nn = idx >> 5, kk = idx & 31;
        dh[(long long)nn*NP + kk] = th[kk][nn];
    }
}

// ---------------- fp32 -> fp16 hi/lo split (conv weight) ----------------
__global__ void split_kernel(const float* __restrict__ s, h16* __restrict__ h,
                             h16* __restrict__ l, long long n)
{
    long long i = ((long long)blockIdx.x*256 + threadIdx.x)*4;
    if (i >= n) return;
    float4 v = *(const float4*)&s[i];
    h16 h0,h1,h2,h3,l0,l1,l2,l3;
    split_f16(v.x,h0,l0); split_f16(v.y,h1,l1);
    split_f16(v.z,h2,l2); split_f16(v.w,h3,l3);
    *(__half2*)&h[i  ] = __halves2half2(h0,h1);
    *(__half2*)&h[i+2] = __halves2half2(h2,h3);
    *(__half2*)&l[i  ] = __halves2half2(l0,l1);
    *(__half2*)&l[i+2] = __halves2half2(l2,l3);
}

// ---------------- fp32 -> fp16 convert (hi only) ----------
__global__ void tohalf_kernel(const float* __restrict__ s, h16* __restrict__ h,
                              long long n)
{
    long long i = ((long long)blockIdx.x*256 + threadIdx.x)*4;
    if (i >= n) return;
    float4 v = *(const float4*)&s[i];
    *(__half2*)&h[i  ] = __halves2half2(__float2half_rn(v.x), __float2half_rn(v.y));
    *(__half2*)&h[i+2] = __halves2half2(__float2half_rn(v.z), __float2half_rn(v.w));
}

// ---------------- layernorm (fp32 out OR fp16-hi out) ----------------
__global__ void ln_kernel(const float* __restrict__ X, const float* __restrict__ sc,
                          const float* __restrict__ bi, float* __restrict__ Yf,
                          h16* __restrict__ Yh, int Cn)
{
    const float* x = X + (long long)blockIdx.x * Cn;
    __shared__ float sh1[32], sh2[32];
    int tid = threadIdx.x;
    float s = 0.f, s2 = 0.f;
    for (int i = tid; i < Cn; i += 256) { float v = x[i]; s += v; s2 += v*v; }
    #pragma unroll
    for (int o = 16; o > 0; o >>= 1) {
        s  += __shfl_xor_sync(0xffffffffu, s,  o);
        s2 += __shfl_xor_sync(0xffffffffu, s2, o);
    }
    if ((tid & 31) == 0) { sh1[tid>>5] = s; sh2[tid>>5] = s2; }
    __syncthreads();
    if (tid < 32) {
        float a = (tid < 8) ? sh1[tid] : 0.f;
        float b = (tid < 8) ? sh2[tid] : 0.f;
        #pragma unroll
        for (int o = 4; o > 0; o >>= 1) {
            a += __shfl_xor_sync(0xffffffffu, a, o);
            b += __shfl_xor_sync(0xffffffffu, b, o);
        }
        if (tid == 0) { sh1[0] = a; sh2[0] = b; }
    }
    __syncthreads();
    float mean = sh1[0] / Cn;
    float var  = sh2[0] / Cn - mean*mean;
    float inv  = rsqrtf(var + 1e-5f);
    for (int i = tid; i < Cn; i += 256) {
        float v = (x[i] - mean) * inv * sc[i] + bi[i];
        if (Yf) Yf[(long long)blockIdx.x*Cn + i] = v;
        else    Yh[(long long)blockIdx.x*Cn + i] = __float2half_rn(v);
    }
}

// ---------------- softmax: max-stabilized, __expf, one gmem read ----------
__global__ void softmax_kernel(const float* __restrict__ S, h16* __restrict__ Ph)
{
    const float* p = S + (long long)blockIdx.x * NP;
    h16* ph = Ph + (long long)blockIdx.x * NP;
    __shared__ float sh[32];
    int tid = threadIdx.x;
    const int IT = (NP + 255) / 256;   // 7
    float vals[(NP + 255) / 256];
    float mx = -1e30f;
    #pragma unroll
    for (int it = 0; it < IT; it++) {
        int i = tid + it*256;
        float v = (i < NP) ? p[i] : -1e30f;
        vals[it] = v;
        mx = fmaxf(mx, v);
    }
    #pragma unroll
    for (int o = 16; o > 0; o >>= 1) mx = fmaxf(mx, __shfl_xor_sync(0xffffffffu, mx, o));
    if ((tid & 31) == 0) sh[tid>>5] = mx;
    __syncthreads();
    if (tid < 32) {
        float v = (tid < 8) ? sh[tid] : -1e30f;
        #pragma unroll
        for (int o = 4; o > 0; o >>= 1) v = fmaxf(v, __shfl_xor_sync(0xffffffffu, v, o));
        if (tid == 0) sh[0] = v;
    }
    __syncthreads();
    mx = sh[0];
    __syncthreads();
    float sum = 0.f;
    #pragma unroll
    for (int it = 0; it < IT; it++) {
        int i = tid + it*256;
        float e = (i < NP) ? __expf(vals[it] - mx) : 0.f;   // arg <= 0: safe
        vals[it] = e;
        sum += e;
    }
    #pragma unroll
    for (int o = 16; o > 0; o >>= 1) sum += __shfl_xor_sync(0xffffffffu, sum, o);
    if ((tid & 31) == 0) sh[tid>>5] = sum;
    __syncthreads();
    if (tid < 32) {
        float v = (tid < 8) ? sh[tid] : 0.f;
        #pragma unroll
        for (int o = 4; o > 0; o >>= 1) v += __shfl_xor_sync(0xffffffffu, v, o);
        if (tid == 0) sh[0] = v;
    }
    __syncthreads();
    float inv = 1.0f / sh[0];
    #pragma unroll
    for (int it = 0; it < IT; it++) {
        int i = tid + it*256;
        if (i < NP) ph[i] = __float2half_rn(vals[it] * inv);
    }
}

// ---------------- im2col (writes fp16 hi only) ----------------
__global__ void im2col_kernel(const float* __restrict__ x)
{
    long long idx = (long long)blockIdx.x * 256 + threadIdx.x;
    if (idx >= (long long)NTOK * KPATCH) return;
    int j = (int)(idx % KPATCH);
    int m = (int)(idx / KPATCH);
    int b = m / NP, n = m % NP;
    int t = n / 196, r = n % 196, yy = r / 14, xx = r % 14;
    int i  = j / 512, r2 = j % 512;
    int dt = r2 / 256, r3 = r2 % 256;
    int dy = r3 / 16,  dx = r3 % 16;
    long long off = ((((long long)(b*3 + i)*16 + (2*t + dt))*224) + (16*yy + dy))*224 + (16*xx + dx);
    g_imh[idx] = __float2half_rn(x[off]);
}

// ---------------- positional encoding ----------------
__global__ void freq_kernel()
{
    int c2 = threadIdx.x;
    if (c2 < EMBED/2) g_freq[c2] = pow(10000.0, -2.0 * c2 / (double)EMBED);
}
__global__ void posadd_kernel()
{
    int idx = blockIdx.x * 256 + threadIdx.x;
    if (idx >= NP*EMBED) return;
    int n = idx / EMBED, c = idx % EMBED;
    double a = (double)n * g_freq[c >> 1];
    const double TWO_PI = 6.283185307179586476925286766559;
    int k = (int)(a * (1.0 / TWO_PI) + 0.5);
    float rf = (float)(a - (double)k * TWO_PI);
    float v = (c & 1) ? cosf(rf) : sinf(rf);
    g_h[idx]            += v;
    g_h[idx + NP*EMBED] += v;
}

// ---------------- mean pool: coalesced block reduce ----------------
__global__ void pool_kernel()
{
    __shared__ float acc[2][128];
    const int b  = blockIdx.y;
    const int c0 = blockIdx.x * 128;
    const int tg = threadIdx.x >> 7;
    const int c  = threadIdx.x & 127;
    const float* base = g_h + (long long)b*NP*EMBED + c0 + c;
    float s = 0.f;
    for (int n = tg; n < NP; n += 2)
        s += base[(long long)n*EMBED];
    acc[tg][c] = s;
    __syncthreads();
    if (tg == 0)
        g_pool[b*EMBED + c0 + c] = (acc[0][c] + acc[1][c]) * (1.0f / NP);
}

// ---------------- classifier head ----------------
__global__ void head_kernel(const float* __restrict__ W, const float* __restrict__ hb,
                            float* __restrict__ out)
{
    int g = blockIdx.x * 256 + threadIdx.x;
    int warp = g >> 5, lane = g & 31;
    if (warp >= BATCH*1000) return;
    int b = warp / 1000, j = warp % 1000;
    float s = 0.f;
    for (int c = lane; c < EMBED; c += 32)
        s += g_pln[b*EMBED + c] * W[j*EMBED + c];
    #pragma unroll
    for (int o = 16; o > 0; o >>= 1) s += __shfl_xor_sync(0xffffffffu, s, o);
    if (lane == 0) out[warp] = s + hb[j];
}

// ---------------- host orchestration ----------------
#define DSZ(anb,bnb,bnt) (((anb)*128 + (bnb)*(bnt))*SA*2*3)

extern "C" void kernel_launch(void* const* d_in, const int* in_sizes, int n_in,
                              void* d_out, int out_size)
{
    const float* x      = (const float*)d_in[0];
    const float* conv_w = (const float*)d_in[1];
    const float* conv_b = (const float*)d_in[2];
    const float* n1s    = (const float*)d_in[3];
    const float* n1b    = (const float*)d_in[4];
    const float* qkv_w  = (const float*)d_in[5];
    const float* out_w  = (const float*)d_in[6];
    const float* out_b  = (const float*)d_in[7];
    const float* n2s    = (const float*)d_in[8];
    const float* n2b    = (const float*)d_in[9];
    const float* fc1_w  = (const float*)d_in[10];
    const float* fc1_b  = (const float*)d_in[11];
    const float* fc2_w  = (const float*)d_in[12];
    const float* fc2_b  = (const float*)d_in[13];
    const float* fns    = (const float*)d_in[14];
    const float* fnb    = (const float*)d_in[15];
    const float* head_w = (const float*)d_in[16];
    const float* head_b = (const float*)d_in[17];
    float* out = (float*)d_out;

    float *h, *attn, *pool, *pln;
    h16 *imh,*yh,*qkvh,*qkvl,*Ph,*vth,*aoh,*mlph;
    h16 *cwh,*cwl,*qwh,*owh,*w1h,*w2h;
    cudaGetSymbolAddress((void**)&h,    g_h);
    cudaGetSymbolAddress((void**)&attn, g_attn);
    cudaGetSymbolAddress((void**)&pool, g_pool);
    cudaGetSymbolAddress((void**)&pln,  g_pln);
    cudaGetSymbolAddress((void**)&imh,  g_imh);
    cudaGetSymbolAddress((void**)&yh,   g_yh);
    cudaGetSymbolAddress((void**)&qkvh, g_qkvh);  cudaGetSymbolAddress((void**)&qkvl,g_qkvl);
    cudaGetSymbolAddress((void**)&Ph,   g_Ph);
    cudaGetSymbolAddress((void**)&vth,  g_vth);
    cudaGetSymbolAddress((void**)&aoh,  g_aoh);
    cudaGetSymbolAddress((void**)&mlph, g_mlph);
    cudaGetSymbolAddress((void**)&cwh,  g_cwh);   cudaGetSymbolAddress((void**)&cwl, g_cwl);
    cudaGetSymbolAddress((void**)&qwh,  g_qwh);
    cudaGetSymbolAddress((void**)&owh,  g_owh);
    cudaGetSymbolAddress((void**)&w1h,  g_w1h);
    cudaGetSymbolAddress((void**)&w2h,  g_w2h);

    cudaFuncSetAttribute(mma12_gemm<1,0,2,64 >, cudaFuncAttributeMaxDynamicSharedMemorySize, DSZ(1,2,64));
    cudaFuncSetAttribute(mma12_gemm<0,2,1,128>, cudaFuncAttributeMaxDynamicSharedMemorySize, DSZ(1,1,128));
    cudaFuncSetAttribute(mma12_gemm<0,0,2,128>, cudaFuncAttributeMaxDynamicSharedMemorySize, DSZ(1,2,128));
    cudaFuncSetAttribute(mma12_gemm<0,1,1,96 >, cudaFuncAttributeMaxDynamicSharedMemorySize, DSZ(1,1,96));
    cudaFuncSetAttribute(mma12_gemm<4,0,1,64 >, cudaFuncAttributeMaxDynamicSharedMemorySize, DSZ(1,1,64));
    cudaFuncSetAttribute(mma12_gemm<2,1,1,128>, cudaFuncAttributeMaxDynamicSharedMemorySize, DSZ(1,1,128));

    const long long Z0 = 0;

    // ---- weight prep ----
    {
        long long n;
        n = (long long)EMBED*KPATCH;
        split_kernel<<<(int)((n/4+255)/256),256>>>(conv_w, cwh, cwl, n);
        n = (long long)DEPTH*3*EMBED*EMBED;
        tohalf_kernel<<<(int)((n/4+255)/256),256>>>(qkv_w, qwh, n);
        n = (long long)DEPTH*EMBED*EMBED;
        tohalf_kernel<<<(int)((n/4+255)/256),256>>>(out_w, owh, n);
        n = (long long)DEPTH*MLPH*EMBED;
        tohalf_kernel<<<(int)((n/4+255)/256),256>>>(fc1_w, w1h, n);
        n = (long long)DEPTH*EMBED*MLPH;
        tohalf_kernel<<<(int)((n/4+255)/256),256>>>(fc2_w, w2h, n);
    }

    // ---- patch embed ----
    im2col_kernel<<<(int)(((long long)NTOK*KPATCH + 255)/256), 256>>>(x);
    {
        dim3 g(EMBED/64, (NTOK+127)/128, 1);
        mma12_gemm<1,0,2,64><<<g,256,DSZ(1,2,64)>>>(
            imh, nullptr, cwh, cwl, conv_b, nullptr, h, nullptr, nullptr,
            NTOK, EMBED, KPATCH, KPATCH, KPATCH, EMBED, 0,
            Z0,Z0,Z0,Z0,Z0,Z0,Z0,Z0, 1);
    }
    freq_kernel<<<1, EMBED/2>>>();
    posadd_kernel<<<(NP*EMBED + 255)/256, 256>>>();

    // ---- transformer blocks ----
    for (int l = 0; l < DEPTH; l++) {
        h16* lqwh = qwh + (long long)l*3*EMBED*EMBED;
        h16* lowh = owh + (long long)l*EMBED*EMBED;
        h16* lw1h = w1h + (long long)l*MLPH*EMBED;
        h16* lw2h = w2h + (long long)l*EMBED*MLPH;
        const float* ob = out_b + (long long)l*EMBED;
        const float* b1 = fc1_b + (long long)l*MLPH;
        const float* b2 = fc2_b + (long long)l*EMBED;

        // y = LN1(h) -> fp16 hi
        ln_kernel<<<NTOK,256>>>(h, n1s + l*EMBED, n1b + l*EMBED, nullptr, yh, EMBED);

        {   // qkv = y @ qw^T  (1-term) -> fp16 hi+lo (K lo used by 2-term QK)
            dim3 g((3*EMBED)/128, (NTOK+127)/128, 1);
            mma12_gemm<0,2,1,128><<<g,256,DSZ(1,1,128)>>>(
                yh, nullptr, lqwh, nullptr, nullptr, nullptr, nullptr, qkvh, qkvl,
                NTOK, 3*EMBED, EMBED, EMBED, EMBED, 3*EMBED, 0,
                Z0,Z0,Z0,Z0,Z0,Z0,Z0,Z0, 1);
        }

        {   // V^T per (b,h), hi only
            dim3 g(NP/32, BATCH*HEADS, 1);
            vtrans_kernel<<<g,256>>>(qkvh, vth);
        }

        {   // S = Q @ K^T  fp32 (2-term: Qh*Kh + Qh*Kl; Ql*Kh dropped)
            dim3 g((NP+127)/128, (NP+127)/128, BATCH*HEADS);
            mma12_gemm<0,0,2,128><<<g,256,DSZ(1,2,128)>>>(
                qkvh, nullptr, qkvh + EMBED, qkvl + EMBED, nullptr, nullptr,
                attn, nullptr, nullptr,
                NP, NP, HDIM, 3*EMBED, 3*EMBED, NP, 0,
                (long long)NP*3*EMBED, (long long)HDIM,
                (long long)NP*3*EMBED, (long long)HDIM,
                (long long)HEADS*NP*NP, (long long)NP*NP,
                Z0, Z0, HEADS);
        }

        softmax_kernel<<<BATCH*HEADS*NP, 256>>>(attn, Ph);

        {   // ao = P @ VT^T  (1-term) -> fp16 hi (N=96)
            dim3 g(1, (NP+127)/128, BATCH*HEADS);
            mma12_gemm<0,1,1,96><<<g,256,DSZ(1,1,96)>>>(
                Ph, nullptr, vth, nullptr, nullptr, nullptr, nullptr, aoh, nullptr,
                NP, HDIM, NP, NP, NP, EMBED, 0,
                (long long)HEADS*NP*NP, (long long)NP*NP,
                (long long)HEADS*HDIM*NP, (long long)HDIM*NP,
                (long long)NP*EMBED, (long long)HDIM,
                Z0, Z0, HEADS);
        }

        {   // h = h + ao @ ow^T + ob  (1-term)
            dim3 g(EMBED/64, (NTOK+127)/128, 1);
            mma12_gemm<4,0,1,64><<<g,256,DSZ(1,1,64)>>>(
                aoh, nullptr, lowh, nullptr, ob, h, h, nullptr, nullptr,
                NTOK, EMBED, EMBED, EMBED, EMBED, EMBED, EMBED,
                Z0,Z0,Z0,Z0,Z0,Z0,Z0,Z0, 1);
        }

        // y = LN2(h) -> fp16 hi
        ln_kernel<<<NTOK,256>>>(h, n2s + l*EMBED, n2b + l*EMBED, nullptr, yh, EMBED);

        {   // mlp = gelu(y @ w1^T + b1)  (1-term) -> fp16 hi
            dim3 g(MLPH/128, (NTOK+127)/128, 1);
            mma12_gemm<2,1,1,128><<<g,256,DSZ(1,1,128)>>>(
                yh, nullptr, lw1h, nullptr, b1, nullptr, nullptr, mlph, nullptr,
                NTOK, MLPH, EMBED, EMBED, EMBED, MLPH, 0,
                Z0,Z0,Z0,Z0,Z0,Z0,Z0,Z0, 1);
        }

        {   // h = h + mlp @ w2^T + b2  (1-term)
            dim3 g(EMBED/64, (NTOK+127)/128, 1);
            mma12_gemm<4,0,1,64><<<g,256,DSZ(1,1,64)>>>(
                mlph, nullptr, lw2h, nullptr, b2, h, h, nullptr, nullptr,
                NTOK, EMBED, MLPH, MLPH, MLPH, EMBED, EMBED,
                Z0,Z0,Z0,Z0,Z0,Z0,Z0,Z0, 1);
        }
    }

    // ---- pooled head ----
    {
        dim3 g(EMBED/128, BATCH);
        pool_kernel<<<g,256>>>();
    }
    ln_kernel<<<BATCH,256>>>(pool, fns, fnb, pln, nullptr, EMBED);
    head_kernel<<<(BATCH*1000*32 + 255)/256, 256>>>(head_w, head_b, out);
}

// round 13
// speedup vs baseline: 2.3326x; 1.0584x over previous
#include <cuda_runtime.h>
#include <cuda_fp16.h>
#include <math.h>
#include <stdint.h>

#define EMBED   768
#define HEADS   8
#define HDIM    96
#define DEPTH   12
#define MLPH    3072
#define NP      1568
#define BATCH   2
#define NTOK    (BATCH*NP)      // 3136
#define KPATCH  1536

typedef __half h16;

// ---------------- scratch (device globals: allocation-free) ----------------
__device__ __align__(256) h16   g_imh [NTOK*KPATCH];
__device__ __align__(256) float g_h   [NTOK*EMBED];
__device__ __align__(256) h16   g_yh  [NTOK*EMBED];
__device__ __align__(256) h16   g_qkvh[NTOK*3*EMBED];
__device__ __align__(256) float g_attn[39337984];     // 2*8*1568^2 fp32
__device__ __align__(256) h16   g_Ph  [39337984];
__device__ __align__(256) h16   g_vth [16*HDIM*NP];   // V^T per (b,h): [96][1568]
__device__ __align__(256) h16   g_aoh [NTOK*EMBED];
__device__ __align__(256) h16   g_mlph[NTOK*MLPH];
__device__ float g_pool[BATCH*EMBED];
__device__ float g_pln [BATCH*EMBED];
__device__ double g_freq[EMBED/2];
// weights: conv hi+lo (2-term); qkv/out/fc1/fc2 hi only (1-term)
__device__ __align__(256) h16 g_cwh[EMBED*KPATCH];
__device__ __align__(256) h16 g_cwl[EMBED*KPATCH];
__device__ __align__(256) h16 g_qwh[DEPTH*3*EMBED*EMBED];
__device__ __align__(256) h16 g_owh[DEPTH*EMBED*EMBED];
__device__ __align__(256) h16 g_w1h[DEPTH*MLPH*EMBED];
__device__ __align__(256) h16 g_w2h[DEPTH*EMBED*MLPH];

__device__ __forceinline__ void split_f16(float v, h16& h, h16& l)
{
    h = __float2half_rn(v);
    l = __float2half_rn(v - __half2float(h));
}

// ================= GEMM: fp16 split, TERMS in {1,2,3} ======================
// C = A @ B^T (+EPI). A[M,K] k-contig (hi [,lo if TERMS=3]).
// B[N,K] k-contig (hi [,lo if TERMS>=2]). All terms f32-accum:
//   TERMS=1: Ah*Bh   TERMS=2: +Ah*Bl   TERMS=3: +Al*Bh
// Block: 128 x BNT, BK=32. 8 warps = 4m x 2n, warp tile 32 x (BNT/2).
// EPI: 0 none | 1 +bias | 2 +bias,gelu | 4 +bias,+residual
// OUT: 0 fp32 | 1 fp16 hi only | 2 fp16 hi+lo
#define BK 32
#define SA 40           // padded k-stride (elems); conflict-free LDSM

#define LDSM4(R, addr) \
    asm volatile("ldmatrix.sync.aligned.m8n8.x4.shared.b16 {%0,%1,%2,%3},[%4];" \
        : "=r"((R)[0]), "=r"((R)[1]), "=r"((R)[2]), "=r"((R)[3]) : "r"(addr))

#define MMA_F32(C, A, B0, B1) \
    asm volatile("mma.sync.aligned.m16n8k16.row.col.f32.f16.f16.f32 " \
        "{%0,%1,%2,%3},{%4,%5,%6,%7},{%8,%9},{%0,%1,%2,%3};" \
        : "+f"((C)[0]), "+f"((C)[1]), "+f"((C)[2]), "+f"((C)[3]) \
        : "r"((A)[0]), "r"((A)[1]), "r"((A)[2]), "r"((A)[3]), "r"(B0), "r"(B1))

__device__ __forceinline__ void cpa16(uint32_t dst, const void* src, bool p)
{
    int sz = p ? 16 : 0;
    asm volatile("cp.async.cg.shared.global [%0],[%1],16,%2;\n"
                 :: "r"(dst), "l"(src), "r"(sz));
}

template<int EPI, int OUT, int TERMS, int BNT>
__global__ void __launch_bounds__(256)
mma13_gemm(const h16* __restrict__ Agh, const h16* __restrict__ Agl,
           const h16* __restrict__ Bgh, const h16* __restrict__ Bgl,
           const float* __restrict__ bias, const float* __restrict__ R,
           float* __restrict__ Cf, h16* __restrict__ Ch, h16* __restrict__ Cl,
           int M, int N, int K, int lda, int ldb, int ldc, int ldr,
           long long zab, long long zah, long long zbb, long long zbh,
           long long zcb, long long zch, long long zrb, long long zrh, int H)
{
    constexpr int WN    = BNT / 2;
    constexpr int NPR   = WN / 16;
    constexpr int ANB   = (TERMS == 3) ? 2 : 1;
    constexpr int BNB   = (TERMS >= 2) ? 2 : 1;
    constexpr int OFFAL = 128 * SA;
    constexpr int OFFB  = ANB * 128 * SA;
    constexpr int STAGE = (ANB * 128 + BNB * BNT) * SA;

    const int z  = blockIdx.z;
    const int bb = z / H, hh = z % H;
    Agh += bb*zab + hh*zah;
    if (TERMS == 3) Agl += bb*zab + hh*zah;
    Bgh += bb*zbb + hh*zbh;
    if (TERMS >= 2) Bgl += bb*zbb + hh*zbh;
    const long long coff = bb*zcb + hh*zch;
    if (OUT == 0) Cf += coff; else { Ch += coff; if (OUT == 2) Cl += coff; }
    if (EPI >= 3) R += bb*zrb + hh*zrh;

    extern __shared__ __align__(16) h16 smem[];
    const uint32_t su = (uint32_t)__cvta_generic_to_shared(smem);

    const int tid  = threadIdx.x;
    const int lane = tid & 31;
    const int w    = tid >> 5;
    const int wm   = w >> 1;
    const int wn   = w & 1;
    const int m0   = blockIdx.y * 128;
    const int n0   = blockIdx.x * BNT;

    float c[2][2*NPR][4];
    #pragma unroll
    for (int i = 0; i < 2; i++)
        #pragma unroll
        for (int j = 0; j < 2*NPR; j++)
            #pragma unroll
            for (int q = 0; q < 4; q++) c[i][j][q] = 0.f;

    const int lrow = lane & 15;
    const int lcol = (lane >> 4) * 8;
    const uint32_t aoffA = (uint32_t)(((wm*32 + lrow)*SA + lcol) * 2);
    const uint32_t boffB = (uint32_t)(((wn*WN + lrow)*SA + lcol) * 2);

    const int T = K / BK;

    auto issue = [&](int t, int s) {
        const int k0 = t * BK;
        const uint32_t sb = su + (uint32_t)(s * STAGE) * 2u;
        #pragma unroll
        for (int i = 0; i < 2*ANB; i++) {             // A: exactly ANB*128*4 chunks
            const int hl  = i >> 1;
            const int ch  = ((i & 1) << 8) + tid;
            const int row = ch >> 2;
            const int kc  = (ch & 3) << 3;
            const bool p  = (m0 + row) < M;
            const h16* src = (hl ? Agl : Agh)
                           + (long long)(p ? (m0 + row) : 0) * lda + k0 + kc;
            cpa16(sb + (uint32_t)((hl ? OFFAL : 0) + row*SA + kc) * 2u, src, p);
        }
        // B: BNB*BNT*4 total 16B chunks (may not divide 256 evenly -> guard)
        constexpr int BTOT = BNB * BNT * 4;
        constexpr int BCH  = (BTOT + 255) / 256;
        #pragma unroll
        for (int i = 0; i < BCH; i++) {
            const int ch = i*256 + tid;
            if (BTOT % 256 != 0 && ch >= BTOT) break;
            const int hl  = ch / (BNT*4);
            const int rem = ch % (BNT*4);
            const int row = rem >> 2;
            const int kc  = (rem & 3) << 3;
            const bool p  = (n0 + row) < N;
            const h16* src = (hl ? Bgl : Bgh)
                           + (long long)(p ? (n0 + row) : 0) * ldb + k0 + kc;
            cpa16(sb + (uint32_t)(OFFB + hl*BNT*SA + row*SA + kc) * 2u, src, p);
        }
    };

    issue(0, 0);
    asm volatile("cp.async.commit_group;");
    if (T > 1) { issue(1, 1); asm volatile("cp.async.commit_group;"); }

    for (int t = 0; t < T; t++) {
        if (t + 1 < T) asm volatile("cp.async.wait_group 1;");
        else           asm volatile("cp.async.wait_group 0;");
        __syncthreads();

        if (t + 2 < T) {
            issue(t + 2, (t + 2) % 3);
            asm volatile("cp.async.commit_group;");
        }

        const int s = t % 3;
        const uint32_t sb  = su + (uint32_t)(s * STAGE) * 2u;
        const uint32_t aHb = sb + aoffA;
        const uint32_t aLb = aHb + (uint32_t)OFFAL * 2u;
        const uint32_t bHb = sb + (uint32_t)OFFB * 2u + boffB;
        const uint32_t bLb = bHb + (uint32_t)(BNT*SA) * 2u;

        #pragma unroll
        for (int kk2 = 0; kk2 < 2; kk2++) {
            const uint32_t kb = (uint32_t)(kk2 * 32);
            uint32_t Ahf[2][4], Alf[2][4], Bhf[NPR][4], Blf[NPR][4];
            #pragma unroll
            for (int mi = 0; mi < 2; mi++) {
                LDSM4(Ahf[mi], aHb + (uint32_t)(mi*16*SA*2) + kb);
                if (TERMS == 3)
                    LDSM4(Alf[mi], aLb + (uint32_t)(mi*16*SA*2) + kb);
            }
            #pragma unroll
            for (int pr = 0; pr < NPR; pr++) {
                LDSM4(Bhf[pr], bHb + (uint32_t)(pr*16*SA*2) + kb);
                if (TERMS >= 2)
                    LDSM4(Blf[pr], bLb + (uint32_t)(pr*16*SA*2) + kb);
            }
            #pragma unroll
            for (int mi = 0; mi < 2; mi++) {
                #pragma unroll
                for (int pr = 0; pr < NPR; pr++) {
                    MMA_F32(c[mi][2*pr  ], Ahf[mi], Bhf[pr][0], Bhf[pr][2]);
                    MMA_F32(c[mi][2*pr+1], Ahf[mi], Bhf[pr][1], Bhf[pr][3]);
                    if (TERMS >= 2) {
                        MMA_F32(c[mi][2*pr  ], Ahf[mi], Blf[pr][0], Blf[pr][2]);
                        MMA_F32(c[mi][2*pr+1], Ahf[mi], Blf[pr][1], Blf[pr][3]);
                    }
                    if (TERMS == 3) {
                        MMA_F32(c[mi][2*pr  ], Alf[mi], Bhf[pr][0], Bhf[pr][2]);
                        MMA_F32(c[mi][2*pr+1], Alf[mi], Bhf[pr][1], Bhf[pr][3]);
                    }
                }
            }
        }
    }

    // ---------------- epilogue ----------------
    const int g  = lane >> 2;
    const int tq = lane & 3;
    #pragma unroll
    for (int mi = 0; mi < 2; mi++) {
        #pragma unroll
        for (int nf = 0; nf < 2*NPR; nf++) {
            int col = n0 + wn*WN + nf*8 + tq*2;
            #pragma unroll
            for (int half = 0; half < 2; half++) {
                int row = m0 + wm*32 + mi*16 + g + half*8;
                if (row >= M || col >= N) continue;
                float v0 = c[mi][nf][half*2 + 0];
                float v1 = c[mi][nf][half*2 + 1];
                if (EPI == 1 || EPI == 2 || EPI == 4) { v0 += bias[col]; v1 += bias[col+1]; }
                if (EPI == 2) {
                    v0 = 0.5f * v0 * (1.0f + erff(v0 * 0.70710678118654752f));
                    v1 = 0.5f * v1 * (1.0f + erff(v1 * 0.70710678118654752f));
                }
                if (EPI >= 3) {
                    float2 r2 = *(const float2*)&R[(long long)row*ldr + col];
                    v0 += r2.x; v1 += r2.y;
                }
                if (OUT == 0) {
                    float2 o; o.x = v0; o.y = v1;
                    *(float2*)&Cf[(long long)row*ldc + col] = o;
                } else if (OUT == 1) {
                    *(__half2*)&Ch[(long long)row*ldc + col] =
                        __halves2half2(__float2half_rn(v0), __float2half_rn(v1));
                } else {
                    h16 h0,h1,l0,l1;
                    split_f16(v0,h0,l0); split_f16(v1,h1,l1);
                    *(__half2*)&Ch[(long long)row*ldc + col] = __halves2half2(h0,h1);
                    *(__half2*)&Cl[(long long)row*ldc + col] = __halves2half2(l0,l1);
                }
            }
        }
    }
}

// ---------------- V transpose (hi only): VT[z][n][k] = V[z][k][n] ----------
__global__ void vtrans_kernel(const h16* __restrict__ qh, h16* __restrict__ vth)
{
    __shared__ h16 th[32][100];
    const int z = blockIdx.y, bb = z >> 3, hh = z & 7;
    const int k0 = blockIdx.x * 32;
    const int tid = threadIdx.x;
    const h16* sh = qh + ((long long)(bb*NP) + k0)*(3*EMBED) + 2*EMBED + hh*HDIM;
    for (int idx = tid; idx < 32*HDIM; idx += 256) {
        int kk = idx / HDIM, nn = idx % HDIM;
        th[kk][nn] = sh[(long long)kk*(3*EMBED) + nn];
    }
    __syncthreads();
    h16* dh = vth + (long long)z*HDIM*NP + k0;
    for (int idx = tid; idx < 32*HDIM; idx += 256) {
        int nn = idx >> 5, kk = idx & 31;
        dh[(long long)nn*NP + kk] = th[kk][nn];
    }
}

// ---------------- fp32 -> fp16 hi/lo split (conv weight) ----------------
__global__ void split_kernel(const float* __restrict__ s, h16* __restrict__ h,
                             h16* __restrict__ l, long long n)
{
    long long i = ((long long)blockIdx.x*256 + threadIdx.x)*4;
    if (i >= n) return;
    float4 v = *(const float4*)&s[i];
    h16 h0,h1,h2,h3,l0,l1,l2,l3;
    split_f16(v.x,h0,l0); split_f16(v.y,h1,l1);
    split_f16(v.z,h2,l2); split_f16(v.w,h3,l3);
    *(__half2*)&h[i  ] = __halves2half2(h0,h1);
    *(__half2*)&h[i+2] = __halves2half2(h2,h3);
    *(__half2*)&l[i  ] = __halves2half2(l0,l1);
    *(__half2*)&l[i+2] = __halves2half2(l2,l3);
}

// ---------------- fp32 -> fp16 convert (hi only) ----------
__global__ void tohalf_kernel(const float* __restrict__ s, h16* __restrict__ h,
                              long long n)
{
    long long i = ((long long)blockIdx.x*256 + threadIdx.x)*4;
    if (i >= n) return;
    float4 v = *(const float4*)&s[i];
    *(__half2*)&h[i  ] = __halves2half2(__float2half_rn(v.x), __float2half_rn(v.y));
    *(__half2*)&h[i+2] = __halves2half2(__float2half_rn(v.z), __float2half_rn(v.w));
}

// ---------------- layernorm (fp32 out OR fp16-hi out) ----------------
__global__ void ln_kernel(const float* __restrict__ X, const float* __restrict__ sc,
                          const float* __restrict__ bi, float* __restrict__ Yf,
                          h16* __restrict__ Yh, int Cn)
{
    const float* x = X + (long long)blockIdx.x * Cn;
    __shared__ float sh1[32], sh2[32];
    int tid = threadIdx.x;
    float s = 0.f, s2 = 0.f;
    for (int i = tid; i < Cn; i += 256) { float v = x[i]; s += v; s2 += v*v; }
    #pragma unroll
    for (int o = 16; o > 0; o >>= 1) {
        s  += __shfl_xor_sync(0xffffffffu, s,  o);
        s2 += __shfl_xor_sync(0xffffffffu, s2, o);
    }
    if ((tid & 31) == 0) { sh1[tid>>5] = s; sh2[tid>>5] = s2; }
    __syncthreads();
    if (tid < 32) {
        float a = (tid < 8) ? sh1[tid] : 0.f;
        float b = (tid < 8) ? sh2[tid] : 0.f;
        #pragma unroll
        for (int o = 4; o > 0; o >>= 1) {
            a += __shfl_xor_sync(0xffffffffu, a, o);
            b += __shfl_xor_sync(0xffffffffu, b, o);
        }
        if (tid == 0) { sh1[0] = a; sh2[0] = b; }
    }
    __syncthreads();
    float mean = sh1[0] / Cn;
    float var  = sh2[0] / Cn - mean*mean;
    float inv  = rsqrtf(var + 1e-5f);
    for (int i = tid; i < Cn; i += 256) {
        float v = (x[i] - mean) * inv * sc[i] + bi[i];
        if (Yf) Yf[(long long)blockIdx.x*Cn + i] = v;
        else    Yh[(long long)blockIdx.x*Cn + i] = __float2half_rn(v);
    }
}

// ---------------- softmax: max-stabilized, __expf, one gmem read ----------
__global__ void softmax_kernel(const float* __restrict__ S, h16* __restrict__ Ph)
{
    const float* p = S + (long long)blockIdx.x * NP;
    h16* ph = Ph + (long long)blockIdx.x * NP;
    __shared__ float sh[32];
    int tid = threadIdx.x;
    const int IT = (NP + 255) / 256;   // 7
    float vals[(NP + 255) / 256];
    float mx = -1e30f;
    #pragma unroll
    for (int it = 0; it < IT; it++) {
        int i = tid + it*256;
        float v = (i < NP) ? p[i] : -1e30f;
        vals[it] = v;
        mx = fmaxf(mx, v);
    }
    #pragma unroll
    for (int o = 16; o > 0; o >>= 1) mx = fmaxf(mx, __shfl_xor_sync(0xffffffffu, mx, o));
    if ((tid & 31) == 0) sh[tid>>5] = mx;
    __syncthreads();
    if (tid < 32) {
        float v = (tid < 8) ? sh[tid] : -1e30f;
        #pragma unroll
        for (int o = 4; o > 0; o >>= 1) v = fmaxf(v, __shfl_xor_sync(0xffffffffu, v, o));
        if (tid == 0) sh[0] = v;
    }
    __syncthreads();
    mx = sh[0];
    __syncthreads();
    float sum = 0.f;
    #pragma unroll
    for (int it = 0; it < IT; it++) {
        int i = tid + it*256;
        float e = (i < NP) ? __expf(vals[it] - mx) : 0.f;   // arg <= 0: safe
        vals[it] = e;
        sum += e;
    }
    #pragma unroll
    for (int o = 16; o > 0; o >>= 1) sum += __shfl_xor_sync(0xffffffffu, sum, o);
    if ((tid & 31) == 0) sh[tid>>5] = sum;
    __syncthreads();
    if (tid < 32) {
        float v = (tid < 8) ? sh[tid] : 0.f;
        #pragma unroll
        for (int o = 4; o > 0; o >>= 1) v += __shfl_xor_sync(0xffffffffu, v, o);
        if (tid == 0) sh[0] = v;
    }
    __syncthreads();
    float inv = 1.0f / sh[0];
    #pragma unroll
    for (int it = 0; it < IT; it++) {
        int i = tid + it*256;
        if (i < NP) ph[i] = __float2half_rn(vals[it] * inv);
    }
}

// ---------------- im2col (writes fp16 hi only) ----------------
__global__ void im2col_kernel(const float* __restrict__ x)
{
    long long idx = (long long)blockIdx.x * 256 + threadIdx.x;
    if (idx >= (long long)NTOK * KPATCH) return;
    int j = (int)(idx % KPATCH);
    int m = (int)(idx / KPATCH);
    int b = m / NP, n = m % NP;
    int t = n / 196, r = n % 196, yy = r / 14, xx = r % 14;
    int i  = j / 512, r2 = j % 512;
    int dt = r2 / 256, r3 = r2 % 256;
    int dy = r3 / 16,  dx = r3 % 16;
    long long off = ((((long long)(b*3 + i)*16 + (2*t + dt))*224) + (16*yy + dy))*224 + (16*xx + dx);
    g_imh[idx] = __float2half_rn(x[off]);
}

// ---------------- positional encoding ----------------
__global__ void freq_kernel()
{
    int c2 = threadIdx.x;
    if (c2 < EMBED/2) g_freq[c2] = pow(10000.0, -2.0 * c2 / (double)EMBED);
}
__global__ void posadd_kernel()
{
    int idx = blockIdx.x * 256 + threadIdx.x;
    if (idx >= NP*EMBED) return;
    int n = idx / EMBED, c = idx % EMBED;
    double a = (double)n * g_freq[c >> 1];
    const double TWO_PI = 6.283185307179586476925286766559;
    int k = (int)(a * (1.0 / TWO_PI) + 0.5);
    float rf = (float)(a - (double)k * TWO_PI);
    float v = (c & 1) ? cosf(rf) : sinf(rf);
    g_h[idx]            += v;
    g_h[idx + NP*EMBED] += v;
}

// ---------------- mean pool: coalesced block reduce ----------------
__global__ void pool_kernel()
{
    __shared__ float acc[2][128];
    const int b  = blockIdx.y;
    const int c0 = blockIdx.x * 128;
    const int tg = threadIdx.x >> 7;
    const int c  = threadIdx.x & 127;
    const float* base = g_h + (long long)b*NP*EMBED + c0 + c;
    float s = 0.f;
    for (int n = tg; n < NP; n += 2)
        s += base[(long long)n*EMBED];
    acc[tg][c] = s;
    __syncthreads();
    if (tg == 0)
        g_pool[b*EMBED + c0 + c] = (acc[0][c] + acc[1][c]) * (1.0f / NP);
}

// ---------------- classifier head ----------------
__global__ void head_kernel(const float* __restrict__ W, const float* __restrict__ hb,
                            float* __restrict__ out)
{
    int g = blockIdx.x * 256 + threadIdx.x;
    int warp = g >> 5, lane = g & 31;
    if (warp >= BATCH*1000) return;
    int b = warp / 1000, j = warp % 1000;
    float s = 0.f;
    for (int c = lane; c < EMBED; c += 32)
        s += g_pln[b*EMBED + c] * W[j*EMBED + c];
    #pragma unroll
    for (int o = 16; o > 0; o >>= 1) s += __shfl_xor_sync(0xffffffffu, s, o);
    if (lane == 0) out[warp] = s + hb[j];
}

// ---------------- host orchestration ----------------
#define DSZ(anb,bnb,bnt) (((anb)*128 + (bnb)*(bnt))*SA*2*3)

extern "C" void kernel_launch(void* const* d_in, const int* in_sizes, int n_in,
                              void* d_out, int out_size)
{
    const float* x      = (const float*)d_in[0];
    const float* conv_w = (const float*)d_in[1];
    const float* conv_b = (const float*)d_in[2];
    const float* n1s    = (const float*)d_in[3];
    const float* n1b    = (const float*)d_in[4];
    const float* qkv_w  = (const float*)d_in[5];
    const float* out_w  = (const float*)d_in[6];
    const float* out_b  = (const float*)d_in[7];
    const float* n2s    = (const float*)d_in[8];
    const float* n2b    = (const float*)d_in[9];
    const float* fc1_w  = (const float*)d_in[10];
    const float* fc1_b  = (const float*)d_in[11];
    const float* fc2_w  = (const float*)d_in[12];
    const float* fc2_b  = (const float*)d_in[13];
    const float* fns    = (const float*)d_in[14];
    const float* fnb    = (const float*)d_in[15];
    const float* head_w = (const float*)d_in[16];
    const float* head_b = (const float*)d_in[17];
    float* out = (float*)d_out;

    float *h, *attn, *pool, *pln;
    h16 *imh,*yh,*qkvh,*Ph,*vth,*aoh,*mlph;
    h16 *cwh,*cwl,*qwh,*owh,*w1h,*w2h;
    cudaGetSymbolAddress((void**)&h,    g_h);
    cudaGetSymbolAddress((void**)&attn, g_attn);
    cudaGetSymbolAddress((void**)&pool, g_pool);
    cudaGetSymbolAddress((void**)&pln,  g_pln);
    cudaGetSymbolAddress((void**)&imh,  g_imh);
    cudaGetSymbolAddress((void**)&yh,   g_yh);
    cudaGetSymbolAddress((void**)&qkvh, g_qkvh);
    cudaGetSymbolAddress((void**)&Ph,   g_Ph);
    cudaGetSymbolAddress((void**)&vth,  g_vth);
    cudaGetSymbolAddress((void**)&aoh,  g_aoh);
    cudaGetSymbolAddress((void**)&mlph, g_mlph);
    cudaGetSymbolAddress((void**)&cwh,  g_cwh);   cudaGetSymbolAddress((void**)&cwl, g_cwl);
    cudaGetSymbolAddress((void**)&qwh,  g_qwh);
    cudaGetSymbolAddress((void**)&owh,  g_owh);
    cudaGetSymbolAddress((void**)&w1h,  g_w1h);
    cudaGetSymbolAddress((void**)&w2h,  g_w2h);

    cudaFuncSetAttribute(mma13_gemm<1,0,2,64 >, cudaFuncAttributeMaxDynamicSharedMemorySize, DSZ(1,2,64));
    cudaFuncSetAttribute(mma13_gemm<0,1,1,128>, cudaFuncAttributeMaxDynamicSharedMemorySize, DSZ(1,1,128));
    cudaFuncSetAttribute(mma13_gemm<0,0,1,128>, cudaFuncAttributeMaxDynamicSharedMemorySize, DSZ(1,1,128));
    cudaFuncSetAttribute(mma13_gemm<0,1,1,96 >, cudaFuncAttributeMaxDynamicSharedMemorySize, DSZ(1,1,96));
    cudaFuncSetAttribute(mma13_gemm<4,0,1,64 >, cudaFuncAttributeMaxDynamicSharedMemorySize, DSZ(1,1,64));
    cudaFuncSetAttribute(mma13_gemm<2,1,1,128>, cudaFuncAttributeMaxDynamicSharedMemorySize, DSZ(1,1,128));

    const long long Z0 = 0;

    // ---- weight prep ----
    {
        long long n;
        n = (long long)EMBED*KPATCH;
        split_kernel<<<(int)((n/4+255)/256),256>>>(conv_w, cwh, cwl, n);
        n = (long long)DEPTH*3*EMBED*EMBED;
        tohalf_kernel<<<(int)((n/4+255)/256),256>>>(qkv_w, qwh, n);
        n = (long long)DEPTH*EMBED*EMBED;
        tohalf_kernel<<<(int)((n/4+255)/256),256>>>(out_w, owh, n);
        n = (long long)DEPTH*MLPH*EMBED;
        tohalf_kernel<<<(int)((n/4+255)/256),256>>>(fc1_w, w1h, n);
        n = (long long)DEPTH*EMBED*MLPH;
        tohalf_kernel<<<(int)((n/4+255)/256),256>>>(fc2_w, w2h, n);
    }

    // ---- patch embed ----
    im2col_kernel<<<(int)(((long long)NTOK*KPATCH + 255)/256), 256>>>(x);
    {
        dim3 g(EMBED/64, (NTOK+127)/128, 1);
        mma13_gemm<1,0,2,64><<<g,256,DSZ(1,2,64)>>>(
            imh, nullptr, cwh, cwl, conv_b, nullptr, h, nullptr, nullptr,
            NTOK, EMBED, KPATCH, KPATCH, KPATCH, EMBED, 0,
            Z0,Z0,Z0,Z0,Z0,Z0,Z0,Z0, 1);
    }
    freq_kernel<<<1, EMBED/2>>>();
    posadd_kernel<<<(NP*EMBED + 255)/256, 256>>>();

    // ---- transformer blocks ----
    for (int l = 0; l < DEPTH; l++) {
        h16* lqwh = qwh + (long long)l*3*EMBED*EMBED;
        h16* lowh = owh + (long long)l*EMBED*EMBED;
        h16* lw1h = w1h + (long long)l*MLPH*EMBED;
        h16* lw2h = w2h + (long long)l*EMBED*MLPH;
        const float* ob = out_b + (long long)l*EMBED;
        const float* b1 = fc1_b + (long long)l*MLPH;
        const float* b2 = fc2_b + (long long)l*EMBED;

        // y = LN1(h) -> fp16 hi
        ln_kernel<<<NTOK,256>>>(h, n1s + l*EMBED, n1b + l*EMBED, nullptr, yh, EMBED);

        {   // qkv = y @ qw^T  (1-term) -> fp16 hi only
            dim3 g((3*EMBED)/128, (NTOK+127)/128, 1);
            mma13_gemm<0,1,1,128><<<g,256,DSZ(1,1,128)>>>(
                yh, nullptr, lqwh, nullptr, nullptr, nullptr, nullptr, qkvh, nullptr,
                NTOK, 3*EMBED, EMBED, EMBED, EMBED, 3*EMBED, 0,
                Z0,Z0,Z0,Z0,Z0,Z0,Z0,Z0, 1);
        }

        {   // V^T per (b,h), hi only
            dim3 g(NP/32, BATCH*HEADS, 1);
            vtrans_kernel<<<g,256>>>(qkvh, vth);
        }

        {   // S = Q @ K^T  fp32 (1-term: Qh*Kh)
            dim3 g((NP+127)/128, (NP+127)/128, BATCH*HEADS);
            mma13_gemm<0,0,1,128><<<g,256,DSZ(1,1,128)>>>(
                qkvh, nullptr, qkvh + EMBED, nullptr, nullptr, nullptr,
                attn, nullptr, nullptr,
                NP, NP, HDIM, 3*EMBED, 3*EMBED, NP, 0,
                (long long)NP*3*EMBED, (long long)HDIM,
                (long long)NP*3*EMBED, (long long)HDIM,
                (long long)HEADS*NP*NP, (long long)NP*NP,
                Z0, Z0, HEADS);
        }

        softmax_kernel<<<BATCH*HEADS*NP, 256>>>(attn, Ph);

        {   // ao = P @ VT^T  (1-term) -> fp16 hi (N=96)
            dim3 g(1, (NP+127)/128, BATCH*HEADS);
            mma13_gemm<0,1,1,96><<<g,256,DSZ(1,1,96)>>>(
                Ph, nullptr, vth, nullptr, nullptr, nullptr, nullptr, aoh, nullptr,
                NP, HDIM, NP, NP, NP, EMBED, 0,
                (long long)HEADS*NP*NP, (long long)NP*NP,
                (long long)HEADS*HDIM*NP, (long long)HDIM*NP,
                (long long)NP*EMBED, (long long)HDIM,
                Z0, Z0, HEADS);
        }

        {   // h = h + ao @ ow^T + ob  (1-term)
            dim3 g(EMBED/64, (NTOK+127)/128, 1);
            mma13_gemm<4,0,1,64><<<g,256,DSZ(1,1,64)>>>(
                aoh, nullptr, lowh, nullptr, ob, h, h, nullptr, nullptr,
                NTOK, EMBED, EMBED, EMBED, EMBED, EMBED, EMBED,
                Z0,Z0,Z0,Z0,Z0,Z0,Z0,Z0, 1);
        }

        // y = LN2(h) -> fp16 hi
        ln_kernel<<<NTOK,256>>>(h, n2s + l*EMBED, n2b + l*EMBED, nullptr, yh, EMBED);

        {   // mlp = gelu(y @ w1^T + b1)  (1-term) -> fp16 hi
            dim3 g(MLPH/128, (NTOK+127)/128, 1);
            mma13_gemm<2,1,1,128><<<g,256,DSZ(1,1,128)>>>(
                yh, nullptr, lw1h, nullptr, b1, nullptr, nullptr, mlph, nullptr,
                NTOK, MLPH, EMBED, EMBED, EMBED, MLPH, 0,
                Z0,Z0,Z0,Z0,Z0,Z0,Z0,Z0, 1);
        }

        {   // h = h + mlp @ w2^T + b2  (1-term)
            dim3 g(EMBED/64, (NTOK+127)/128, 1);
            mma13_gemm<4,0,1,64><<<g,256,DSZ(1,1,64)>>>(
                mlph, nullptr, lw2h, nullptr, b2, h, h, nullptr, nullptr,
                NTOK, EMBED, MLPH, MLPH, MLPH, EMBED, EMBED,
                Z0,Z0,Z0,Z0,Z0,Z0,Z0,Z0, 1);
        }
    }

    // ---- pooled head ----
    {
        dim3 g(EMBED/128, BATCH);
        pool_kernel<<<g,256>>>();
    }
    ln_kernel<<<BATCH,256>>>(pool, fns, fnb, pln, nullptr, EMBED);
    head_kernel<<<(BATCH*1000*32 + 255)/256, 256>>>(head_w, head_b, out);
}

// round 14
// speedup vs baseline: 2.6584x; 1.1397x over previous
#include <cuda_runtime.h>
#include <cuda_fp16.h>
#include <math.h>
#include <stdint.h>

#define EMBED   768
#define HEADS   8
#define HDIM    96
#define DEPTH   12
#define MLPH    3072
#define NP      1568
#define BATCH   2
#define NTOK    (BATCH*NP)      // 3136
#define KPATCH  1536

typedef __half h16;

// ---------------- scratch (device globals: allocation-free) ----------------
__device__ __align__(256) h16   g_imh [NTOK*KPATCH];
__device__ __align__(256) float g_h   [NTOK*EMBED];
__device__ __align__(256) h16   g_yh  [NTOK*EMBED];
__device__ __align__(256) h16   g_qkvh[NTOK*3*EMBED];
__device__ __align__(256) h16   g_vth [16*HDIM*NP];   // V^T per (b,h): [96][1568]
__device__ __align__(256) h16   g_aoh [NTOK*EMBED];
__device__ __align__(256) h16   g_mlph[NTOK*MLPH];
__device__ float g_pool[BATCH*EMBED];
__device__ float g_pln [BATCH*EMBED];
__device__ double g_freq[EMBED/2];
// weights: conv hi+lo (2-term); qkv/out/fc1/fc2 hi only (1-term)
__device__ __align__(256) h16 g_cwh[EMBED*KPATCH];
__device__ __align__(256) h16 g_cwl[EMBED*KPATCH];
__device__ __align__(256) h16 g_qwh[DEPTH*3*EMBED*EMBED];
__device__ __align__(256) h16 g_owh[DEPTH*EMBED*EMBED];
__device__ __align__(256) h16 g_w1h[DEPTH*MLPH*EMBED];
__device__ __align__(256) h16 g_w2h[DEPTH*EMBED*MLPH];

__device__ __forceinline__ void split_f16(float v, h16& h, h16& l)
{
    h = __float2half_rn(v);
    l = __float2half_rn(v - __half2float(h));
}

#define LDSM4(R, addr) \
    asm volatile("ldmatrix.sync.aligned.m8n8.x4.shared.b16 {%0,%1,%2,%3},[%4];" \
        : "=r"((R)[0]), "=r"((R)[1]), "=r"((R)[2]), "=r"((R)[3]) : "r"(addr))

#define MMA_F32(C, A, B0, B1) \
    asm volatile("mma.sync.aligned.m16n8k16.row.col.f32.f16.f16.f32 " \
        "{%0,%1,%2,%3},{%4,%5,%6,%7},{%8,%9},{%0,%1,%2,%3};" \
        : "+f"((C)[0]), "+f"((C)[1]), "+f"((C)[2]), "+f"((C)[3]) \
        : "r"((A)[0]), "r"((A)[1]), "r"((A)[2]), "r"((A)[3]), "r"(B0), "r"(B1))

__device__ __forceinline__ void cpa16(uint32_t dst, const void* src, bool p)
{
    int sz = p ? 16 : 0;
    asm volatile("cp.async.cg.shared.global [%0],[%1],16,%2;\n"
                 :: "r"(dst), "l"(src), "r"(sz));
}

// ================= GEMM: fp16, TERMS in {1,2} (conv uses 2) ================
#define BK 32
#define SA 40

template<int EPI, int OUT, int TERMS, int BNT>
__global__ void __launch_bounds__(256)
mma14_gemm(const h16* __restrict__ Agh,
           const h16* __restrict__ Bgh, const h16* __restrict__ Bgl,
           const float* __restrict__ bias, const float* __restrict__ R,
           float* __restrict__ Cf, h16* __restrict__ Ch,
           int M, int N, int K, int lda, int ldb, int ldc, int ldr)
{
    constexpr int WN    = BNT / 2;
    constexpr int NPR   = WN / 16;
    constexpr int BNB   = (TERMS >= 2) ? 2 : 1;
    constexpr int OFFB  = 128 * SA;
    constexpr int STAGE = (128 + BNB * BNT) * SA;

    extern __shared__ __align__(16) h16 smem[];
    const uint32_t su = (uint32_t)__cvta_generic_to_shared(smem);

    const int tid  = threadIdx.x;
    const int lane = tid & 31;
    const int w    = tid >> 5;
    const int wm   = w >> 1;
    const int wn   = w & 1;
    const int m0   = blockIdx.y * 128;
    const int n0   = blockIdx.x * BNT;

    float c[2][2*NPR][4];
    #pragma unroll
    for (int i = 0; i < 2; i++)
        #pragma unroll
        for (int j = 0; j < 2*NPR; j++)
            #pragma unroll
            for (int q = 0; q < 4; q++) c[i][j][q] = 0.f;

    const int lrow = lane & 15;
    const int lcol = (lane >> 4) * 8;
    const uint32_t aoffA = (uint32_t)(((wm*32 + lrow)*SA + lcol) * 2);
    const uint32_t boffB = (uint32_t)(((wn*WN + lrow)*SA + lcol) * 2);

    const int T = K / BK;

    auto issue = [&](int t, int s) {
        const int k0 = t * BK;
        const uint32_t sb = su + (uint32_t)(s * STAGE) * 2u;
        #pragma unroll
        for (int i = 0; i < 2; i++) {
            const int ch  = (i << 8) + tid;
            const int row = ch >> 2;
            const int kc  = (ch & 3) << 3;
            const bool p  = (m0 + row) < M;
            const h16* src = Agh + (long long)(p ? (m0 + row) : 0) * lda + k0 + kc;
            cpa16(sb + (uint32_t)(row*SA + kc) * 2u, src, p);
        }
        constexpr int BTOT = BNB * BNT * 4;
        constexpr int BCH  = (BTOT + 255) / 256;
        #pragma unroll
        for (int i = 0; i < BCH; i++) {
            const int ch = i*256 + tid;
            if (BTOT % 256 != 0 && ch >= BTOT) break;
            const int hl  = ch / (BNT*4);
            const int rem = ch % (BNT*4);
            const int row = rem >> 2;
            const int kc  = (rem & 3) << 3;
            const bool p  = (n0 + row) < N;
            const h16* src = (hl ? Bgl : Bgh)
                           + (long long)(p ? (n0 + row) : 0) * ldb + k0 + kc;
            cpa16(sb + (uint32_t)(OFFB + hl*BNT*SA + row*SA + kc) * 2u, src, p);
        }
    };

    issue(0, 0);
    asm volatile("cp.async.commit_group;");
    if (T > 1) { issue(1, 1); asm volatile("cp.async.commit_group;"); }

    for (int t = 0; t < T; t++) {
        if (t + 1 < T) asm volatile("cp.async.wait_group 1;");
        else           asm volatile("cp.async.wait_group 0;");
        __syncthreads();

        if (t + 2 < T) {
            issue(t + 2, (t + 2) % 3);
            asm volatile("cp.async.commit_group;");
        }

        const int s = t % 3;
        const uint32_t sb  = su + (uint32_t)(s * STAGE) * 2u;
        const uint32_t aHb = sb + aoffA;
        const uint32_t bHb = sb + (uint32_t)OFFB * 2u + boffB;
        const uint32_t bLb = bHb + (uint32_t)(BNT*SA) * 2u;

        #pragma unroll
        for (int kk2 = 0; kk2 < 2; kk2++) {
            const uint32_t kb = (uint32_t)(kk2 * 32);
            uint32_t Ahf[2][4], Bhf[NPR][4], Blf[NPR][4];
            #pragma unroll
            for (int mi = 0; mi < 2; mi++)
                LDSM4(Ahf[mi], aHb + (uint32_t)(mi*16*SA*2) + kb);
            #pragma unroll
            for (int pr = 0; pr < NPR; pr++) {
                LDSM4(Bhf[pr], bHb + (uint32_t)(pr*16*SA*2) + kb);
                if (TERMS >= 2)
                    LDSM4(Blf[pr], bLb + (uint32_t)(pr*16*SA*2) + kb);
            }
            #pragma unroll
            for (int mi = 0; mi < 2; mi++) {
                #pragma unroll
                for (int pr = 0; pr < NPR; pr++) {
                    MMA_F32(c[mi][2*pr  ], Ahf[mi], Bhf[pr][0], Bhf[pr][2]);
                    MMA_F32(c[mi][2*pr+1], Ahf[mi], Bhf[pr][1], Bhf[pr][3]);
                    if (TERMS >= 2) {
                        MMA_F32(c[mi][2*pr  ], Ahf[mi], Blf[pr][0], Blf[pr][2]);
                        MMA_F32(c[mi][2*pr+1], Ahf[mi], Blf[pr][1], Blf[pr][3]);
                    }
                }
            }
        }
    }

    const int g  = lane >> 2;
    const int tq = lane & 3;
    #pragma unroll
    for (int mi = 0; mi < 2; mi++) {
        #pragma unroll
        for (int nf = 0; nf < 2*NPR; nf++) {
            int col = n0 + wn*WN + nf*8 + tq*2;
            #pragma unroll
            for (int half = 0; half < 2; half++) {
                int row = m0 + wm*32 + mi*16 + g + half*8;
                if (row >= M || col >= N) continue;
                float v0 = c[mi][nf][half*2 + 0];
                float v1 = c[mi][nf][half*2 + 1];
                if (EPI == 1 || EPI == 2 || EPI == 4) { v0 += bias[col]; v1 += bias[col+1]; }
                if (EPI == 2) {
                    v0 = 0.5f * v0 * (1.0f + erff(v0 * 0.70710678118654752f));
                    v1 = 0.5f * v1 * (1.0f + erff(v1 * 0.70710678118654752f));
                }
                if (EPI >= 3) {
                    float2 r2 = *(const float2*)&R[(long long)row*ldr + col];
                    v0 += r2.x; v1 += r2.y;
                }
                if (OUT == 0) {
                    float2 o; o.x = v0; o.y = v1;
                    *(float2*)&Cf[(long long)row*ldc + col] = o;
                } else {
                    *(__half2*)&Ch[(long long)row*ldc + col] =
                        __halves2half2(__float2half_rn(v0), __float2half_rn(v1));
                }
            }
        }
    }
}

// ================= flash attention: QK + softmax + PV fused ================
// grid (1, 13, 16); block 256. Per (b,h): Q tile 128 rows, loop 13 key tiles.
#define QSTR 104    // 96 dims + pad (208B stride: conflict-free, same as SA=40)
#define PSTR 136    // 128 keys + pad (272B stride: conflict-free)
#define FT   13     // ceil(NP/128)
// smem (h16 elems): Q[128*QSTR] | K[2][128*QSTR] | VT[2][96*PSTR] | P[128*PSTR] | stats
#define F_OQ  0
#define F_OK  (128*QSTR)
#define F_OVT (F_OK + 2*128*QSTR)
#define F_OP  (F_OVT + 2*96*PSTR)
#define F_ELEMS (F_OP + 128*PSTR)
#define F_SMEM (F_ELEMS*2 + 2*256*4)

__global__ void __launch_bounds__(256)
flash_kernel(const h16* __restrict__ qkv, const h16* __restrict__ vt,
             h16* __restrict__ ao)
{
    extern __shared__ __align__(16) h16 smem[];
    const uint32_t su = (uint32_t)__cvta_generic_to_shared(smem);
    float* statm = (float*)(smem + F_ELEMS);
    float* stats = statm + 256;

    const int tid = threadIdx.x, lane = tid & 31, w = tid >> 5;
    const int wm = w >> 1, wn = w & 1;
    const int g = lane >> 2, tq = lane & 3;
    const int z = blockIdx.z, bb = z >> 3, hh = z & 7;
    const int m0 = blockIdx.y * 128;

    const h16* Qg  = qkv + (long long)bb*NP*(3*EMBED) + hh*HDIM;
    const h16* Kg  = Qg + EMBED;
    const h16* VTg = vt + (long long)z*HDIM*NP;
    h16* AOg = ao + (long long)bb*NP*EMBED + hh*HDIM;

    // Q tile load (group 0 with KV tile 0)
    #pragma unroll
    for (int i = 0; i < 6; i++) {
        int ch = i*256 + tid;
        int row = ch / 12, c16 = ch % 12;
        bool p = (m0 + row) < NP;
        cpa16(su + (uint32_t)((F_OQ + row*QSTR + c16*8) * 2),
              Qg + (long long)(p ? (m0 + row) : 0)*(3*EMBED) + c16*8, p);
    }

    auto issueKV = [&](int t, int s) {
        const int k0 = t * 128;
        #pragma unroll
        for (int i = 0; i < 6; i++) {        // K: 128 keys x 96 dims
            int ch = i*256 + tid;
            int row = ch / 12, c16 = ch % 12;
            bool p = (k0 + row) < NP;
            cpa16(su + (uint32_t)((F_OK + s*128*QSTR + row*QSTR + c16*8) * 2),
                  Kg + (long long)(p ? (k0 + row) : 0)*(3*EMBED) + c16*8, p);
        }
        #pragma unroll
        for (int i = 0; i < 6; i++) {        // VT: 96 dims x 128 keys
            int ch = i*256 + tid;
            int row = ch >> 4, c16 = ch & 15;
            bool p = (k0 + c16*8) < NP;      // NP%8==0: chunks align
            cpa16(su + (uint32_t)((F_OVT + s*96*PSTR + row*PSTR + c16*8) * 2),
                  VTg + (long long)row*NP + (p ? (k0 + c16*8) : 0), p);
        }
    };

    issueKV(0, 0);
    asm volatile("cp.async.commit_group;");

    const int lrow = lane & 15;
    const int lcol = (lane >> 4) * 8;
    const uint32_t qoff  = su + (uint32_t)((F_OQ + (wm*32 + lrow)*QSTR + lcol) * 2);
    const uint32_t poffA = su + (uint32_t)((F_OP + (wm*32 + lrow)*PSTR + lcol) * 2);
    const int rbase = wm*32 + g;

    float o[2][6][4];
    float m_run[2][2], l_run[2][2], scl[2][2];
    #pragma unroll
    for (int mi = 0; mi < 2; mi++) {
        #pragma unroll
        for (int nf = 0; nf < 6; nf++)
            #pragma unroll
            for (int q = 0; q < 4; q++) o[mi][nf][q] = 0.f;
        m_run[mi][0] = m_run[mi][1] = -1e30f;
        l_run[mi][0] = l_run[mi][1] = 0.f;
    }

    for (int t = 0; t < FT; t++) {
        asm volatile("cp.async.wait_group 0;");
        __syncthreads();                               // tiles ready; prev P reads done
        if (t + 1 < FT) {
            issueKV(t + 1, (t + 1) & 1);
            asm volatile("cp.async.commit_group;");
        }

        const int s = t & 1;
        const uint32_t koff  = su + (uint32_t)((F_OK + s*128*QSTR + (wn*64 + lrow)*QSTR + lcol) * 2);
        const uint32_t vtoff = su + (uint32_t)((F_OVT + s*96*PSTR + (wn*48 + lrow)*PSTR + lcol) * 2);

        // ---- S = Q @ K^T (128x128) ----
        float c[2][8][4];
        #pragma unroll
        for (int mi = 0; mi < 2; mi++)
            #pragma unroll
            for (int nf = 0; nf < 8; nf++)
                #pragma unroll
                for (int q = 0; q < 4; q++) c[mi][nf][q] = 0.f;
        #pragma unroll
        for (int kci = 0; kci < 6; kci++) {
            const uint32_t kb = (uint32_t)(kci * 32);
            uint32_t Af[2][4], Bf[4][4];
            LDSM4(Af[0], qoff + kb);
            LDSM4(Af[1], qoff + (uint32_t)(16*QSTR*2) + kb);
            #pragma unroll
            for (int pr = 0; pr < 4; pr++)
                LDSM4(Bf[pr], koff + (uint32_t)(pr*16*QSTR*2) + kb);
            #pragma unroll
            for (int mi = 0; mi < 2; mi++)
                #pragma unroll
                for (int pr = 0; pr < 4; pr++) {
                    MMA_F32(c[mi][2*pr  ], Af[mi], Bf[pr][0], Bf[pr][2]);
                    MMA_F32(c[mi][2*pr+1], Af[mi], Bf[pr][1], Bf[pr][3]);
                }
        }
        // ---- mask invalid keys (last tile only) ----
        if (t == FT - 1) {
            #pragma unroll
            for (int nf = 0; nf < 8; nf++) {
                int col0 = t*128 + wn*64 + nf*8 + tq*2;
                if (col0 >= NP)     { c[0][nf][0]=c[0][nf][2]=c[1][nf][0]=c[1][nf][2]=-1e30f; }
                if (col0 + 1 >= NP) { c[0][nf][1]=c[0][nf][3]=c[1][nf][1]=c[1][nf][3]=-1e30f; }
            }
        }
        // ---- phase 1: warp-slice row max ----
        #pragma unroll
        for (int mi = 0; mi < 2; mi++)
            #pragma unroll
            for (int qh = 0; qh < 2; qh++) {
                float v = -1e30f;
                #pragma unroll
                for (int nf = 0; nf < 8; nf++)
                    v = fmaxf(v, fmaxf(c[mi][nf][qh*2], c[mi][nf][qh*2+1]));
                v = fmaxf(v, __shfl_xor_sync(0xffffffffu, v, 1));
                v = fmaxf(v, __shfl_xor_sync(0xffffffffu, v, 2));
                if (tq == 0) statm[(rbase + mi*16 + qh*8)*2 + wn] = v;
            }
        __syncthreads();
        // ---- phase 2: new max, rescale O, p = exp(s-m), sums, store P ----
        #pragma unroll
        for (int mi = 0; mi < 2; mi++)
            #pragma unroll
            for (int qh = 0; qh < 2; qh++) {
                const int r = rbase + mi*16 + qh*8;
                float tm = fmaxf(statm[r*2], statm[r*2+1]);
                float mn = fmaxf(m_run[mi][qh], tm);
                float sc = __expf(m_run[mi][qh] - mn);
                m_run[mi][qh] = mn; scl[mi][qh] = sc;
                #pragma unroll
                for (int nf = 0; nf < 6; nf++) {
                    o[mi][nf][qh*2  ] *= sc;
                    o[mi][nf][qh*2+1] *= sc;
                }
                float ps = 0.f;
                #pragma unroll
                for (int nf = 0; nf < 8; nf++) {
                    float p0 = __expf(c[mi][nf][qh*2  ] - mn);
                    float p1 = __expf(c[mi][nf][qh*2+1] - mn);
                    c[mi][nf][qh*2] = p0; c[mi][nf][qh*2+1] = p1;
                    ps += p0 + p1;
                    *(__half2*)(smem + F_OP + (wm*32 + mi*16 + g + qh*8)*PSTR
                                + wn*64 + nf*8 + tq*2) =
                        __halves2half2(__float2half_rn(p0), __float2half_rn(p1));
                }
                ps += __shfl_xor_sync(0xffffffffu, ps, 1);
                ps += __shfl_xor_sync(0xffffffffu, ps, 2);
                if (tq == 0) stats[r*2 + wn] = ps;
            }
        __syncthreads();                               // P + sums visible
        // ---- phase 3: update l; O += P @ VT^T ----
        #pragma unroll
        for (int mi = 0; mi < 2; mi++)
            #pragma unroll
            for (int qh = 0; qh < 2; qh++) {
                const int r = rbase + mi*16 + qh*8;
                l_run[mi][qh] = l_run[mi][qh]*scl[mi][qh] + stats[r*2] + stats[r*2+1];
            }
        #pragma unroll
        for (int kci = 0; kci < 8; kci++) {
            const uint32_t kb = (uint32_t)(kci * 32);
            uint32_t Af[2][4], Bf[3][4];
            LDSM4(Af[0], poffA + kb);
            LDSM4(Af[1], poffA + (uint32_t)(16*PSTR*2) + kb);
            #pragma unroll
            for (int pr = 0; pr < 3; pr++)
                LDSM4(Bf[pr], vtoff + (uint32_t)(pr*16*PSTR*2) + kb);
            #pragma unroll
            for (int mi = 0; mi < 2; mi++)
                #pragma unroll
                for (int pr = 0; pr < 3; pr++) {
                    MMA_F32(o[mi][2*pr  ], Af[mi], Bf[pr][0], Bf[pr][2]);
                    MMA_F32(o[mi][2*pr+1], Af[mi], Bf[pr][1], Bf[pr][3]);
                }
        }
    }

    // ---- epilogue: ao = O / l ----
    #pragma unroll
    for (int mi = 0; mi < 2; mi++)
        #pragma unroll
        for (int qh = 0; qh < 2; qh++) {
            const int row = m0 + rbase + mi*16 + qh*8;
            if (row >= NP) continue;
            const float inv = 1.0f / l_run[mi][qh];
            #pragma unroll
            for (int nf = 0; nf < 6; nf++) {
                const int col = wn*48 + nf*8 + tq*2;
                float v0 = o[mi][nf][qh*2  ] * inv;
                float v1 = o[mi][nf][qh*2+1] * inv;
                *(__half2*)&AOg[(long long)row*EMBED + col] =
                    __halves2half2(__float2half_rn(v0), __float2half_rn(v1));
            }
        }
}

// ---------------- V transpose (hi only): VT[z][n][k] = V[z][k][n] ----------
__global__ void vtrans_kernel(const h16* __restrict__ qh, h16* __restrict__ vth)
{
    __shared__ h16 th[32][100];
    const int z = blockIdx.y, bb = z >> 3, hh = z & 7;
    const int k0 = blockIdx.x * 32;
    const int tid = threadIdx.x;
    const h16* sh = qh + ((long long)(bb*NP) + k0)*(3*EMBED) + 2*EMBED + hh*HDIM;
    for (int idx = tid; idx < 32*HDIM; idx += 256) {
        int kk = idx / HDIM, nn = idx % HDIM;
        th[kk][nn] = sh[(long long)kk*(3*EMBED) + nn];
    }
    __syncthreads();
    h16* dh = vth + (long long)z*HDIM*NP + k0;
    for (int idx = tid; idx < 32*HDIM; idx += 256) {
        int nn = idx >> 5, kk = idx & 31;
        dh[(long long)nn*NP + kk] = th[kk][nn];
    }
}

// ---------------- fp32 -> fp16 hi/lo split (conv weight) ----------------
__global__ void split_kernel(const float* __restrict__ s, h16* __restrict__ h,
                             h16* __restrict__ l, long long n)
{
    long long i = ((long long)blockIdx.x*256 + threadIdx.x)*4;
    if (i >= n) return;
    float4 v = *(const float4*)&s[i];
    h16 h0,h1,h2,h3,l0,l1,l2,l3;
    split_f16(v.x,h0,l0); split_f16(v.y,h1,l1);
    split_f16(v.z,h2,l2); split_f16(v.w,h3,l3);
    *(__half2*)&h[i  ] = __halves2half2(h0,h1);
    *(__half2*)&h[i+2] = __halves2half2(h2,h3);
    *(__half2*)&l[i  ] = __halves2half2(l0,l1);
    *(__half2*)&l[i+2] = __halves2half2(l2,l3);
}

// ---------------- fp32 -> fp16 convert (hi only) ----------
__global__ void tohalf_kernel(const float* __restrict__ s, h16* __restrict__ h,
                              long long n)
{
    long long i = ((long long)blockIdx.x*256 + threadIdx.x)*4;
    if (i >= n) return;
    float4 v = *(const float4*)&s[i];
    *(__half2*)&h[i  ] = __halves2half2(__float2half_rn(v.x), __float2half_rn(v.y));
    *(__half2*)&h[i+2] = __halves2half2(__float2half_rn(v.z), __float2half_rn(v.w));
}

// ---------------- layernorm (fp32 out OR fp16-hi out) ----------------
__global__ void ln_kernel(const float* __restrict__ X, const float* __restrict__ sc,
                          const float* __restrict__ bi, float* __restrict__ Yf,
                          h16* __restrict__ Yh, int Cn)
{
    const float* x = X + (long long)blockIdx.x * Cn;
    __shared__ float sh1[32], sh2[32];
    int tid = threadIdx.x;
    float s = 0.f, s2 = 0.f;
    for (int i = tid; i < Cn; i += 256) { float v = x[i]; s += v; s2 += v*v; }
    #pragma unroll
    for (int o = 16; o > 0; o >>= 1) {
        s  += __shfl_xor_sync(0xffffffffu, s,  o);
        s2 += __shfl_xor_sync(0xffffffffu, s2, o);
    }
    if ((tid & 31) == 0) { sh1[tid>>5] = s; sh2[tid>>5] = s2; }
    __syncthreads();
    if (tid < 32) {
        float a = (tid < 8) ? sh1[tid] : 0.f;
        float b = (tid < 8) ? sh2[tid] : 0.f;
        #pragma unroll
        for (int o = 4; o > 0; o >>= 1) {
            a += __shfl_xor_sync(0xffffffffu, a, o);
            b += __shfl_xor_sync(0xffffffffu, b, o);
        }
        if (tid == 0) { sh1[0] = a; sh2[0] = b; }
    }
    __syncthreads();
    float mean = sh1[0] / Cn;
    float var  = sh2[0] / Cn - mean*mean;
    float inv  = rsqrtf(var + 1e-5f);
    for (int i = tid; i < Cn; i += 256) {
        float v = (x[i] - mean) * inv * sc[i] + bi[i];
        if (Yf) Yf[(long long)blockIdx.x*Cn + i] = v;
        else    Yh[(long long)blockIdx.x*Cn + i] = __float2half_rn(v);
    }
}

// ---------------- im2col (writes fp16 hi only) ----------------
__global__ void im2col_kernel(const float* __restrict__ x)
{
    long long idx = (long long)blockIdx.x * 256 + threadIdx.x;
    if (idx >= (long long)NTOK * KPATCH) return;
    int j = (int)(idx % KPATCH);
    int m = (int)(idx / KPATCH);
    int b = m / NP, n = m % NP;
    int t = n / 196, r = n % 196, yy = r / 14, xx = r % 14;
    int i  = j / 512, r2 = j % 512;
    int dt = r2 / 256, r3 = r2 % 256;
    int dy = r3 / 16,  dx = r3 % 16;
    long long off = ((((long long)(b*3 + i)*16 + (2*t + dt))*224) + (16*yy + dy))*224 + (16*xx + dx);
    g_imh[idx] = __float2half_rn(x[off]);
}

// ---------------- positional encoding ----------------
__global__ void freq_kernel()
{
    int c2 = threadIdx.x;
    if (c2 < EMBED/2) g_freq[c2] = pow(10000.0, -2.0 * c2 / (double)EMBED);
}
__global__ void posadd_kernel()
{
    int idx = blockIdx.x * 256 + threadIdx.x;
    if (idx >= NP*EMBED) return;
    int n = idx / EMBED, c = idx % EMBED;
    double a = (double)n * g_freq[c >> 1];
    const double TWO_PI = 6.283185307179586476925286766559;
    int k = (int)(a * (1.0 / TWO_PI) + 0.5);
    float rf = (float)(a - (double)k * TWO_PI);
    float v = (c & 1) ? cosf(rf) : sinf(rf);
    g_h[idx]            += v;
    g_h[idx + NP*EMBED] += v;
}

// ---------------- mean pool: coalesced block reduce ----------------
__global__ void pool_kernel()
{
    __shared__ float acc[2][128];
    const int b  = blockIdx.y;
    const int c0 = blockIdx.x * 128;
    const int tg = threadIdx.x >> 7;
    const int c  = threadIdx.x & 127;
    const float* base = g_h + (long long)b*NP*EMBED + c0 + c;
    float s = 0.f;
    for (int n = tg; n < NP; n += 2)
        s += base[(long long)n*EMBED];
    acc[tg][c] = s;
    __syncthreads();
    if (tg == 0)
        g_pool[b*EMBED + c0 + c] = (acc[0][c] + acc[1][c]) * (1.0f / NP);
}

// ---------------- classifier head ----------------
__global__ void head_kernel(const float* __restrict__ W, const float* __restrict__ hb,
                            float* __restrict__ out)
{
    int g = blockIdx.x * 256 + threadIdx.x;
    int warp = g >> 5, lane = g & 31;
    if (warp >= BATCH*1000) return;
    int b = warp / 1000, j = warp % 1000;
    float s = 0.f;
    for (int c = lane; c < EMBED; c += 32)
        s += g_pln[b*EMBED + c] * W[j*EMBED + c];
    #pragma unroll
    for (int o = 16; o > 0; o >>= 1) s += __shfl_xor_sync(0xffffffffu, s, o);
    if (lane == 0) out[warp] = s + hb[j];
}

// ---------------- host orchestration ----------------
#define DSZ(bnb,bnt) ((128 + (bnb)*(bnt))*SA*2*3)

extern "C" void kernel_launch(void* const* d_in, const int* in_sizes, int n_in,
                              void* d_out, int out_size)
{
    const float* x      = (const float*)d_in[0];
    const float* conv_w = (const float*)d_in[1];
    const float* conv_b = (const float*)d_in[2];
    const float* n1s    = (const float*)d_in[3];
    const float* n1b    = (const float*)d_in[4];
    const float* qkv_w  = (const float*)d_in[5];
    const float* out_w  = (const float*)d_in[6];
    const float* out_b  = (const float*)d_in[7];
    const float* n2s    = (const float*)d_in[8];
    const float* n2b    = (const float*)d_in[9];
    const float* fc1_w  = (const float*)d_in[10];
    const float* fc1_b  = (const float*)d_in[11];
    const float* fc2_w  = (const float*)d_in[12];
    const float* fc2_b  = (const float*)d_in[13];
    const float* fns    = (const float*)d_in[14];
    const float* fnb    = (const float*)d_in[15];
    const float* head_w = (const float*)d_in[16];
    const float* head_b = (const float*)d_in[17];
    float* out = (float*)d_out;

    float *h, *pool, *pln;
    h16 *imh,*yh,*qkvh,*vth,*aoh,*mlph;
    h16 *cwh,*cwl,*qwh,*owh,*w1h,*w2h;
    cudaGetSymbolAddress((void**)&h,    g_h);
    cudaGetSymbolAddress((void**)&pool, g_pool);
    cudaGetSymbolAddress((void**)&pln,  g_pln);
    cudaGetSymbolAddress((void**)&imh,  g_imh);
    cudaGetSymbolAddress((void**)&yh,   g_yh);
    cudaGetSymbolAddress((void**)&qkvh, g_qkvh);
    cudaGetSymbolAddress((void**)&vth,  g_vth);
    cudaGetSymbolAddress((void**)&aoh,  g_aoh);
    cudaGetSymbolAddress((void**)&mlph, g_mlph);
    cudaGetSymbolAddress((void**)&cwh,  g_cwh);   cudaGetSymbolAddress((void**)&cwl, g_cwl);
    cudaGetSymbolAddress((void**)&qwh,  g_qwh);
    cudaGetSymbolAddress((void**)&owh,  g_owh);
    cudaGetSymbolAddress((void**)&w1h,  g_w1h);
    cudaGetSymbolAddress((void**)&w2h,  g_w2h);

    cudaFuncSetAttribute(mma14_gemm<1,0,2,64 >, cudaFuncAttributeMaxDynamicSharedMemorySize, DSZ(2,64));
    cudaFuncSetAttribute(mma14_gemm<0,1,1,128>, cudaFuncAttributeMaxDynamicSharedMemorySize, DSZ(1,128));
    cudaFuncSetAttribute(mma14_gemm<4,0,1,64 >, cudaFuncAttributeMaxDynamicSharedMemorySize, DSZ(1,64));
    cudaFuncSetAttribute(mma14_gemm<2,1,1,128>, cudaFuncAttributeMaxDynamicSharedMemorySize, DSZ(1,128));
    cudaFuncSetAttribute(flash_kernel, cudaFuncAttributeMaxDynamicSharedMemorySize, F_SMEM);

    // ---- weight prep ----
    {
        long long n;
        n = (long long)EMBED*KPATCH;
        split_kernel<<<(int)((n/4+255)/256),256>>>(conv_w, cwh, cwl, n);
        n = (long long)DEPTH*3*EMBED*EMBED;
        tohalf_kernel<<<(int)((n/4+255)/256),256>>>(qkv_w, qwh, n);
        n = (long long)DEPTH*EMBED*EMBED;
        tohalf_kernel<<<(int)((n/4+255)/256),256>>>(out_w, owh, n);
        n = (long long)DEPTH*MLPH*EMBED;
        tohalf_kernel<<<(int)((n/4+255)/256),256>>>(fc1_w, w1h, n);
        n = (long long)DEPTH*EMBED*MLPH;
        tohalf_kernel<<<(int)((n/4+255)/256),256>>>(fc2_w, w2h, n);
    }

    // ---- patch embed ----
    im2col_kernel<<<(int)(((long long)NTOK*KPATCH + 255)/256), 256>>>(x);
    {
        dim3 g(EMBED/64, (NTOK+127)/128, 1);
        mma14_gemm<1,0,2,64><<<g,256,DSZ(2,64)>>>(
            imh, cwh, cwl, conv_b, nullptr, h, nullptr,
            NTOK, EMBED, KPATCH, KPATCH, KPATCH, EMBED, 0);
    }
    freq_kernel<<<1, EMBED/2>>>();
    posadd_kernel<<<(NP*EMBED + 255)/256, 256>>>();

    // ---- transformer blocks ----
    for (int l = 0; l < DEPTH; l++) {
        h16* lqwh = qwh + (long long)l*3*EMBED*EMBED;
        h16* lowh = owh + (long long)l*EMBED*EMBED;
        h16* lw1h = w1h + (long long)l*MLPH*EMBED;
        h16* lw2h = w2h + (long long)l*EMBED*MLPH;
        const float* ob = out_b + (long long)l*EMBED;
        const float* b1 = fc1_b + (long long)l*MLPH;
        const float* b2 = fc2_b + (long long)l*EMBED;

        ln_kernel<<<NTOK,256>>>(h, n1s + l*EMBED, n1b + l*EMBED, nullptr, yh, EMBED);

        {   // qkv = y @ qw^T  (1-term) -> fp16 hi
            dim3 g((3*EMBED)/128, (NTOK+127)/128, 1);
            mma14_gemm<0,1,1,128><<<g,256,DSZ(1,128)>>>(
                yh, lqwh, nullptr, nullptr, nullptr, nullptr, qkvh,
                NTOK, 3*EMBED, EMBED, EMBED, EMBED, 3*EMBED, 0);
        }

        {   // V^T per (b,h)
            dim3 g(NP/32, BATCH*HEADS, 1);
            vtrans_kernel<<<g,256>>>(qkvh, vth);
        }

        {   // fused attention: ao = softmax(Q K^T) V
            dim3 g(1, FT, BATCH*HEADS);
            flash_kernel<<<g,256,F_SMEM>>>(qkvh, vth, aoh);
        }

        {   // h = h + ao @ ow^T + ob  (1-term)
            dim3 g(EMBED/64, (NTOK+127)/128, 1);
            mma14_gemm<4,0,1,64><<<g,256,DSZ(1,64)>>>(
                aoh, lowh, nullptr, ob, h, h, nullptr,
                NTOK, EMBED, EMBED, EMBED, EMBED, EMBED, EMBED);
        }

        ln_kernel<<<NTOK,256>>>(h, n2s + l*EMBED, n2b + l*EMBED, nullptr, yh, EMBED);

        {   // mlp = gelu(y @ w1^T + b1)  (1-term)
            dim3 g(MLPH/128, (NTOK+127)/128, 1);
            mma14_gemm<2,1,1,128><<<g,256,DSZ(1,128)>>>(
                yh, lw1h, nullptr, b1, nullptr, nullptr, mlph,
                NTOK, MLPH, EMBED, EMBED, EMBED, MLPH, 0);
        }

        {   // h = h + mlp @ w2^T + b2  (1-term)
            dim3 g(EMBED/64, (NTOK+127)/128, 1);
            mma14_gemm<4,0,1,64><<<g,256,DSZ(1,64)>>>(
                mlph, lw2h, nullptr, b2, h, h, nullptr,
                NTOK, EMBED, MLPH, MLPH, MLPH, EMBED, EMBED);
        }
    }

    // ---- pooled head ----
    {
        dim3 g(EMBED/128, BATCH);
        pool_kernel<<<g,256>>>();
    }
    ln_kernel<<<BATCH,256>>>(pool, fns, fnb, pln, nullptr, EMBED);
    head_kernel<<<(BATCH*1000*32 + 255)/256, 256>>>(head_w, head_b, out);
}

// round 15
// speedup vs baseline: 2.6866x; 1.0106x over previous
#include <cuda_runtime.h>
#include <cuda_fp16.h>
#include <math.h>
#include <stdint.h>

#define EMBED   768
#define HEADS   8
#define HDIM    96
#define DEPTH   12
#define MLPH    3072
#define NP      1568
#define BATCH   2
#define NTOK    (BATCH*NP)      // 3136
#define KPATCH  1536

typedef __half h16;

// ---------------- scratch (device globals: allocation-free) ----------------
__device__ __align__(256) h16   g_imh [NTOK*KPATCH];
__device__ __align__(256) float g_h   [NTOK*EMBED];
__device__ __align__(256) h16   g_yh  [NTOK*EMBED];
__device__ __align__(256) h16   g_qkvh[NTOK*3*EMBED];
__device__ __align__(256) h16   g_vth [16*HDIM*NP];   // V^T per (b,h): [96][1568]
__device__ __align__(256) h16   g_aoh [NTOK*EMBED];
__device__ __align__(256) h16   g_mlph[NTOK*MLPH];
__device__ float g_pool[BATCH*EMBED];
__device__ float g_pln [BATCH*EMBED];
__device__ double g_freq[EMBED/2];
// weights: all hi-only fp16 (1-term)
__device__ __align__(256) h16 g_cwh[EMBED*KPATCH];
__device__ __align__(256) h16 g_qwh[DEPTH*3*EMBED*EMBED];
__device__ __align__(256) h16 g_owh[DEPTH*EMBED*EMBED];
__device__ __align__(256) h16 g_w1h[DEPTH*MLPH*EMBED];
__device__ __align__(256) h16 g_w2h[DEPTH*EMBED*MLPH];

#define LDSM4(R, addr) \
    asm volatile("ldmatrix.sync.aligned.m8n8.x4.shared.b16 {%0,%1,%2,%3},[%4];" \
        : "=r"((R)[0]), "=r"((R)[1]), "=r"((R)[2]), "=r"((R)[3]) : "r"(addr))

#define MMA_F32(C, A, B0, B1) \
    asm volatile("mma.sync.aligned.m16n8k16.row.col.f32.f16.f16.f32 " \
        "{%0,%1,%2,%3},{%4,%5,%6,%7},{%8,%9},{%0,%1,%2,%3};" \
        : "+f"((C)[0]), "+f"((C)[1]), "+f"((C)[2]), "+f"((C)[3]) \
        : "r"((A)[0]), "r"((A)[1]), "r"((A)[2]), "r"((A)[3]), "r"(B0), "r"(B1))

__device__ __forceinline__ void cpa16(uint32_t dst, const void* src, bool p)
{
    int sz = p ? 16 : 0;
    asm volatile("cp.async.cg.shared.global [%0],[%1],16,%2;\n"
                 :: "r"(dst), "l"(src), "r"(sz));
}

// ================= GEMM: fp16 1-term, 3-stage cp.async =====================
#define BK 32
#define SA 40

template<int EPI, int OUT, int BNT>
__global__ void __launch_bounds__(256)
mma15_gemm(const h16* __restrict__ Agh, const h16* __restrict__ Bgh,
           const float* __restrict__ bias, const float* __restrict__ R,
           float* __restrict__ Cf, h16* __restrict__ Ch,
           int M, int N, int K, int lda, int ldb, int ldc, int ldr)
{
    constexpr int WN    = BNT / 2;
    constexpr int NPR   = WN / 16;
    constexpr int OFFB  = 128 * SA;
    constexpr int STAGE = (128 + BNT) * SA;

    extern __shared__ __align__(16) h16 smem[];
    const uint32_t su = (uint32_t)__cvta_generic_to_shared(smem);

    const int tid  = threadIdx.x;
    const int lane = tid & 31;
    const int w    = tid >> 5;
    const int wm   = w >> 1;
    const int wn   = w & 1;
    const int m0   = blockIdx.y * 128;
    const int n0   = blockIdx.x * BNT;

    float c[2][2*NPR][4];
    #pragma unroll
    for (int i = 0; i < 2; i++)
        #pragma unroll
        for (int j = 0; j < 2*NPR; j++)
            #pragma unroll
            for (int q = 0; q < 4; q++) c[i][j][q] = 0.f;

    const int lrow = lane & 15;
    const int lcol = (lane >> 4) * 8;
    const uint32_t aoffA = (uint32_t)(((wm*32 + lrow)*SA + lcol) * 2);
    const uint32_t boffB = (uint32_t)(((wn*WN + lrow)*SA + lcol) * 2);

    const int T = K / BK;

    auto issue = [&](int t, int s) {
        const int k0 = t * BK;
        const uint32_t sb = su + (uint32_t)(s * STAGE) * 2u;
        #pragma unroll
        for (int i = 0; i < 2; i++) {
            const int ch  = (i << 8) + tid;
            const int row = ch >> 2;
            const int kc  = (ch & 3) << 3;
            const bool p  = (m0 + row) < M;
            const h16* src = Agh + (long long)(p ? (m0 + row) : 0) * lda + k0 + kc;
            cpa16(sb + (uint32_t)(row*SA + kc) * 2u, src, p);
        }
        constexpr int BTOT = BNT * 4;
        constexpr int BCH  = (BTOT + 255) / 256;
        #pragma unroll
        for (int i = 0; i < BCH; i++) {
            const int ch = i*256 + tid;
            if (BTOT % 256 != 0 && ch >= BTOT) break;
            const int row = ch >> 2;
            const int kc  = (ch & 3) << 3;
            const bool p  = (n0 + row) < N;
            const h16* src = Bgh + (long long)(p ? (n0 + row) : 0) * ldb + k0 + kc;
            cpa16(sb + (uint32_t)(OFFB + row*SA + kc) * 2u, src, p);
        }
    };

    issue(0, 0);
    asm volatile("cp.async.commit_group;");
    if (T > 1) { issue(1, 1); asm volatile("cp.async.commit_group;"); }

    for (int t = 0; t < T; t++) {
        if (t + 1 < T) asm volatile("cp.async.wait_group 1;");
        else           asm volatile("cp.async.wait_group 0;");
        __syncthreads();

        if (t + 2 < T) {
            issue(t + 2, (t + 2) % 3);
            asm volatile("cp.async.commit_group;");
        }

        const int s = t % 3;
        const uint32_t sb  = su + (uint32_t)(s * STAGE) * 2u;
        const uint32_t aHb = sb + aoffA;
        const uint32_t bHb = sb + (uint32_t)OFFB * 2u + boffB;

        #pragma unroll
        for (int kk2 = 0; kk2 < 2; kk2++) {
            const uint32_t kb = (uint32_t)(kk2 * 32);
            uint32_t Ahf[2][4], Bhf[NPR][4];
            #pragma unroll
            for (int mi = 0; mi < 2; mi++)
                LDSM4(Ahf[mi], aHb + (uint32_t)(mi*16*SA*2) + kb);
            #pragma unroll
            for (int pr = 0; pr < NPR; pr++)
                LDSM4(Bhf[pr], bHb + (uint32_t)(pr*16*SA*2) + kb);
            #pragma unroll
            for (int mi = 0; mi < 2; mi++)
                #pragma unroll
                for (int pr = 0; pr < NPR; pr++) {
                    MMA_F32(c[mi][2*pr  ], Ahf[mi], Bhf[pr][0], Bhf[pr][2]);
                    MMA_F32(c[mi][2*pr+1], Ahf[mi], Bhf[pr][1], Bhf[pr][3]);
                }
        }
    }

    const int g  = lane >> 2;
    const int tq = lane & 3;
    #pragma unroll
    for (int mi = 0; mi < 2; mi++) {
        #pragma unroll
        for (int nf = 0; nf < 2*NPR; nf++) {
            int col = n0 + wn*WN + nf*8 + tq*2;
            #pragma unroll
            for (int half = 0; half < 2; half++) {
                int row = m0 + wm*32 + mi*16 + g + half*8;
                if (row >= M || col >= N) continue;
                float v0 = c[mi][nf][half*2 + 0];
                float v1 = c[mi][nf][half*2 + 1];
                if (EPI == 1 || EPI == 2 || EPI == 4) { v0 += bias[col]; v1 += bias[col+1]; }
                if (EPI == 2) {
                    v0 = 0.5f * v0 * (1.0f + erff(v0 * 0.70710678118654752f));
                    v1 = 0.5f * v1 * (1.0f + erff(v1 * 0.70710678118654752f));
                }
                if (EPI >= 3) {
                    float2 r2 = *(const float2*)&R[(long long)row*ldr + col];
                    v0 += r2.x; v1 += r2.y;
                }
                if (OUT == 0) {
                    float2 o; o.x = v0; o.y = v1;
                    *(float2*)&Cf[(long long)row*ldc + col] = o;
                } else {
                    *(__half2*)&Ch[(long long)row*ldc + col] =
                        __halves2half2(__float2half_rn(v0), __float2half_rn(v1));
                }
            }
        }
    }
}

// ================= flash attention: KT=64, 2 CTAs/SM =======================
#define QSTR 104
#define PSTR 72      // 64 keys + 8 pad; 72 == 8 mod 64 -> conflict-free ldsm
#define KTILES 25    // ceil(1568/64)
#define F_OQ  0
#define F_OK  (128*QSTR)
#define F_OVT (F_OK + 2*64*QSTR)
#define F_OP  (F_OVT + 2*96*PSTR)
#define F_ELEMS (F_OP + 128*PSTR)
#define F_SMEM (F_ELEMS*2 + 2*256*4)   // 101,376 B

__global__ void __launch_bounds__(256, 2)
flash_kernel(const h16* __restrict__ qkv, const h16* __restrict__ vt,
             h16* __restrict__ ao)
{
    extern __shared__ __align__(16) h16 smem[];
    const uint32_t su = (uint32_t)__cvta_generic_to_shared(smem);
    float* statm = (float*)(smem + F_ELEMS);
    float* stats = statm + 256;

    const int tid = threadIdx.x, lane = tid & 31, w = tid >> 5;
    const int wm = w >> 1, wn = w & 1;
    const int g = lane >> 2, tq = lane & 3;
    const int z = blockIdx.z, bb = z >> 3, hh = z & 7;
    const int m0 = blockIdx.y * 128;

    const h16* Qg  = qkv + (long long)bb*NP*(3*EMBED) + hh*HDIM;
    const h16* Kg  = Qg + EMBED;
    const h16* VTg = vt + (long long)z*HDIM*NP;
    h16* AOg = ao + (long long)bb*NP*EMBED + hh*HDIM;

    // Q tile load
    #pragma unroll
    for (int i = 0; i < 6; i++) {
        int ch = i*256 + tid;
        int row = ch / 12, c16 = ch % 12;
        bool p = (m0 + row) < NP;
        cpa16(su + (uint32_t)((F_OQ + row*QSTR + c16*8) * 2),
              Qg + (long long)(p ? (m0 + row) : 0)*(3*EMBED) + c16*8, p);
    }

    auto issueKV = [&](int t, int s) {
        const int k0 = t * 64;
        #pragma unroll
        for (int i = 0; i < 3; i++) {        // K: 64 keys x 96 dims = 768 chunks
            int ch = i*256 + tid;
            int row = ch / 12, c16 = ch % 12;
            bool p = (k0 + row) < NP;
            cpa16(su + (uint32_t)((F_OK + s*64*QSTR + row*QSTR + c16*8) * 2),
                  Kg + (long long)(p ? (k0 + row) : 0)*(3*EMBED) + c16*8, p);
        }
        #pragma unroll
        for (int i = 0; i < 3; i++) {        // VT: 96 dims x 64 keys = 768 chunks
            int ch = i*256 + tid;
            int row = ch >> 3, c16 = ch & 7;
            bool p = (k0 + c16*8) < NP;
            cpa16(su + (uint32_t)((F_OVT + s*96*PSTR + row*PSTR + c16*8) * 2),
                  VTg + (long long)row*NP + (p ? (k0 + c16*8) : 0), p);
        }
    };

    issueKV(0, 0);
    asm volatile("cp.async.commit_group;");

    const int lrow = lane & 15;
    const int lcol = (lane >> 4) * 8;
    const uint32_t qoff  = su + (uint32_t)((F_OQ + (wm*32 + lrow)*QSTR + lcol) * 2);
    const uint32_t poffA = su + (uint32_t)((F_OP + (wm*32 + lrow)*PSTR + lcol) * 2);
    const int rbase = wm*32 + g;

    float o[2][6][4];
    float m_run[2][2], l_run[2][2], scl[2][2];
    #pragma unroll
    for (int mi = 0; mi < 2; mi++) {
        #pragma unroll
        for (int nf = 0; nf < 6; nf++)
            #pragma unroll
            for (int q = 0; q < 4; q++) o[mi][nf][q] = 0.f;
        m_run[mi][0] = m_run[mi][1] = -1e30f;
        l_run[mi][0] = l_run[mi][1] = 0.f;
    }

    for (int t = 0; t < KTILES; t++) {
        asm volatile("cp.async.wait_group 0;");
        __syncthreads();
        if (t + 1 < KTILES) {
            issueKV(t + 1, (t + 1) & 1);
            asm volatile("cp.async.commit_group;");
        }

        const int s = t & 1;
        const uint32_t koff  = su + (uint32_t)((F_OK + s*64*QSTR + (wn*32 + lrow)*QSTR + lcol) * 2);
        const uint32_t vtoff = su + (uint32_t)((F_OVT + s*96*PSTR + (wn*48 + lrow)*PSTR + lcol) * 2);

        // ---- S = Q @ K^T (128x64) ----
        float c[2][4][4];
        #pragma unroll
        for (int mi = 0; mi < 2; mi++)
            #pragma unroll
            for (int nf = 0; nf < 4; nf++)
                #pragma unroll
                for (int q = 0; q < 4; q++) c[mi][nf][q] = 0.f;
        #pragma unroll
        for (int kci = 0; kci < 6; kci++) {
            const uint32_t kb = (uint32_t)(kci * 32);
            uint32_t Af[2][4], Bf[2][4];
            LDSM4(Af[0], qoff + kb);
            LDSM4(Af[1], qoff + (uint32_t)(16*QSTR*2) + kb);
            LDSM4(Bf[0], koff + kb);
            LDSM4(Bf[1], koff + (uint32_t)(16*QSTR*2) + kb);
            #pragma unroll
            for (int mi = 0; mi < 2; mi++)
                #pragma unroll
                for (int pr = 0; pr < 2; pr++) {
                    MMA_F32(c[mi][2*pr  ], Af[mi], Bf[pr][0], Bf[pr][2]);
                    MMA_F32(c[mi][2*pr+1], Af[mi], Bf[pr][1], Bf[pr][3]);
                }
        }
        // ---- mask invalid keys (last tile) ----
        if (t == KTILES - 1) {
            #pragma unroll
            for (int nf = 0; nf < 4; nf++) {
                int col0 = t*64 + wn*32 + nf*8 + tq*2;
                if (col0 >= NP)     { c[0][nf][0]=c[0][nf][2]=c[1][nf][0]=c[1][nf][2]=-1e30f; }
                if (col0 + 1 >= NP) { c[0][nf][1]=c[0][nf][3]=c[1][nf][1]=c[1][nf][3]=-1e30f; }
            }
        }
        // ---- phase 1: warp-slice row max ----
        #pragma unroll
        for (int mi = 0; mi < 2; mi++)
            #pragma unroll
            for (int qh = 0; qh < 2; qh++) {
                float v = -1e30f;
                #pragma unroll
                for (int nf = 0; nf < 4; nf++)
                    v = fmaxf(v, fmaxf(c[mi][nf][qh*2], c[mi][nf][qh*2+1]));
                v = fmaxf(v, __shfl_xor_sync(0xffffffffu, v, 1));
                v = fmaxf(v, __shfl_xor_sync(0xffffffffu, v, 2));
                if (tq == 0) statm[(rbase + mi*16 + qh*8)*2 + wn] = v;
            }
        __syncthreads();
        // ---- phase 2: new max, rescale O, p = exp(s-m), sums, store P ----
        #pragma unroll
        for (int mi = 0; mi < 2; mi++)
            #pragma unroll
            for (int qh = 0; qh < 2; qh++) {
                const int r = rbase + mi*16 + qh*8;
                float tm = fmaxf(statm[r*2], statm[r*2+1]);
                float mn = fmaxf(m_run[mi][qh], tm);
                float sc = __expf(m_run[mi][qh] - mn);
                m_run[mi][qh] = mn; scl[mi][qh] = sc;
                #pragma unroll
                for (int nf = 0; nf < 6; nf++) {
                    o[mi][nf][qh*2  ] *= sc;
                    o[mi][nf][qh*2+1] *= sc;
                }
                float ps = 0.f;
                #pragma unroll
                for (int nf = 0; nf < 4; nf++) {
                    float p0 = __expf(c[mi][nf][qh*2  ] - mn);
                    float p1 = __expf(c[mi][nf][qh*2+1] - mn);
                    ps += p0 + p1;
                    *(__half2*)(smem + F_OP + (wm*32 + mi*16 + g + qh*8)*PSTR
                                + wn*32 + nf*8 + tq*2) =
                        __halves2half2(__float2half_rn(p0), __float2half_rn(p1));
                }
                ps += __shfl_xor_sync(0xffffffffu, ps, 1);
                ps += __shfl_xor_sync(0xffffffffu, ps, 2);
                if (tq == 0) stats[r*2 + wn] = ps;
            }
        __syncthreads();
        // ---- phase 3: update l; O += P @ VT^T ----
        #pragma unroll
        for (int mi = 0; mi < 2; mi++)
            #pragma unroll
            for (int qh = 0; qh < 2; qh++) {
                const int r = rbase + mi*16 + qh*8;
                l_run[mi][qh] = l_run[mi][qh]*scl[mi][qh] + stats[r*2] + stats[r*2+1];
            }
        #pragma unroll
        for (int kci = 0; kci < 4; kci++) {
            const uint32_t kb = (uint32_t)(kci * 32);
            uint32_t Af[2][4], Bf[3][4];
            LDSM4(Af[0], poffA + kb);
            LDSM4(Af[1], poffA + (uint32_t)(16*PSTR*2) + kb);
            #pragma unroll
            for (int pr = 0; pr < 3; pr++)
                LDSM4(Bf[pr], vtoff + (uint32_t)(pr*16*PSTR*2) + kb);
            #pragma unroll
            for (int mi = 0; mi < 2; mi++)
                #pragma unroll
                for (int pr = 0; pr < 3; pr++) {
                    MMA_F32(o[mi][2*pr  ], Af[mi], Bf[pr][0], Bf[pr][2]);
                    MMA_F32(o[mi][2*pr+1], Af[mi], Bf[pr][1], Bf[pr][3]);
                }
        }
    }

    // ---- epilogue: ao = O / l ----
    #pragma unroll
    for (int mi = 0; mi < 2; mi++)
        #pragma unroll
        for (int qh = 0; qh < 2; qh++) {
            const int row = m0 + rbase + mi*16 + qh*8;
            if (row >= NP) continue;
            const float inv = 1.0f / l_run[mi][qh];
            #pragma unroll
            for (int nf = 0; nf < 6; nf++) {
                const int col = wn*48 + nf*8 + tq*2;
                float v0 = o[mi][nf][qh*2  ] * inv;
                float v1 = o[mi][nf][qh*2+1] * inv;
                *(__half2*)&AOg[(long long)row*EMBED + col] =
                    __halves2half2(__float2half_rn(v0), __float2half_rn(v1));
            }
        }
}

// ---------------- V transpose (hi only): VT[z][n][k] = V[z][k][n] ----------
__global__ void vtrans_kernel(const h16* __restrict__ qh, h16* __restrict__ vth)
{
    __shared__ h16 th[32][100];
    const int z = blockIdx.y, bb = z >> 3, hh = z & 7;
    const int k0 = blockIdx.x * 32;
    const int tid = threadIdx.x;
    const h16* sh = qh + ((long long)(bb*NP) + k0)*(3*EMBED) + 2*EMBED + hh*HDIM;
    for (int idx = tid; idx < 32*HDIM; idx += 256) {
        int kk = idx / HDIM, nn = idx % HDIM;
        th[kk][nn] = sh[(long long)kk*(3*EMBED) + nn];
    }
    __syncthreads();
    h16* dh = vth + (long long)z*HDIM*NP + k0;
    for (int idx = tid; idx < 32*HDIM; idx += 256) {
        int nn = idx >> 5, kk = idx & 31;
        dh[(long long)nn*NP + kk] = th[kk][nn];
    }
}

// ---------------- fp32 -> fp16 convert (hi only) ----------
__global__ void tohalf_kernel(const float* __restrict__ s, h16* __restrict__ h,
                              long long n)
{
    long long i = ((long long)blockIdx.x*256 + threadIdx.x)*4;
    if (i >= n) return;
    float4 v = *(const float4*)&s[i];
    *(__half2*)&h[i  ] = __halves2half2(__float2half_rn(v.x), __float2half_rn(v.y));
    *(__half2*)&h[i+2] = __halves2half2(__float2half_rn(v.z), __float2half_rn(v.w));
}

// ---------------- layernorm (fp32 out OR fp16-hi out) ----------------
__global__ void ln_kernel(const float* __restrict__ X, const float* __restrict__ sc,
                          const float* __restrict__ bi, float* __restrict__ Yf,
                          h16* __restrict__ Yh, int Cn)
{
    const float* x = X + (long long)blockIdx.x * Cn;
    __shared__ float sh1[32], sh2[32];
    int tid = threadIdx.x;
    float s = 0.f, s2 = 0.f;
    for (int i = tid; i < Cn; i += 256) { float v = x[i]; s += v; s2 += v*v; }
    #pragma unroll
    for (int o = 16; o > 0; o >>= 1) {
        s  += __shfl_xor_sync(0xffffffffu, s,  o);
        s2 += __shfl_xor_sync(0xffffffffu, s2, o);
    }
    if ((tid & 31) == 0) { sh1[tid>>5] = s; sh2[tid>>5] = s2; }
    __syncthreads();
    if (tid < 32) {
        float a = (tid < 8) ? sh1[tid] : 0.f;
        float b = (tid < 8) ? sh2[tid] : 0.f;
        #pragma unroll
        for (int o = 4; o > 0; o >>= 1) {
            a += __shfl_xor_sync(0xffffffffu, a, o);
            b += __shfl_xor_sync(0xffffffffu, b, o);
        }
        if (tid == 0) { sh1[0] = a; sh2[0] = b; }
    }
    __syncthreads();
    float mean = sh1[0] / Cn;
    float var  = sh2[0] / Cn - mean*mean;
    float inv  = rsqrtf(var + 1e-5f);
    for (int i = tid; i < Cn; i += 256) {
        float v = (x[i] - mean) * inv * sc[i] + bi[i];
        if (Yf) Yf[(long long)blockIdx.x*Cn + i] = v;
        else    Yh[(long long)blockIdx.x*Cn + i] = __float2half_rn(v);
    }
}

// ---------------- im2col (writes fp16 hi only) ----------------
__global__ void im2col_kernel(const float* __restrict__ x)
{
    long long idx = (long long)blockIdx.x * 256 + threadIdx.x;
    if (idx >= (long long)NTOK * KPATCH) return;
    int j = (int)(idx % KPATCH);
    int m = (int)(idx / KPATCH);
    int b = m / NP, n = m % NP;
    int t = n / 196, r = n % 196, yy = r / 14, xx = r % 14;
    int i  = j / 512, r2 = j % 512;
    int dt = r2 / 256, r3 = r2 % 256;
    int dy = r3 / 16,  dx = r3 % 16;
    long long off = ((((long long)(b*3 + i)*16 + (2*t + dt))*224) + (16*yy + dy))*224 + (16*xx + dx);
    g_imh[idx] = __float2half_rn(x[off]);
}

// ---------------- positional encoding ----------------
__global__ void freq_kernel()
{
    int c2 = threadIdx.x;
    if (c2 < EMBED/2) g_freq[c2] = pow(10000.0, -2.0 * c2 / (double)EMBED);
}
__global__ void posadd_kernel()
{
    int idx = blockIdx.x * 256 + threadIdx.x;
    if (idx >= NP*EMBED) return;
    int n = idx / EMBED, c = idx % EMBED;
    double a = (double)n * g_freq[c >> 1];
    const double TWO_PI = 6.283185307179586476925286766559;
    int k = (int)(a * (1.0 / TWO_PI) + 0.5);
    float rf = (float)(a - (double)k * TWO_PI);
    float v = (c & 1) ? cosf(rf) : sinf(rf);
    g_h[idx]            += v;
    g_h[idx + NP*EMBED] += v;
}

// ---------------- mean pool: coalesced block reduce ----------------
__global__ void pool_kernel()
{
    __shared__ float acc[2][128];
    const int b  = blockIdx.y;
    const int c0 = blockIdx.x * 128;
    const int tg = threadIdx.x >> 7;
    const int c  = threadIdx.x & 127;
    const float* base = g_h + (long long)b*NP*EMBED + c0 + c;
    float s = 0.f;
    for (int n = tg; n < NP; n += 2)
        s += base[(long long)n*EMBED];
    acc[tg][c] = s;
    __syncthreads();
    if (tg == 0)
        g_pool[b*EMBED + c0 + c] = (acc[0][c] + acc[1][c]) * (1.0f / NP);
}

// ---------------- classifier head ----------------
__global__ void head_kernel(const float* __restrict__ W, const float* __restrict__ hb,
                            float* __restrict__ out)
{
    int g = blockIdx.x * 256 + threadIdx.x;
    int warp = g >> 5, lane = g & 31;
    if (warp >= BATCH*1000) return;
    int b = warp / 1000, j = warp % 1000;
    float s = 0.f;
    for (int c = lane; c < EMBED; c += 32)
        s += g_pln[b*EMBED + c] * W[j*EMBED + c];
    #pragma unroll
    for (int o = 16; o > 0; o >>= 1) s += __shfl_xor_sync(0xffffffffu, s, o);
    if (lane == 0) out[warp] = s + hb[j];
}

// ---------------- host orchestration ----------------
#define DSZ(bnt) ((128 + (bnt))*SA*2*3)

extern "C" void kernel_launch(void* const* d_in, const int* in_sizes, int n_in,
                              void* d_out, int out_size)
{
    const float* x      = (const float*)d_in[0];
    const float* conv_w = (const float*)d_in[1];
    const float* conv_b = (const float*)d_in[2];
    const float* n1s    = (const float*)d_in[3];
    const float* n1b    = (const float*)d_in[4];
    const float* qkv_w  = (const float*)d_in[5];
    const float* out_w  = (const float*)d_in[6];
    const float* out_b  = (const float*)d_in[7];
    const float* n2s    = (const float*)d_in[8];
    const float* n2b    = (const float*)d_in[9];
    const float* fc1_w  = (const float*)d_in[10];
    const float* fc1_b  = (const float*)d_in[11];
    const float* fc2_w  = (const float*)d_in[12];
    const float* fc2_b  = (const float*)d_in[13];
    const float* fns    = (const float*)d_in[14];
    const float* fnb    = (const float*)d_in[15];
    const float* head_w = (const float*)d_in[16];
    const float* head_b = (const float*)d_in[17];
    float* out = (float*)d_out;

    float *h, *pool, *pln;
    h16 *imh,*yh,*qkvh,*vth,*aoh,*mlph;
    h16 *cwh,*qwh,*owh,*w1h,*w2h;
    cudaGetSymbolAddress((void**)&h,    g_h);
    cudaGetSymbolAddress((void**)&pool, g_pool);
    cudaGetSymbolAddress((void**)&pln,  g_pln);
    cudaGetSymbolAddress((void**)&imh,  g_imh);
    cudaGetSymbolAddress((void**)&yh,   g_yh);
    cudaGetSymbolAddress((void**)&qkvh, g_qkvh);
    cudaGetSymbolAddress((void**)&vth,  g_vth);
    cudaGetSymbolAddress((void**)&aoh,  g_aoh);
    cudaGetSymbolAddress((void**)&mlph, g_mlph);
    cudaGetSymbolAddress((void**)&cwh,  g_cwh);
    cudaGetSymbolAddress((void**)&qwh,  g_qwh);
    cudaGetSymbolAddress((void**)&owh,  g_owh);
    cudaGetSymbolAddress((void**)&w1h,  g_w1h);
    cudaGetSymbolAddress((void**)&w2h,  g_w2h);

    cudaFuncSetAttribute(mma15_gemm<1,0,64 >, cudaFuncAttributeMaxDynamicSharedMemorySize, DSZ(64));
    cudaFuncSetAttribute(mma15_gemm<0,1,128>, cudaFuncAttributeMaxDynamicSharedMemorySize, DSZ(128));
    cudaFuncSetAttribute(mma15_gemm<4,0,64 >, cudaFuncAttributeMaxDynamicSharedMemorySize, DSZ(64));
    cudaFuncSetAttribute(mma15_gemm<2,1,128>, cudaFuncAttributeMaxDynamicSharedMemorySize, DSZ(128));
    cudaFuncSetAttribute(flash_kernel, cudaFuncAttributeMaxDynamicSharedMemorySize, F_SMEM);

    // ---- weight prep (all fp16 hi) ----
    {
        long long n;
        n = (long long)EMBED*KPATCH;
        tohalf_kernel<<<(int)((n/4+255)/256),256>>>(conv_w, cwh, n);
        n = (long long)DEPTH*3*EMBED*EMBED;
        tohalf_kernel<<<(int)((n/4+255)/256),256>>>(qkv_w, qwh, n);
        n = (long long)DEPTH*EMBED*EMBED;
        tohalf_kernel<<<(int)((n/4+255)/256),256>>>(out_w, owh, n);
        n = (long long)DEPTH*MLPH*EMBED;
        tohalf_kernel<<<(int)((n/4+255)/256),256>>>(fc1_w, w1h, n);
        n = (long long)DEPTH*EMBED*MLPH;
        tohalf_kernel<<<(int)((n/4+255)/256),256>>>(fc2_w, w2h, n);
    }

    // ---- patch embed ----
    im2col_kernel<<<(int)(((long long)NTOK*KPATCH + 255)/256), 256>>>(x);
    {
        dim3 g(EMBED/64, (NTOK+127)/128, 1);
        mma15_gemm<1,0,64><<<g,256,DSZ(64)>>>(
            imh, cwh, conv_b, nullptr, h, nullptr,
            NTOK, EMBED, KPATCH, KPATCH, KPATCH, EMBED, 0);
    }
    freq_kernel<<<1, EMBED/2>>>();
    posadd_kernel<<<(NP*EMBED + 255)/256, 256>>>();

    // ---- transformer blocks ----
    for (int l = 0; l < DEPTH; l++) {
        h16* lqwh = qwh + (long long)l*3*EMBED*EMBED;
        h16* lowh = owh + (long long)l*EMBED*EMBED;
        h16* lw1h = w1h + (long long)l*MLPH*EMBED;
        h16* lw2h = w2h + (long long)l*EMBED*MLPH;
        const float* ob = out_b + (long long)l*EMBED;
        const float* b1 = fc1_b + (long long)l*MLPH;
        const float* b2 = fc2_b + (long long)l*EMBED;

        ln_kernel<<<NTOK,256>>>(h, n1s + l*EMBED, n1b + l*EMBED, nullptr, yh, EMBED);

        {   // qkv = y @ qw^T
            dim3 g((3*EMBED)/128, (NTOK+127)/128, 1);
            mma15_gemm<0,1,128><<<g,256,DSZ(128)>>>(
                yh, lqwh, nullptr, nullptr, nullptr, qkvh,
                NTOK, 3*EMBED, EMBED, EMBED, EMBED, 3*EMBED, 0);
        }

        {   // V^T per (b,h)
            dim3 g(NP/32, BATCH*HEADS, 1);
            vtrans_kernel<<<g,256>>>(qkvh, vth);
        }

        {   // fused attention
            dim3 g(1, 13, BATCH*HEADS);
            flash_kernel<<<g,256,F_SMEM>>>(qkvh, vth, aoh);
        }

        {   // h = h + ao @ ow^T + ob
            dim3 g(EMBED/64, (NTOK+127)/128, 1);
            mma15_gemm<4,0,64><<<g,256,DSZ(64)>>>(
                aoh, lowh, ob, h, h, nullptr,
                NTOK, EMBED, EMBED, EMBED, EMBED, EMBED, EMBED);
        }

        ln_kernel<<<NTOK,256>>>(h, n2s + l*EMBED, n2b + l*EMBED, nullptr, yh, EMBED);

        {   // mlp = gelu(y @ w1^T + b1)
            dim3 g(MLPH/128, (NTOK+127)/128, 1);
            mma15_gemm<2,1,128><<<g,256,DSZ(128)>>>(
                yh, lw1h, b1, nullptr, nullptr, mlph,
                NTOK, MLPH, EMBED, EMBED, EMBED, MLPH, 0);
        }

        {   // h = h + mlp @ w2^T + b2
            dim3 g(EMBED/64, (NTOK+127)/128, 1);
            mma15_gemm<4,0,64><<<g,256,DSZ(64)>>>(
                mlph, lw2h, b2, h, h, nullptr,
                NTOK, EMBED, MLPH, MLPH, MLPH, EMBED, EMBED);
        }
    }

    // ---- pooled head ----
    {
        dim3 g(EMBED/128, BATCH);
        pool_kernel<<<g,256>>>();
    }
    ln_kernel<<<BATCH,256>>>(pool, fns, fnb, pln, nullptr, EMBED);
    head_kernel<<<(BATCH*1000*32 + 255)/256, 256>>>(head_w, head_b, out);
}

// round 16
// speedup vs baseline: 2.8352x; 1.0553x over previous
#include <cuda_runtime.h>
#include <cuda_fp16.h>
#include <math.h>
#include <stdint.h>

#define EMBED   768
#define HEADS   8
#define HDIM    96
#define DEPTH   12
#define MLPH    3072
#define NP      1568
#define BATCH   2
#define NTOK    (BATCH*NP)      // 3136
#define KPATCH  1536

typedef __half h16;

// ---------------- scratch (device globals: allocation-free) ----------------
__device__ __align__(256) h16   g_imh [NTOK*KPATCH];
__device__ __align__(256) float g_h   [NTOK*EMBED];
__device__ __align__(256) h16   g_yh  [NTOK*EMBED];
__device__ __align__(256) h16   g_qkvh[NTOK*3*EMBED];
__device__ __align__(256) h16   g_aoh [NTOK*EMBED];
__device__ __align__(256) h16   g_mlph[NTOK*MLPH];
__device__ float g_pool[BATCH*EMBED];
__device__ float g_pln [BATCH*EMBED];
__device__ double g_freq[EMBED/2];
// weights: all hi-only fp16 (1-term)
__device__ __align__(256) h16 g_cwh[EMBED*KPATCH];
__device__ __align__(256) h16 g_qwh[DEPTH*3*EMBED*EMBED];
__device__ __align__(256) h16 g_owh[DEPTH*EMBED*EMBED];
__device__ __align__(256) h16 g_w1h[DEPTH*MLPH*EMBED];
__device__ __align__(256) h16 g_w2h[DEPTH*EMBED*MLPH];

#define LDSM4(R, addr) \
    asm volatile("ldmatrix.sync.aligned.m8n8.x4.shared.b16 {%0,%1,%2,%3},[%4];" \
        : "=r"((R)[0]), "=r"((R)[1]), "=r"((R)[2]), "=r"((R)[3]) : "r"(addr))

#define LDSM4T(R, addr) \
    asm volatile("ldmatrix.sync.aligned.m8n8.x4.trans.shared.b16 {%0,%1,%2,%3},[%4];" \
        : "=r"((R)[0]), "=r"((R)[1]), "=r"((R)[2]), "=r"((R)[3]) : "r"(addr))

#define MMA_F32(C, A, B0, B1) \
    asm volatile("mma.sync.aligned.m16n8k16.row.col.f32.f16.f16.f32 " \
        "{%0,%1,%2,%3},{%4,%5,%6,%7},{%8,%9},{%0,%1,%2,%3};" \
        : "+f"((C)[0]), "+f"((C)[1]), "+f"((C)[2]), "+f"((C)[3]) \
        : "r"((A)[0]), "r"((A)[1]), "r"((A)[2]), "r"((A)[3]), "r"(B0), "r"(B1))

__device__ __forceinline__ void cpa16(uint32_t dst, const void* src, bool p)
{
    int sz = p ? 16 : 0;
    asm volatile("cp.async.cg.shared.global [%0],[%1],16,%2;\n"
                 :: "r"(dst), "l"(src), "r"(sz));
}

// ================= GEMM: fp16 1-term, 3-stage cp.async =====================
#define BK 32
#define SA 40

template<int EPI, int OUT, int BNT>
__global__ void __launch_bounds__(256, (BNT == 64) ? 2 : 1)
mma16_gemm(const h16* __restrict__ Agh, const h16* __restrict__ Bgh,
           const float* __restrict__ bias, const float* __restrict__ R,
           float* __restrict__ Cf, h16* __restrict__ Ch,
           int M, int N, int K, int lda, int ldb, int ldc, int ldr)
{
    constexpr int WN    = BNT / 2;
    constexpr int NPR   = WN / 16;
    constexpr int OFFB  = 128 * SA;
    constexpr int STAGE = (128 + BNT) * SA;

    extern __shared__ __align__(16) h16 smem[];
    const uint32_t su = (uint32_t)__cvta_generic_to_shared(smem);

    const int tid  = threadIdx.x;
    const int lane = tid & 31;
    const int w    = tid >> 5;
    const int wm   = w >> 1;
    const int wn   = w & 1;
    const int m0   = blockIdx.y * 128;
    const int n0   = blockIdx.x * BNT;

    float c[2][2*NPR][4];
    #pragma unroll
    for (int i = 0; i < 2; i++)
        #pragma unroll
        for (int j = 0; j < 2*NPR; j++)
            #pragma unroll
            for (int q = 0; q < 4; q++) c[i][j][q] = 0.f;

    const int lrow = lane & 15;
    const int lcol = (lane >> 4) * 8;
    const uint32_t aoffA = (uint32_t)(((wm*32 + lrow)*SA + lcol) * 2);
    const uint32_t boffB = (uint32_t)(((wn*WN + lrow)*SA + lcol) * 2);

    const int T = K / BK;

    auto issue = [&](int t, int s) {
        const int k0 = t * BK;
        const uint32_t sb = su + (uint32_t)(s * STAGE) * 2u;
        #pragma unroll
        for (int i = 0; i < 2; i++) {
            const int ch  = (i << 8) + tid;
            const int row = ch >> 2;
            const int kc  = (ch & 3) << 3;
            const bool p  = (m0 + row) < M;
            const h16* src = Agh + (long long)(p ? (m0 + row) : 0) * lda + k0 + kc;
            cpa16(sb + (uint32_t)(row*SA + kc) * 2u, src, p);
        }
        constexpr int BTOT = BNT * 4;
        constexpr int BCH  = (BTOT + 255) / 256;
        #pragma unroll
        for (int i = 0; i < BCH; i++) {
            const int ch = i*256 + tid;
            if (BTOT % 256 != 0 && ch >= BTOT) break;
            const int row = ch >> 2;
            const int kc  = (ch & 3) << 3;
            const bool p  = (n0 + row) < N;
            const h16* src = Bgh + (long long)(p ? (n0 + row) : 0) * ldb + k0 + kc;
            cpa16(sb + (uint32_t)(OFFB + row*SA + kc) * 2u, src, p);
        }
    };

    issue(0, 0);
    asm volatile("cp.async.commit_group;");
    if (T > 1) { issue(1, 1); asm volatile("cp.async.commit_group;"); }

    for (int t = 0; t < T; t++) {
        if (t + 1 < T) asm volatile("cp.async.wait_group 1;");
        else           asm volatile("cp.async.wait_group 0;");
        __syncthreads();

        if (t + 2 < T) {
            issue(t + 2, (t + 2) % 3);
            asm volatile("cp.async.commit_group;");
        }

        const int s = t % 3;
        const uint32_t sb  = su + (uint32_t)(s * STAGE) * 2u;
        const uint32_t aHb = sb + aoffA;
        const uint32_t bHb = sb + (uint32_t)OFFB * 2u + boffB;

        #pragma unroll
        for (int kk2 = 0; kk2 < 2; kk2++) {
            const uint32_t kb = (uint32_t)(kk2 * 32);
            uint32_t Ahf[2][4], Bhf[NPR][4];
            #pragma unroll
            for (int mi = 0; mi < 2; mi++)
                LDSM4(Ahf[mi], aHb + (uint32_t)(mi*16*SA*2) + kb);
            #pragma unroll
            for (int pr = 0; pr < NPR; pr++)
                LDSM4(Bhf[pr], bHb + (uint32_t)(pr*16*SA*2) + kb);
            #pragma unroll
            for (int mi = 0; mi < 2; mi++)
                #pragma unroll
                for (int pr = 0; pr < NPR; pr++) {
                    MMA_F32(c[mi][2*pr  ], Ahf[mi], Bhf[pr][0], Bhf[pr][2]);
                    MMA_F32(c[mi][2*pr+1], Ahf[mi], Bhf[pr][1], Bhf[pr][3]);
                }
        }
    }

    const int g  = lane >> 2;
    const int tq = lane & 3;
    #pragma unroll
    for (int mi = 0; mi < 2; mi++) {
        #pragma unroll
        for (int nf = 0; nf < 2*NPR; nf++) {
            int col = n0 + wn*WN + nf*8 + tq*2;
            #pragma unroll
            for (int half = 0; half < 2; half++) {
                int row = m0 + wm*32 + mi*16 + g + half*8;
                if (row >= M || col >= N) continue;
                float v0 = c[mi][nf][half*2 + 0];
                float v1 = c[mi][nf][half*2 + 1];
                if (EPI == 1 || EPI == 2 || EPI == 4) { v0 += bias[col]; v1 += bias[col+1]; }
                if (EPI == 2) {
                    v0 = 0.5f * v0 * (1.0f + erff(v0 * 0.70710678118654752f));
                    v1 = 0.5f * v1 * (1.0f + erff(v1 * 0.70710678118654752f));
                }
                if (EPI >= 3) {
                    float2 r2 = *(const float2*)&R[(long long)row*ldr + col];
                    v0 += r2.x; v1 += r2.y;
                }
                if (OUT == 0) {
                    float2 o; o.x = v0; o.y = v1;
                    *(float2*)&Cf[(long long)row*ldc + col] = o;
                } else {
                    *(__half2*)&Ch[(long long)row*ldc + col] =
                        __halves2half2(__float2half_rn(v0), __float2half_rn(v1));
                }
            }
        }
    }
}

// ================= flash attention: KT=64, V via ldmatrix.trans ============
#define QSTR 104
#define PSTR 72
#define KTILES 25
#define F_OQ  0
#define F_OK  (128*QSTR)
#define F_OV  (F_OK + 2*64*QSTR)
#define F_OP  (F_OV + 2*64*QSTR)
#define F_ELEMS (F_OP + 128*PSTR)
#define F_SMEM (F_ELEMS*2 + 2*256*4)   // 100,352 B -> 2 CTAs/SM

__global__ void __launch_bounds__(256, 2)
flash_kernel(const h16* __restrict__ qkv, h16* __restrict__ ao)
{
    extern __shared__ __align__(16) h16 smem[];
    const uint32_t su = (uint32_t)__cvta_generic_to_shared(smem);
    float* statm = (float*)(smem + F_ELEMS);
    float* stats = statm + 256;

    const int tid = threadIdx.x, lane = tid & 31, w = tid >> 5;
    const int wm = w >> 1, wn = w & 1;
    const int g = lane >> 2, tq = lane & 3;
    const int z = blockIdx.z, bb = z >> 3, hh = z & 7;
    const int m0 = blockIdx.y * 128;

    const h16* Qg = qkv + (long long)bb*NP*(3*EMBED) + hh*HDIM;
    const h16* Kg = Qg + EMBED;
    const h16* Vg = Qg + 2*EMBED;
    h16* AOg = ao + (long long)bb*NP*EMBED + hh*HDIM;

    // Q tile load
    #pragma unroll
    for (int i = 0; i < 6; i++) {
        int ch = i*256 + tid;
        int row = ch / 12, c16 = ch % 12;
        bool p = (m0 + row) < NP;
        cpa16(su + (uint32_t)((F_OQ + row*QSTR + c16*8) * 2),
              Qg + (long long)(p ? (m0 + row) : 0)*(3*EMBED) + c16*8, p);
    }

    auto issueKV = [&](int t, int s) {
        const int k0 = t * 64;
        #pragma unroll
        for (int i = 0; i < 3; i++) {        // K: 64 keys x 96 dims
            int ch = i*256 + tid;
            int row = ch / 12, c16 = ch % 12;
            bool p = (k0 + row) < NP;
            cpa16(su + (uint32_t)((F_OK + s*64*QSTR + row*QSTR + c16*8) * 2),
                  Kg + (long long)(p ? (k0 + row) : 0)*(3*EMBED) + c16*8, p);
        }
        #pragma unroll
        for (int i = 0; i < 3; i++) {        // V: 64 keys x 96 dims (zfill OOB)
            int ch = i*256 + tid;
            int row = ch / 12, c16 = ch % 12;
            bool p = (k0 + row) < NP;
            cpa16(su + (uint32_t)((F_OV + s*64*QSTR + row*QSTR + c16*8) * 2),
                  Vg + (long long)(p ? (k0 + row) : 0)*(3*EMBED) + c16*8, p);
        }
    };

    issueKV(0, 0);
    asm volatile("cp.async.commit_group;");

    const int lrow = lane & 15;
    const int lcol = (lane >> 4) * 8;
    const uint32_t qoff  = su + (uint32_t)((F_OQ + (wm*32 + lrow)*QSTR + lcol) * 2);
    const uint32_t poffA = su + (uint32_t)((F_OP + (wm*32 + lrow)*PSTR + lcol) * 2);
    // V trans-fragment lane address: rows = keys, col-half select by lane>>3
    const int vkrow = (lane & 7) + ((lane >> 4) & 1) * 8;
    const int vncol = ((lane >> 3) & 1) * 8;
    const uint32_t voffB = su + (uint32_t)((F_OV + vkrow*QSTR + wn*48 + vncol) * 2);
    const int rbase = wm*32 + g;

    float o[2][6][4];
    float m_run[2][2], l_run[2][2], scl[2][2];
    #pragma unroll
    for (int mi = 0; mi < 2; mi++) {
        #pragma unroll
        for (int nf = 0; nf < 6; nf++)
            #pragma unroll
            for (int q = 0; q < 4; q++) o[mi][nf][q] = 0.f;
        m_run[mi][0] = m_run[mi][1] = -1e30f;
        l_run[mi][0] = l_run[mi][1] = 0.f;
    }

    for (int t = 0; t < KTILES; t++) {
        asm volatile("cp.async.wait_group 0;");
        __syncthreads();
        if (t + 1 < KTILES) {
            issueKV(t + 1, (t + 1) & 1);
            asm volatile("cp.async.commit_group;");
        }

        const int s = t & 1;
        const uint32_t koff = su + (uint32_t)((F_OK + s*64*QSTR + (wn*32 + lrow)*QSTR + lcol) * 2);
        const uint32_t voff = voffB + (uint32_t)(s*64*QSTR * 2);

        // ---- S = Q @ K^T (128x64) ----
        float c[2][4][4];
        #pragma unroll
        for (int mi = 0; mi < 2; mi++)
            #pragma unroll
            for (int nf = 0; nf < 4; nf++)
                #pragma unroll
                for (int q = 0; q < 4; q++) c[mi][nf][q] = 0.f;
        #pragma unroll
        for (int kci = 0; kci < 6; kci++) {
            const uint32_t kb = (uint32_t)(kci * 32);
            uint32_t Af[2][4], Bf[2][4];
            LDSM4(Af[0], qoff + kb);
            LDSM4(Af[1], qoff + (uint32_t)(16*QSTR*2) + kb);
            LDSM4(Bf[0], koff + kb);
            LDSM4(Bf[1], koff + (uint32_t)(16*QSTR*2) + kb);
            #pragma unroll
            for (int mi = 0; mi < 2; mi++)
                #pragma unroll
                for (int pr = 0; pr < 2; pr++) {
                    MMA_F32(c[mi][2*pr  ], Af[mi], Bf[pr][0], Bf[pr][2]);
                    MMA_F32(c[mi][2*pr+1], Af[mi], Bf[pr][1], Bf[pr][3]);
                }
        }
        // ---- mask invalid keys (last tile) ----
        if (t == KTILES - 1) {
            #pragma unroll
            for (int nf = 0; nf < 4; nf++) {
                int col0 = t*64 + wn*32 + nf*8 + tq*2;
                if (col0 >= NP)     { c[0][nf][0]=c[0][nf][2]=c[1][nf][0]=c[1][nf][2]=-1e30f; }
                if (col0 + 1 >= NP) { c[0][nf][1]=c[0][nf][3]=c[1][nf][1]=c[1][nf][3]=-1e30f; }
            }
        }
        // ---- phase 1: warp-slice row max ----
        #pragma unroll
        for (int mi = 0; mi < 2; mi++)
            #pragma unroll
            for (int qh = 0; qh < 2; qh++) {
                float v = -1e30f;
                #pragma unroll
                for (int nf = 0; nf < 4; nf++)
                    v = fmaxf(v, fmaxf(c[mi][nf][qh*2], c[mi][nf][qh*2+1]));
                v = fmaxf(v, __shfl_xor_sync(0xffffffffu, v, 1));
                v = fmaxf(v, __shfl_xor_sync(0xffffffffu, v, 2));
                if (tq == 0) statm[(rbase + mi*16 + qh*8)*2 + wn] = v;
            }
        __syncthreads();
        // ---- phase 2: new max, rescale O, p = exp(s-m), sums, store P ----
        #pragma unroll
        for (int mi = 0; mi < 2; mi++)
            #pragma unroll
            for (int qh = 0; qh < 2; qh++) {
                const int r = rbase + mi*16 + qh*8;
                float tm = fmaxf(statm[r*2], statm[r*2+1]);
                float mn = fmaxf(m_run[mi][qh], tm);
                float sc = __expf(m_run[mi][qh] - mn);
                m_run[mi][qh] = mn; scl[mi][qh] = sc;
                #pragma unroll
                for (int nf = 0; nf < 6; nf++) {
                    o[mi][nf][qh*2  ] *= sc;
                    o[mi][nf][qh*2+1] *= sc;
                }
                float ps = 0.f;
                #pragma unroll
                for (int nf = 0; nf < 4; nf++) {
                    float p0 = __expf(c[mi][nf][qh*2  ] - mn);
                    float p1 = __expf(c[mi][nf][qh*2+1] - mn);
                    ps += p0 + p1;
                    *(__half2*)(smem + F_OP + (wm*32 + mi*16 + g + qh*8)*PSTR
                                + wn*32 + nf*8 + tq*2) =
                        __halves2half2(__float2half_rn(p0), __float2half_rn(p1));
                }
                ps += __shfl_xor_sync(0xffffffffu, ps, 1);
                ps += __shfl_xor_sync(0xffffffffu, ps, 2);
                if (tq == 0) stats[r*2 + wn] = ps;
            }
        __syncthreads();
        // ---- phase 3: update l; O += P @ V (B frags via ldmatrix.trans) ----
        #pragma unroll
        for (int mi = 0; mi < 2; mi++)
            #pragma unroll
            for (int qh = 0; qh < 2; qh++) {
                const int r = rbase + mi*16 + qh*8;
                l_run[mi][qh] = l_run[mi][qh]*scl[mi][qh] + stats[r*2] + stats[r*2+1];
            }
        #pragma unroll
        for (int kci = 0; kci < 4; kci++) {
            uint32_t Af[2][4], Bf[3][4];
            LDSM4(Af[0], poffA + (uint32_t)(kci*32));
            LDSM4(Af[1], poffA + (uint32_t)(16*PSTR*2) + (uint32_t)(kci*32));
            #pragma unroll
            for (int pr = 0; pr < 3; pr++)
                LDSM4T(Bf[pr], voff + (uint32_t)((kci*16*QSTR + pr*16) * 2));
            #pragma unroll
            for (int mi = 0; mi < 2; mi++)
                #pragma unroll
                for (int pr = 0; pr < 3; pr++) {
                    MMA_F32(o[mi][2*pr  ], Af[mi], Bf[pr][0], Bf[pr][2]);
                    MMA_F32(o[mi][2*pr+1], Af[mi], Bf[pr][1], Bf[pr][3]);
                }
        }
    }

    // ---- epilogue: ao = O / l ----
    #pragma unroll
    for (int mi = 0; mi < 2; mi++)
        #pragma unroll
        for (int qh = 0; qh < 2; qh++) {
            const int row = m0 + rbase + mi*16 + qh*8;
            if (row >= NP) continue;
            const float inv = 1.0f / l_run[mi][qh];
            #pragma unroll
            for (int nf = 0; nf < 6; nf++) {
                const int col = wn*48 + nf*8 + tq*2;
                float v0 = o[mi][nf][qh*2  ] * inv;
                float v1 = o[mi][nf][qh*2+1] * inv;
                *(__half2*)&AOg[(long long)row*EMBED + col] =
                    __halves2half2(__float2half_rn(v0), __float2half_rn(v1));
            }
        }
}

// ---------------- fp32 -> fp16 convert (hi only) ----------
__global__ void tohalf_kernel(const float* __restrict__ s, h16* __restrict__ h,
                              long long n)
{
    long long i = ((long long)blockIdx.x*256 + threadIdx.x)*4;
    if (i >= n) return;
    float4 v = *(const float4*)&s[i];
    *(__half2*)&h[i  ] = __halves2half2(__float2half_rn(v.x), __float2half_rn(v.y));
    *(__half2*)&h[i+2] = __halves2half2(__float2half_rn(v.z), __float2half_rn(v.w));
}

// ---------------- layernorm (fp32 out OR fp16-hi out) ----------------
__global__ void ln_kernel(const float* __restrict__ X, const float* __restrict__ sc,
                          const float* __restrict__ bi, float* __restrict__ Yf,
                          h16* __restrict__ Yh, int Cn)
{
    const float* x = X + (long long)blockIdx.x * Cn;
    __shared__ float sh1[32], sh2[32];
    int tid = threadIdx.x;
    float s = 0.f, s2 = 0.f;
    for (int i = tid; i < Cn; i += 256) { float v = x[i]; s += v; s2 += v*v; }
    #pragma unroll
    for (int o = 16; o > 0; o >>= 1) {
        s  += __shfl_xor_sync(0xffffffffu, s,  o);
        s2 += __shfl_xor_sync(0xffffffffu, s2, o);
    }
    if ((tid & 31) == 0) { sh1[tid>>5] = s; sh2[tid>>5] = s2; }
    __syncthreads();
    if (tid < 32) {
        float a = (tid < 8) ? sh1[tid] : 0.f;
        float b = (tid < 8) ? sh2[tid] : 0.f;
        #pragma unroll
        for (int o = 4; o > 0; o >>= 1) {
            a += __shfl_xor_sync(0xffffffffu, a, o);
            b += __shfl_xor_sync(0xffffffffu, b, o);
        }
        if (tid == 0) { sh1[0] = a; sh2[0] = b; }
    }
    __syncthreads();
    float mean = sh1[0] / Cn;
    float var  = sh2[0] / Cn - mean*mean;
    float inv  = rsqrtf(var + 1e-5f);
    for (int i = tid; i < Cn; i += 256) {
        float v = (x[i] - mean) * inv * sc[i] + bi[i];
        if (Yf) Yf[(long long)blockIdx.x*Cn + i] = v;
        else    Yh[(long long)blockIdx.x*Cn + i] = __float2half_rn(v);
    }
}

// ---------------- im2col (writes fp16 hi only) ----------------
__global__ void im2col_kernel(const float* __restrict__ x)
{
    long long idx = (long long)blockIdx.x * 256 + threadIdx.x;
    if (idx >= (long long)NTOK * KPATCH) return;
    int j = (int)(idx % KPATCH);
    int m = (int)(idx / KPATCH);
    int b = m / NP, n = m % NP;
    int t = n / 196, r = n % 196, yy = r / 14, xx = r % 14;
    int i  = j / 512, r2 = j % 512;
    int dt = r2 / 256, r3 = r2 % 256;
    int dy = r3 / 16,  dx = r3 % 16;
    long long off = ((((long long)(b*3 + i)*16 + (2*t + dt))*224) + (16*yy + dy))*224 + (16*xx + dx);
    g_imh[idx] = __float2half_rn(x[off]);
}

// ---------------- positional encoding ----------------
__global__ void freq_kernel()
{
    int c2 = threadIdx.x;
    if (c2 < EMBED/2) g_freq[c2] = pow(10000.0, -2.0 * c2 / (double)EMBED);
}
__global__ void posadd_kernel()
{
    int idx = blockIdx.x * 256 + threadIdx.x;
    if (idx >= NP*EMBED) return;
    int n = idx / EMBED, c = idx % EMBED;
    double a = (double)n * g_freq[c >> 1];
    const double TWO_PI = 6.283185307179586476925286766559;
    int k = (int)(a * (1.0 / TWO_PI) + 0.5);
    float rf = (float)(a - (double)k * TWO_PI);
    float v = (c & 1) ? cosf(rf) : sinf(rf);
    g_h[idx]            += v;
    g_h[idx + NP*EMBED] += v;
}

// ---------------- mean pool: coalesced block reduce ----------------
__global__ void pool_kernel()
{
    __shared__ float acc[2][128];
    const int b  = blockIdx.y;
    const int c0 = blockIdx.x * 128;
    const int tg = threadIdx.x >> 7;
    const int c  = threadIdx.x & 127;
    const float* base = g_h + (long long)b*NP*EMBED + c0 + c;
    float s = 0.f;
    for (int n = tg; n < NP; n += 2)
        s += base[(long long)n*EMBED];
    acc[tg][c] = s;
    __syncthreads();
    if (tg == 0)
        g_pool[b*EMBED + c0 + c] = (acc[0][c] + acc[1][c]) * (1.0f / NP);
}

// ---------------- classifier head ----------------
__global__ void head_kernel(const float* __restrict__ W, const float* __restrict__ hb,
                            float* __restrict__ out)
{
    int g = blockIdx.x * 256 + threadIdx.x;
    int warp = g >> 5, lane = g & 31;
    if (warp >= BATCH*1000) return;
    int b = warp / 1000, j = warp % 1000;
    float s = 0.f;
    for (int c = lane; c < EMBED; c += 32)
        s += g_pln[b*EMBED + c] * W[j*EMBED + c];
    #pragma unroll
    for (int o = 16; o > 0; o >>= 1) s += __shfl_xor_sync(0xffffffffu, s, o);
    if (lane == 0) out[warp] = s + hb[j];
}

// ---------------- host orchestration ----------------
#define DSZ(bnt) ((128 + (bnt))*SA*2*3)

extern "C" void kernel_launch(void* const* d_in, const int* in_sizes, int n_in,
                              void* d_out, int out_size)
{
    const float* x      = (const float*)d_in[0];
    const float* conv_w = (const float*)d_in[1];
    const float* conv_b = (const float*)d_in[2];
    const float* n1s    = (const float*)d_in[3];
    const float* n1b    = (const float*)d_in[4];
    const float* qkv_w  = (const float*)d_in[5];
    const float* out_w  = (const float*)d_in[6];
    const float* out_b  = (const float*)d_in[7];
    const float* n2s    = (const float*)d_in[8];
    const float* n2b    = (const float*)d_in[9];
    const float* fc1_w  = (const float*)d_in[10];
    const float* fc1_b  = (const float*)d_in[11];
    const float* fc2_w  = (const float*)d_in[12];
    const float* fc2_b  = (const float*)d_in[13];
    const float* fns    = (const float*)d_in[14];
    const float* fnb    = (const float*)d_in[15];
    const float* head_w = (const float*)d_in[16];
    const float* head_b = (const float*)d_in[17];
    float* out = (float*)d_out;

    float *h, *pool, *pln;
    h16 *imh,*yh,*qkvh,*aoh,*mlph;
    h16 *cwh,*qwh,*owh,*w1h,*w2h;
    cudaGetSymbolAddress((void**)&h,    g_h);
    cudaGetSymbolAddress((void**)&pool, g_pool);
    cudaGetSymbolAddress((void**)&pln,  g_pln);
    cudaGetSymbolAddress((void**)&imh,  g_imh);
    cudaGetSymbolAddress((void**)&yh,   g_yh);
    cudaGetSymbolAddress((void**)&qkvh, g_qkvh);
    cudaGetSymbolAddress((void**)&aoh,  g_aoh);
    cudaGetSymbolAddress((void**)&mlph, g_mlph);
    cudaGetSymbolAddress((void**)&cwh,  g_cwh);
    cudaGetSymbolAddress((void**)&qwh,  g_qwh);
    cudaGetSymbolAddress((void**)&owh,  g_owh);
    cudaGetSymbolAddress((void**)&w1h,  g_w1h);
    cudaGetSymbolAddress((void**)&w2h,  g_w2h);

    cudaFuncSetAttribute(mma16_gemm<1,0,64 >, cudaFuncAttributeMaxDynamicSharedMemorySize, DSZ(64));
    cudaFuncSetAttribute(mma16_gemm<0,1,128>, cudaFuncAttributeMaxDynamicSharedMemorySize, DSZ(128));
    cudaFuncSetAttribute(mma16_gemm<4,0,64 >, cudaFuncAttributeMaxDynamicSharedMemorySize, DSZ(64));
    cudaFuncSetAttribute(mma16_gemm<2,1,128>, cudaFuncAttributeMaxDynamicSharedMemorySize, DSZ(128));
    cudaFuncSetAttribute(flash_kernel, cudaFuncAttributeMaxDynamicSharedMemorySize, F_SMEM);

    // ---- weight prep (all fp16 hi) ----
    {
        long long n;
        n = (long long)EMBED*KPATCH;
        tohalf_kernel<<<(int)((n/4+255)/256),256>>>(conv_w, cwh, n);
        n = (long long)DEPTH*3*EMBED*EMBED;
        tohalf_kernel<<<(int)((n/4+255)/256),256>>>(qkv_w, qwh, n);
        n = (long long)DEPTH*EMBED*EMBED;
        tohalf_kernel<<<(int)((n/4+255)/256),256>>>(out_w, owh, n);
        n = (long long)DEPTH*MLPH*EMBED;
        tohalf_kernel<<<(int)((n/4+255)/256),256>>>(fc1_w, w1h, n);
        n = (long long)DEPTH*EMBED*MLPH;
        tohalf_kernel<<<(int)((n/4+255)/256),256>>>(fc2_w, w2h, n);
    }

    // ---- patch embed ----
    im2col_kernel<<<(int)(((long long)NTOK*KPATCH + 255)/256), 256>>>(x);
    {
        dim3 g(EMBED/64, (NTOK+127)/128, 1);
        mma16_gemm<1,0,64><<<g,256,DSZ(64)>>>(
            imh, cwh, conv_b, nullptr, h, nullptr,
            NTOK, EMBED, KPATCH, KPATCH, KPATCH, EMBED, 0);
    }
    freq_kernel<<<1, EMBED/2>>>();
    posadd_kernel<<<(NP*EMBED + 255)/256, 256>>>();

    // ---- transformer blocks ----
    for (int l = 0; l < DEPTH; l++) {
        h16* lqwh = qwh + (long long)l*3*EMBED*EMBED;
        h16* lowh = owh + (long long)l*EMBED*EMBED;
        h16* lw1h = w1h + (long long)l*MLPH*EMBED;
        h16* lw2h = w2h + (long long)l*EMBED*MLPH;
        const float* ob = out_b + (long long)l*EMBED;
        const float* b1 = fc1_b + (long long)l*MLPH;
        const float* b2 = fc2_b + (long long)l*EMBED;

        ln_kernel<<<NTOK,256>>>(h, n1s + l*EMBED, n1b + l*EMBED, nullptr, yh, EMBED);

        {   // qkv = y @ qw^T
            dim3 g((3*EMBED)/128, (NTOK+127)/128, 1);
            mma16_gemm<0,1,128><<<g,256,DSZ(128)>>>(
                yh, lqwh, nullptr, nullptr, nullptr, qkvh,
                NTOK, 3*EMBED, EMBED, EMBED, EMBED, 3*EMBED, 0);
        }

        {   // fused attention (V loaded directly, trans ldsm)
            dim3 g(1, 13, BATCH*HEADS);
            flash_kernel<<<g,256,F_SMEM>>>(qkvh, aoh);
        }

        {   // h = h + ao @ ow^T + ob
            dim3 g(EMBED/64, (NTOK+127)/128, 1);
            mma16_gemm<4,0,64><<<g,256,DSZ(64)>>>(
                aoh, lowh, ob, h, h, nullptr,
                NTOK, EMBED, EMBED, EMBED, EMBED, EMBED, EMBED);
        }

        ln_kernel<<<NTOK,256>>>(h, n2s + l*EMBED, n2b + l*EMBED, nullptr, yh, EMBED);

        {   // mlp = gelu(y @ w1^T + b1)
            dim3 g(MLPH/128, (NTOK+127)/128, 1);
            mma16_gemm<2,1,128><<<g,256,DSZ(128)>>>(
                yh, lw1h, b1, nullptr, nullptr, mlph,
                NTOK, MLPH, EMBED, EMBED, EMBED, MLPH, 0);
        }

        {   // h = h + mlp @ w2^T + b2
            dim3 g(EMBED/64, (NTOK+127)/128, 1);
            mma16_gemm<4,0,64><<<g,256,DSZ(64)>>>(
                mlph, lw2h, b2, h, h, nullptr,
                NTOK, EMBED, MLPH, MLPH, MLPH, EMBED, EMBED);
        }
    }

    // ---- pooled head ----
    {
        dim3 g(EMBED/128, BATCH);
        pool_kernel<<<g,256>>>();
    }
    ln_kernel<<<BATCH,256>>>(pool, fns, fnb, pln, nullptr, EMBED);
    head_kernel<<<(BATCH*1000*32 + 255)/256, 256>>>(head_w, head_b, out);
}